// round 1
// baseline (speedup 1.0000x reference)
#include <cuda_runtime.h>
#include <math.h>
#include <stdint.h>

// ---------------- problem dims ----------------
#define NLAYER 18
#define HDIM   1024
#define NHEAD  8
#define HEADD  256
#define MLPD   4096
#define BATCH  8
#define SEQ    50
#define PREF   800
#define ADIM   32
#define TTOT   850          // PREF + SEQ
#define TPAD   864          // padded row for scores
#define MTOK   400          // BATCH*SEQ

// ---------------- device scratch (no allocs allowed) ----------------
__device__ float g_x[MTOK * HDIM];
__device__ float g_h[MTOK * HDIM];
__device__ float g_temb[BATCH * HDIM];
__device__ float g_t1[BATCH * HDIM];
__device__ float g_tv[BATCH * HDIM];
__device__ float g_ada[BATCH * HDIM];
__device__ float g_q[MTOK * NHEAD * HEADD];
__device__ float g_k[MTOK * HEADD];
__device__ float g_v[MTOK * HEADD];
__device__ float g_sc[BATCH * NHEAD * SEQ * TPAD];
__device__ float g_ao[MTOK * NHEAD * HEADD];
__device__ float g_gg[MTOK * MLPD];
__device__ float g_uu[MTOK * MLPD];
__device__ int   g_plen[BATCH];
__device__ float g_biasPref[BATCH * PREF];

// ---------------- prep: mask -> plen/bias, time embedding ----------------
__global__ void prep_kernel(const void* __restrict__ maskp,
                            const float* __restrict__ ts)
{
    int bb = blockIdx.x;
    if (bb < BATCH) {
        int b = bb;
        const int* mi = (const int*)maskp;
        const unsigned char* mu = (const unsigned char*)maskp;
        // dtype sniff: reading first 4 bytes is safe in either layout.
        // int32 transport -> word in {0,1}; uint8 transport (all-true) -> 0x01010101.
        int w0 = mi[0];
        bool is_i32 = (w0 == 0 || w0 == 1);
        __shared__ int cnt;
        if (threadIdx.x == 0) cnt = 0;
        __syncthreads();
        int local = 0;
        for (int t = threadIdx.x; t < PREF; t += blockDim.x) {
            int m = is_i32 ? mi[b * PREF + t] : (int)mu[b * PREF + t];
            bool on = (m != 0);
            g_biasPref[b * PREF + t] = on ? 0.f : -1e9f;
            if (on) local++;
        }
        atomicAdd(&cnt, local);
        __syncthreads();
        if (threadIdx.x == 0) g_plen[b] = cnt;
    } else {
        int b = bb - BATCH;
        float tsb = ts[b];
        for (int i = threadIdx.x; i < 512; i += blockDim.x) {
            float frac = (float)i / 511.f;
            float period = 4e-3f * powf(1000.f, frac);
            float arg = (6.283185307179586f / period) * tsb;
            float sv, cv;
            sincosf(arg, &sv, &cv);
            g_temb[b * HDIM + i]       = sv;
            g_temb[b * HDIM + 512 + i] = cv;
        }
    }
}

// ---------------- generic SGEMM: C[M,N] = A[M,K]*W[K,N] (+bias)(+=C) ----------------
__global__ void __launch_bounds__(256) sgemm_kernel(
    const float* __restrict__ A, const float* __restrict__ W,
    float* __restrict__ C, const float* __restrict__ bias,
    int M, int N, int K, int lda, int accumulate)
{
    __shared__ float As[16][64];
    __shared__ float Bs[16][64];
    const int tid = threadIdx.x;
    const int tx = tid & 15;
    const int ty = tid >> 4;
    const int rowBase = blockIdx.y * 64;
    const int colBase = blockIdx.x * 64;

    const int lm  = tid >> 2;          // 0..63
    const int lk  = (tid & 3) << 2;    // 0,4,8,12
    const int lkr = tid >> 4;          // 0..15
    const int ln  = (tid & 15) << 2;   // 0..60

    float acc[4][4];
#pragma unroll
    for (int i = 0; i < 4; i++)
#pragma unroll
        for (int j = 0; j < 4; j++) acc[i][j] = 0.f;

    for (int k0 = 0; k0 < K; k0 += 16) {
        float4 av = make_float4(0.f, 0.f, 0.f, 0.f);
        int ar = rowBase + lm;
        if (ar < M) av = *(const float4*)(A + (size_t)ar * lda + (k0 + lk));
        As[lk + 0][lm] = av.x;
        As[lk + 1][lm] = av.y;
        As[lk + 2][lm] = av.z;
        As[lk + 3][lm] = av.w;

        float4 bv;
        int bn = colBase + ln;
        const float* wrow = W + (size_t)(k0 + lkr) * N;
        if (bn + 3 < N) {
            bv = *(const float4*)(wrow + bn);
        } else {
            bv.x = (bn + 0 < N) ? wrow[bn + 0] : 0.f;
            bv.y = (bn + 1 < N) ? wrow[bn + 1] : 0.f;
            bv.z = (bn + 2 < N) ? wrow[bn + 2] : 0.f;
            bv.w = (bn + 3 < N) ? wrow[bn + 3] : 0.f;
        }
        *(float4*)(&Bs[lkr][ln]) = bv;
        __syncthreads();

#pragma unroll
        for (int kk = 0; kk < 16; kk++) {
            float4 a = *(const float4*)(&As[kk][ty << 2]);
            float4 b = *(const float4*)(&Bs[kk][tx << 2]);
            acc[0][0] += a.x * b.x; acc[0][1] += a.x * b.y; acc[0][2] += a.x * b.z; acc[0][3] += a.x * b.w;
            acc[1][0] += a.y * b.x; acc[1][1] += a.y * b.y; acc[1][2] += a.y * b.z; acc[1][3] += a.y * b.w;
            acc[2][0] += a.z * b.x; acc[2][1] += a.z * b.y; acc[2][2] += a.z * b.z; acc[2][3] += a.z * b.w;
            acc[3][0] += a.w * b.x; acc[3][1] += a.w * b.y; acc[3][2] += a.w * b.z; acc[3][3] += a.w * b.w;
        }
        __syncthreads();
    }

#pragma unroll
    for (int i = 0; i < 4; i++) {
        int r = rowBase + (ty << 2) + i;
        if (r >= M) continue;
#pragma unroll
        for (int j = 0; j < 4; j++) {
            int c = colBase + (tx << 2) + j;
            if (c >= N) continue;
            float v = acc[i][j];
            if (bias) v += bias[c];
            size_t off = (size_t)r * N + c;
            if (accumulate) v += C[off];
            C[off] = v;
        }
    }
}

// ---------------- small-M (M<=8) GEMM: C[M,N] = A[M,K]*W[K,N] ----------------
// grid: ceil(N/64) blocks, 256 threads. act: 0 none, 1 silu.
__global__ void __launch_bounds__(256) gemv8_kernel(
    const float* __restrict__ A, const float* __restrict__ W,
    const float* __restrict__ bias, float* __restrict__ C,
    int Mrows, int N, int K, int act)
{
    __shared__ float a_s[8 * 1024];
    __shared__ float red[4 * 64 * 8];
    int tid = threadIdx.x;
    for (int e = tid; e < 8 * K; e += 256) {
        int m = e / K;
        a_s[e] = (m < Mrows) ? A[e] : 0.f;
    }
    __syncthreads();

    int nl = tid & 63;
    int n  = blockIdx.x * 64 + nl;
    int ks = tid >> 6;                  // 0..3 K-slice
    float acc[8];
#pragma unroll
    for (int m = 0; m < 8; m++) acc[m] = 0.f;

    int kc = K >> 2;
    if (n < N) {
        int kbeg = ks * kc;
#pragma unroll 4
        for (int k = 0; k < kc; k++) {
            float w = W[(size_t)(kbeg + k) * N + n];
#pragma unroll
            for (int m = 0; m < 8; m++) acc[m] += a_s[m * K + kbeg + k] * w;
        }
    }
#pragma unroll
    for (int m = 0; m < 8; m++) red[tid * 8 + m] = acc[m];
    __syncthreads();
    if (ks == 0 && n < N) {
#pragma unroll
        for (int m = 0; m < 8; m++) {
            float v = red[(0 * 64 + nl) * 8 + m] + red[(1 * 64 + nl) * 8 + m] +
                      red[(2 * 64 + nl) * 8 + m] + red[(3 * 64 + nl) * 8 + m];
            if (bias) v += bias[n];
            if (act == 1) v = v / (1.f + expf(-v));
            if (m < Mrows) C[(size_t)m * N + n] = v;
        }
    }
}

// ---------------- rmsnorm (+optional ada gate) ----------------
__global__ void __launch_bounds__(256) rmsnorm_kernel(
    const float* __restrict__ x, const float* __restrict__ w,
    const float* __restrict__ ada, float* __restrict__ out)
{
    int row = blockIdx.x;               // 0..399
    int b = row / SEQ;
    const float* xr = x + (size_t)row * HDIM;
    __shared__ float red[256];
    float s = 0.f;
    for (int i = threadIdx.x; i < HDIM; i += 256) {
        float v = xr[i];
        s += v * v;
    }
    red[threadIdx.x] = s;
    __syncthreads();
    for (int st = 128; st > 0; st >>= 1) {
        if (threadIdx.x < st) red[threadIdx.x] += red[threadIdx.x + st];
        __syncthreads();
    }
    float r = rsqrtf(red[0] * (1.f / HDIM) + 1e-6f);
    for (int i = threadIdx.x; i < HDIM; i += 256) {
        float gmul = w[i];
        if (ada) gmul *= (1.f + ada[b * HDIM + i]);
        out[(size_t)row * HDIM + i] = xr[i] * r * gmul;
    }
}

// ---------------- rope over q (8 heads) and k (1 head) ----------------
__global__ void rope_kernel(float* __restrict__ q, float* __restrict__ k)
{
    int idx = blockIdx.x * blockDim.x + threadIdx.x;
    const int total = MTOK * 9 * 128;
    if (idx >= total) return;
    int j = idx & 127;
    int rest = idx >> 7;
    int hh = rest % 9;
    int row = rest / 9;                 // 0..399
    int b = row / SEQ, s = row % SEQ;
    float pos = (float)(g_plen[b] + s);
    float inv = powf(10000.f, -(float)j / 128.f);
    float fr = pos * inv;
    float sn, cs;
    sincosf(fr, &sn, &cs);
    float* p = (hh < 8) ? (q + ((size_t)row * 8 + hh) * 256) : (k + (size_t)row * 256);
    float x1 = p[j], x2 = p[j + 128];
    p[j]       = x1 * cs - x2 * sn;
    p[j + 128] = x2 * cs + x1 * sn;
}

// ---------------- attention scores: sc[b,h,s,t] = q.k/16 + bias ----------------
// grid (14, 64), block 160 (5 warps). microtile 5s x 4t per thread.
__global__ void __launch_bounds__(160) scores_kernel(
    const float* __restrict__ q, const float* __restrict__ knew,
    const float* __restrict__ kvc, int layer)
{
    __shared__ float Qs[32][52];
    __shared__ float Ks[32][68];
    int tid = threadIdx.x;
    int bh = blockIdx.y;
    int b = bh >> 3, h = bh & 7;
    int t0 = blockIdx.x * 64;
    const float* Kcache = kvc + ((size_t)(layer * 2) * BATCH + b) * (size_t)(PREF * HEADD);
    int sg = tid / 16;                  // 0..9
    int tg = tid % 16;                  // 0..15
    float acc[5][4];
#pragma unroll
    for (int i = 0; i < 5; i++)
#pragma unroll
        for (int j = 0; j < 4; j++) acc[i][j] = 0.f;

    for (int d0 = 0; d0 < HEADD; d0 += 32) {
        for (int e = tid; e < SEQ * 32; e += 160) {
            int s = e >> 5, dd = e & 31;
            Qs[dd][s] = q[(((size_t)(b * SEQ + s)) * 8 + h) * 256 + d0 + dd];
        }
        for (int e = tid; e < 64 * 32; e += 160) {
            int t = e >> 5, dd = e & 31;
            int tglob = t0 + t;
            float v = 0.f;
            if (tglob < PREF)      v = Kcache[(size_t)tglob * 256 + d0 + dd];
            else if (tglob < TTOT) v = knew[((size_t)(b * SEQ + (tglob - PREF))) * 256 + d0 + dd];
            Ks[dd][t] = v;
        }
        __syncthreads();
#pragma unroll 8
        for (int dd = 0; dd < 32; dd++) {
            float4 kv = *(const float4*)(&Ks[dd][tg << 2]);
#pragma unroll
            for (int i = 0; i < 5; i++) {
                float a = Qs[dd][sg * 5 + i];
                acc[i][0] += a * kv.x;
                acc[i][1] += a * kv.y;
                acc[i][2] += a * kv.z;
                acc[i][3] += a * kv.w;
            }
        }
        __syncthreads();
    }
    const float scale = 0.0625f;
#pragma unroll
    for (int i = 0; i < 5; i++) {
        int s = sg * 5 + i;
#pragma unroll
        for (int j = 0; j < 4; j++) {
            int tglob = t0 + (tg << 2) + j;
            if (tglob < TTOT) {
                float bias = (tglob < PREF) ? g_biasPref[b * PREF + tglob] : 0.f;
                g_sc[((size_t)bh * SEQ + s) * TPAD + tglob] = acc[i][j] * scale + bias;
            }
        }
    }
}

// ---------------- softmax over T=850 per row ----------------
__global__ void __launch_bounds__(256) softmax_kernel()
{
    int row = blockIdx.x;               // 0..3199
    float* p = g_sc + (size_t)row * TPAD;
    __shared__ float red[256];
    float mx = -1e30f;
    for (int i = threadIdx.x; i < TTOT; i += 256) mx = fmaxf(mx, p[i]);
    red[threadIdx.x] = mx;
    __syncthreads();
    for (int st = 128; st > 0; st >>= 1) {
        if (threadIdx.x < st) red[threadIdx.x] = fmaxf(red[threadIdx.x], red[threadIdx.x + st]);
        __syncthreads();
    }
    float m = red[0];
    __syncthreads();
    float s = 0.f;
    for (int i = threadIdx.x; i < TTOT; i += 256) {
        float e = expf(p[i] - m);
        p[i] = e;
        s += e;
    }
    red[threadIdx.x] = s;
    __syncthreads();
    for (int st = 128; st > 0; st >>= 1) {
        if (threadIdx.x < st) red[threadIdx.x] += red[threadIdx.x + st];
        __syncthreads();
    }
    float inv = 1.f / red[0];
    for (int i = threadIdx.x; i < TTOT; i += 256) p[i] *= inv;
}

// ---------------- PV: out[b,s,h,d] = sum_t p[b,h,s,t] * V[b,t,d] ----------------
// grid (4, 64), block 160. microtile 5s x 4d.
__global__ void __launch_bounds__(160) pv_kernel(
    const float* __restrict__ vnew, const float* __restrict__ kvc,
    int layer, float* __restrict__ out)
{
    __shared__ float Ps[32][52];
    __shared__ float Vs[32][68];
    int tid = threadIdx.x;
    int bh = blockIdx.y;
    int b = bh >> 3, h = bh & 7;
    int d0 = blockIdx.x * 64;
    const float* Vcache = kvc + ((size_t)(layer * 2 + 1) * BATCH + b) * (size_t)(PREF * HEADD);
    int sg = tid / 16;
    int dg = tid % 16;
    float acc[5][4];
#pragma unroll
    for (int i = 0; i < 5; i++)
#pragma unroll
        for (int j = 0; j < 4; j++) acc[i][j] = 0.f;

    for (int t0 = 0; t0 < TTOT; t0 += 32) {
        for (int e = tid; e < SEQ * 32; e += 160) {
            int s = e >> 5, tt = e & 31;
            int tglob = t0 + tt;
            Ps[tt][s] = (tglob < TTOT) ? g_sc[((size_t)bh * SEQ + s) * TPAD + tglob] : 0.f;
        }
        for (int e = tid; e < 32 * 64; e += 160) {
            int dd = e & 63, tt = e >> 6;
            int tglob = t0 + tt;
            float v = 0.f;
            if (tglob < PREF)      v = Vcache[(size_t)tglob * 256 + d0 + dd];
            else if (tglob < TTOT) v = vnew[((size_t)(b * SEQ + (tglob - PREF))) * 256 + d0 + dd];
            Vs[tt][dd] = v;
        }
        __syncthreads();
#pragma unroll 8
        for (int tt = 0; tt < 32; tt++) {
            float4 vv = *(const float4*)(&Vs[tt][dg << 2]);
#pragma unroll
            for (int i = 0; i < 5; i++) {
                float a = Ps[tt][sg * 5 + i];
                acc[i][0] += a * vv.x;
                acc[i][1] += a * vv.y;
                acc[i][2] += a * vv.z;
                acc[i][3] += a * vv.w;
            }
        }
        __syncthreads();
    }
#pragma unroll
    for (int i = 0; i < 5; i++) {
        int s = sg * 5 + i;
#pragma unroll
        for (int j = 0; j < 4; j++) {
            int d = d0 + (dg << 2) + j;
            out[(((size_t)(b * SEQ + s)) * 8 + h) * 256 + d] = acc[i][j];
        }
    }
}

// ---------------- gelu(g)*u -> g ----------------
__global__ void gelumul_kernel(float* __restrict__ gg, const float* __restrict__ uu, int n)
{
    int idx = blockIdx.x * blockDim.x + threadIdx.x;
    if (idx >= n) return;
    float x = gg[idx];
    float t = tanhf(0.7978845608028654f * (x + 0.044715f * x * x * x));
    gg[idx] = 0.5f * x * (1.f + t) * uu[idx];
}

// ---------------- host ----------------
static inline dim3 gemm_grid(int M, int N) { return dim3((N + 63) / 64, (M + 63) / 64); }

extern "C" void kernel_launch(void* const* d_in, const int* in_sizes, int n_in,
                              void* d_out, int out_size)
{
    const float* x_t      = (const float*)d_in[0];
    const float* timestep = (const float*)d_in[1];
    const void*  mask     = d_in[2];
    const float* kvc      = (const float*)d_in[3];
    const float* Wa_in    = (const float*)d_in[4];
    const float* ba_in    = (const float*)d_in[5];
    const float* Wt_in    = (const float*)d_in[6];
    const float* bt_in    = (const float*)d_in[7];
    const float* Wt_out   = (const float*)d_in[8];
    const float* bt_out   = (const float*)d_in[9];
    const float* Wq       = (const float*)d_in[10];
    const float* Wk       = (const float*)d_in[11];
    const float* Wv       = (const float*)d_in[12];
    const float* Wo       = (const float*)d_in[13];
    const float* Wg       = (const float*)d_in[14];
    const float* Wu       = (const float*)d_in[15];
    const float* Wd       = (const float*)d_in[16];
    const float* n1_w     = (const float*)d_in[17];
    const float* n2_w     = (const float*)d_in[18];
    const float* Wada1    = (const float*)d_in[19];
    const float* Wada2    = (const float*)d_in[20];
    const float* nf_w     = (const float*)d_in[21];
    const float* Wa_out   = (const float*)d_in[22];
    const float* ba_out   = (const float*)d_in[23];

    void* p;
    cudaGetSymbolAddress(&p, g_x);    float* px    = (float*)p;
    cudaGetSymbolAddress(&p, g_h);    float* ph    = (float*)p;
    cudaGetSymbolAddress(&p, g_temb); float* ptemb = (float*)p;
    cudaGetSymbolAddress(&p, g_t1);   float* pt1   = (float*)p;
    cudaGetSymbolAddress(&p, g_tv);   float* ptv   = (float*)p;
    cudaGetSymbolAddress(&p, g_ada);  float* pada  = (float*)p;
    cudaGetSymbolAddress(&p, g_q);    float* pq    = (float*)p;
    cudaGetSymbolAddress(&p, g_k);    float* pk    = (float*)p;
    cudaGetSymbolAddress(&p, g_v);    float* pv    = (float*)p;
    cudaGetSymbolAddress(&p, g_ao);   float* pao   = (float*)p;
    cudaGetSymbolAddress(&p, g_gg);   float* pg    = (float*)p;
    cudaGetSymbolAddress(&p, g_uu);   float* pu    = (float*)p;

    // prep: mask counts/bias + time embedding
    prep_kernel<<<16, 512>>>(mask, timestep);

    // time MLP: t = silu(silu(temb@Wt_in+b)@Wt_out+b)
    gemv8_kernel<<<16, 256>>>(ptemb, Wt_in, bt_in, pt1, 8, HDIM, HDIM, 1);
    gemv8_kernel<<<16, 256>>>(pt1, Wt_out, bt_out, ptv, 8, HDIM, HDIM, 1);

    // x = x_t @ Wa_in + ba_in
    sgemm_kernel<<<gemm_grid(MTOK, HDIM), 256>>>(x_t, Wa_in, px, ba_in,
                                                 MTOK, HDIM, ADIM, ADIM, 0);

    for (int l = 0; l < NLAYER; l++) {
        const float* wq = Wq + (size_t)l * HDIM * (NHEAD * HEADD);
        const float* wk = Wk + (size_t)l * HDIM * HEADD;
        const float* wv = Wv + (size_t)l * HDIM * HEADD;
        const float* wo = Wo + (size_t)l * (NHEAD * HEADD) * HDIM;
        const float* wg = Wg + (size_t)l * HDIM * MLPD;
        const float* wu = Wu + (size_t)l * HDIM * MLPD;
        const float* wd = Wd + (size_t)l * MLPD * HDIM;
        const float* w1 = n1_w + (size_t)l * HDIM;
        const float* w2 = n2_w + (size_t)l * HDIM;
        const float* wa1 = Wada1 + (size_t)l * HDIM * HDIM;
        const float* wa2 = Wada2 + (size_t)l * HDIM * HDIM;

        // ada1 + pre-attn norm
        gemv8_kernel<<<16, 256>>>(ptv, wa1, nullptr, pada, 8, HDIM, HDIM, 0);
        rmsnorm_kernel<<<MTOK, 256>>>(px, w1, pada, ph);

        // qkv
        sgemm_kernel<<<gemm_grid(MTOK, NHEAD * HEADD), 256>>>(ph, wq, pq, nullptr,
                                                              MTOK, NHEAD * HEADD, HDIM, HDIM, 0);
        sgemm_kernel<<<gemm_grid(MTOK, HEADD), 256>>>(ph, wk, pk, nullptr,
                                                      MTOK, HEADD, HDIM, HDIM, 0);
        sgemm_kernel<<<gemm_grid(MTOK, HEADD), 256>>>(ph, wv, pv, nullptr,
                                                      MTOK, HEADD, HDIM, HDIM, 0);
        rope_kernel<<<(MTOK * 9 * 128 + 255) / 256, 256>>>(pq, pk);

        // attention
        scores_kernel<<<dim3((TTOT + 63) / 64, BATCH * NHEAD), 160>>>(pq, pk, kvc, l);
        softmax_kernel<<<BATCH * NHEAD * SEQ, 256>>>();
        pv_kernel<<<dim3(HEADD / 64, BATCH * NHEAD), 160>>>(pv, kvc, l, pao);

        // x += o @ Wo
        sgemm_kernel<<<gemm_grid(MTOK, HDIM), 256>>>(pao, wo, px, nullptr,
                                                     MTOK, HDIM, NHEAD * HEADD, NHEAD * HEADD, 1);

        // ada2 + pre-mlp norm
        gemv8_kernel<<<16, 256>>>(ptv, wa2, nullptr, pada, 8, HDIM, HDIM, 0);
        rmsnorm_kernel<<<MTOK, 256>>>(px, w2, pada, ph);

        // mlp
        sgemm_kernel<<<gemm_grid(MTOK, MLPD), 256>>>(ph, wg, pg, nullptr,
                                                     MTOK, MLPD, HDIM, HDIM, 0);
        sgemm_kernel<<<gemm_grid(MTOK, MLPD), 256>>>(ph, wu, pu, nullptr,
                                                     MTOK, MLPD, HDIM, HDIM, 0);
        gelumul_kernel<<<(MTOK * MLPD + 255) / 256, 256>>>(pg, pu, MTOK * MLPD);
        sgemm_kernel<<<gemm_grid(MTOK, HDIM), 256>>>(pg, wd, px, nullptr,
                                                     MTOK, HDIM, MLPD, MLPD, 1);
    }

    // final norm + out projection
    rmsnorm_kernel<<<MTOK, 256>>>(px, nf_w, nullptr, ph);
    sgemm_kernel<<<gemm_grid(MTOK, ADIM), 256>>>(ph, Wa_out, (float*)d_out, ba_out,
                                                 MTOK, ADIM, HDIM, HDIM, 0);
}

// round 4
// speedup vs baseline: 1.0426x; 1.0426x over previous
#include <cuda_runtime.h>
#include <math.h>
#include <stdint.h>

// ---------------- problem dims ----------------
#define NLAYER 18
#define HDIM   1024
#define NHEAD  8
#define HEADD  256
#define MLPD   4096
#define BATCH  8
#define SEQ    50
#define PREF   800
#define ADIM   32
#define TTOT   850
#define TPAD   864
#define MTOK   400

// ---------------- device scratch ----------------
__device__ float g_x[MTOK * HDIM];
__device__ float g_h[MTOK * HDIM];
__device__ float g_temb[BATCH * HDIM];
__device__ float g_t1[BATCH * HDIM];
__device__ float g_tv[BATCH * HDIM];
__device__ float g_ada[BATCH * HDIM];
__device__ float g_q[MTOK * NHEAD * HEADD];
__device__ float g_k[MTOK * HEADD];
__device__ float g_v[MTOK * HEADD];
__device__ float g_sc[BATCH * NHEAD * SEQ * TPAD];
__device__ float g_ao[MTOK * NHEAD * HEADD];
__device__ float g_gg[MTOK * MLPD];
__device__ float g_uu[MTOK * MLPD];
__device__ int   g_plen[BATCH];
__device__ float g_biasPref[BATCH * PREF];

// ---------------- tf32 helpers ----------------
__device__ __forceinline__ uint32_t f32_to_tf32(float x) {
    uint32_t r;
    asm("cvt.rna.tf32.f32 %0, %1;" : "=r"(r) : "f"(x));
    return r;
}
__device__ __forceinline__ void split_tf32(float x, uint32_t& hi, uint32_t& lo) {
    uint32_t h;
    asm("cvt.rna.tf32.f32 %0, %1;" : "=r"(h) : "f"(x));
    float hf = __uint_as_float(h);
    uint32_t l;
    asm("cvt.rna.tf32.f32 %0, %1;" : "=r"(l) : "f"(x - hf));
    hi = h; lo = l;
}
__device__ __forceinline__ void mma_tf32(
    float c[4], const uint32_t a[4], uint32_t b0, uint32_t b1)
{
    asm volatile(
        "mma.sync.aligned.m16n8k8.row.col.f32.tf32.tf32.f32 "
        "{%0,%1,%2,%3}, {%4,%5,%6,%7}, {%8,%9}, {%0,%1,%2,%3};"
        : "+f"(c[0]), "+f"(c[1]), "+f"(c[2]), "+f"(c[3])
        : "r"(a[0]), "r"(a[1]), "r"(a[2]), "r"(a[3]), "r"(b0), "r"(b1));
}

// ============ 3xTF32 mma.sync GEMM: C[M,N] = A[M,K] @ W[K,N], (+=C) ============
// Tile 128x128x32. grid (N/128, ceil(M/128)), 256 threads (8 warps, 2m x 4n).
// A = Ahi + Alo (tf32 split); C += Ahi*Bhi + Alo*Bhi + Ahi*Blo  (fp32-accurate).
#define APAD 36
#define BPAD 136
#define A_WORDS (128 * APAD)
#define B_WORDS (32 * BPAD)
#define SMEM_MMA_BYTES ((2 * A_WORDS + 2 * B_WORDS) * 4)

__global__ void __launch_bounds__(256) mma_gemm_kernel(
    const float* __restrict__ A, const float* __restrict__ W,
    float* __restrict__ C, int M, int N, int K, int accumulate)
{
    extern __shared__ uint32_t dyn[];
    uint32_t* AsHi = dyn;
    uint32_t* AsLo = dyn + A_WORDS;
    uint32_t* BsHi = dyn + 2 * A_WORDS;
    uint32_t* BsLo = dyn + 2 * A_WORDS + B_WORDS;

    const int tid  = threadIdx.x;
    const int lane = tid & 31;
    const int warp = tid >> 5;
    const int wm = (warp & 1) << 6;        // 0 or 64
    const int wn = (warp >> 1) << 5;       // 0,32,64,96
    const int rowBase = blockIdx.y * 128;
    const int colBase = blockIdx.x * 128;

    const int aRow = tid >> 3;             // 0..31
    const int aK   = (tid & 7) << 2;       // 0,4,...,28

    float c[4][4][4];
#pragma unroll
    for (int i = 0; i < 4; i++)
#pragma unroll
        for (int j = 0; j < 4; j++)
#pragma unroll
            for (int r = 0; r < 4; r++) c[i][j][r] = 0.f;

    float4 pa[4], pb[4];
#pragma unroll
    for (int p = 0; p < 4; p++) {
        int gr = rowBase + aRow + (p << 5);
        pa[p] = make_float4(0.f, 0.f, 0.f, 0.f);
        if (gr < M) pa[p] = *(const float4*)(A + (size_t)gr * K + aK);
        pb[p] = *(const float4*)(W + (size_t)(warp + (p << 3)) * N + colBase + (lane << 2));
    }

    const int nChunks = K >> 5;
    for (int i = 0; i < nChunks; i++) {
#pragma unroll
        for (int p = 0; p < 4; p++) {
            int r = aRow + (p << 5);
            uint4 ah, al;
            split_tf32(pa[p].x, ah.x, al.x);
            split_tf32(pa[p].y, ah.y, al.y);
            split_tf32(pa[p].z, ah.z, al.z);
            split_tf32(pa[p].w, ah.w, al.w);
            *(uint4*)(&AsHi[r * APAD + aK]) = ah;
            *(uint4*)(&AsLo[r * APAD + aK]) = al;
            int kk = warp + (p << 3);
            uint4 bh, bl;
            split_tf32(pb[p].x, bh.x, bl.x);
            split_tf32(pb[p].y, bh.y, bl.y);
            split_tf32(pb[p].z, bh.z, bl.z);
            split_tf32(pb[p].w, bh.w, bl.w);
            *(uint4*)(&BsHi[kk * BPAD + (lane << 2)]) = bh;
            *(uint4*)(&BsLo[kk * BPAD + (lane << 2)]) = bl;
        }
        __syncthreads();

        if (i + 1 < nChunks) {
            int k0 = (i + 1) << 5;
#pragma unroll
            for (int p = 0; p < 4; p++) {
                int gr = rowBase + aRow + (p << 5);
                pa[p] = make_float4(0.f, 0.f, 0.f, 0.f);
                if (gr < M) pa[p] = *(const float4*)(A + (size_t)gr * K + k0 + aK);
                pb[p] = *(const float4*)(W + (size_t)(k0 + warp + (p << 3)) * N + colBase + (lane << 2));
            }
        }

#pragma unroll
        for (int ks = 0; ks < 4; ks++) {
            const int kb = (ks << 3) + (lane & 3);
            uint32_t bh[4][2], bl[4][2];
#pragma unroll
            for (int nf = 0; nf < 4; nf++) {
                int cn = wn + (nf << 3) + (lane >> 2);
                bh[nf][0] = BsHi[kb * BPAD + cn];
                bh[nf][1] = BsHi[(kb + 4) * BPAD + cn];
                bl[nf][0] = BsLo[kb * BPAD + cn];
                bl[nf][1] = BsLo[(kb + 4) * BPAD + cn];
            }
#pragma unroll
            for (int mf = 0; mf < 4; mf++) {
                int r = wm + (mf << 4) + (lane >> 2);
                uint32_t ah[4], al[4];
                ah[0] = AsHi[r * APAD + kb];
                ah[1] = AsHi[(r + 8) * APAD + kb];
                ah[2] = AsHi[r * APAD + kb + 4];
                ah[3] = AsHi[(r + 8) * APAD + kb + 4];
                al[0] = AsLo[r * APAD + kb];
                al[1] = AsLo[(r + 8) * APAD + kb];
                al[2] = AsLo[r * APAD + kb + 4];
                al[3] = AsLo[(r + 8) * APAD + kb + 4];
#pragma unroll
                for (int nf = 0; nf < 4; nf++) {
                    mma_tf32(c[mf][nf], al, bh[nf][0], bh[nf][1]);
                    mma_tf32(c[mf][nf], ah, bl[nf][0], bl[nf][1]);
                    mma_tf32(c[mf][nf], ah, bh[nf][0], bh[nf][1]);
                }
            }
        }
        __syncthreads();
    }

#pragma unroll
    for (int mf = 0; mf < 4; mf++) {
        int r0 = rowBase + wm + (mf << 4) + (lane >> 2);
#pragma unroll
        for (int nf = 0; nf < 4; nf++) {
            int cc = colBase + wn + (nf << 3) + ((lane & 3) << 1);
            if (r0 < M) {
                float2* p0 = (float2*)(C + (size_t)r0 * N + cc);
                float2 v = make_float2(c[mf][nf][0], c[mf][nf][1]);
                if (accumulate) { float2 old = *p0; v.x += old.x; v.y += old.y; }
                *p0 = v;
            }
            if (r0 + 8 < M) {
                float2* p1 = (float2*)(C + (size_t)(r0 + 8) * N + cc);
                float2 v = make_float2(c[mf][nf][2], c[mf][nf][3]);
                if (accumulate) { float2 old = *p1; v.x += old.x; v.y += old.y; }
                *p1 = v;
            }
        }
    }
}

// ---------------- prep: mask -> plen/bias, time embedding ----------------
__global__ void prep_kernel(const void* __restrict__ maskp,
                            const float* __restrict__ ts)
{
    int bb = blockIdx.x;
    if (bb < BATCH) {
        int b = bb;
        const int* mi = (const int*)maskp;
        const unsigned char* mu = (const unsigned char*)maskp;
        int w0 = mi[0];
        bool is_i32 = (w0 == 0 || w0 == 1);
        __shared__ int cnt;
        if (threadIdx.x == 0) cnt = 0;
        __syncthreads();
        int local = 0;
        for (int t = threadIdx.x; t < PREF; t += blockDim.x) {
            int m = is_i32 ? mi[b * PREF + t] : (int)mu[b * PREF + t];
            bool on = (m != 0);
            g_biasPref[b * PREF + t] = on ? 0.f : -1e9f;
            if (on) local++;
        }
        atomicAdd(&cnt, local);
        __syncthreads();
        if (threadIdx.x == 0) g_plen[b] = cnt;
    } else {
        int b = bb - BATCH;
        float tsb = ts[b];
        for (int i = threadIdx.x; i < 512; i += blockDim.x) {
            float frac = (float)i / 511.f;
            float period = 4e-3f * powf(1000.f, frac);
            float arg = (6.283185307179586f / period) * tsb;
            float sv, cv;
            sincosf(arg, &sv, &cv);
            g_temb[b * HDIM + i]       = sv;
            g_temb[b * HDIM + 512 + i] = cv;
        }
    }
}

// ---------------- SIMT SGEMM (small GEMMs only) ----------------
__global__ void __launch_bounds__(256) sgemm_kernel(
    const float* __restrict__ A, const float* __restrict__ W,
    float* __restrict__ C, const float* __restrict__ bias,
    int M, int N, int K, int lda, int accumulate)
{
    __shared__ float As[16][64];
    __shared__ float Bs[16][64];
    const int tid = threadIdx.x;
    const int tx = tid & 15;
    const int ty = tid >> 4;
    const int rowBase = blockIdx.y * 64;
    const int colBase = blockIdx.x * 64;

    const int lm  = tid >> 2;
    const int lk  = (tid & 3) << 2;
    const int lkr = tid >> 4;
    const int ln  = (tid & 15) << 2;

    float acc[4][4];
#pragma unroll
    for (int i = 0; i < 4; i++)
#pragma unroll
        for (int j = 0; j < 4; j++) acc[i][j] = 0.f;

    for (int k0 = 0; k0 < K; k0 += 16) {
        float4 av = make_float4(0.f, 0.f, 0.f, 0.f);
        int ar = rowBase + lm;
        if (ar < M) av = *(const float4*)(A + (size_t)ar * lda + (k0 + lk));
        As[lk + 0][lm] = av.x;
        As[lk + 1][lm] = av.y;
        As[lk + 2][lm] = av.z;
        As[lk + 3][lm] = av.w;

        float4 bv;
        int bn = colBase + ln;
        const float* wrow = W + (size_t)(k0 + lkr) * N;
        if (bn + 3 < N) {
            bv = *(const float4*)(wrow + bn);
        } else {
            bv.x = (bn + 0 < N) ? wrow[bn + 0] : 0.f;
            bv.y = (bn + 1 < N) ? wrow[bn + 1] : 0.f;
            bv.z = (bn + 2 < N) ? wrow[bn + 2] : 0.f;
            bv.w = (bn + 3 < N) ? wrow[bn + 3] : 0.f;
        }
        *(float4*)(&Bs[lkr][ln]) = bv;
        __syncthreads();

#pragma unroll
        for (int kk = 0; kk < 16; kk++) {
            float4 a = *(const float4*)(&As[kk][ty << 2]);
            float4 b = *(const float4*)(&Bs[kk][tx << 2]);
            acc[0][0] += a.x * b.x; acc[0][1] += a.x * b.y; acc[0][2] += a.x * b.z; acc[0][3] += a.x * b.w;
            acc[1][0] += a.y * b.x; acc[1][1] += a.y * b.y; acc[1][2] += a.y * b.z; acc[1][3] += a.y * b.w;
            acc[2][0] += a.z * b.x; acc[2][1] += a.z * b.y; acc[2][2] += a.z * b.z; acc[2][3] += a.z * b.w;
            acc[3][0] += a.w * b.x; acc[3][1] += a.w * b.y; acc[3][2] += a.w * b.z; acc[3][3] += a.w * b.w;
        }
        __syncthreads();
    }

#pragma unroll
    for (int i = 0; i < 4; i++) {
        int r = rowBase + (ty << 2) + i;
        if (r >= M) continue;
#pragma unroll
        for (int j = 0; j < 4; j++) {
            int cx = colBase + (tx << 2) + j;
            if (cx >= N) continue;
            float v = acc[i][j];
            if (bias) v += bias[cx];
            size_t off = (size_t)r * N + cx;
            if (accumulate) v += C[off];
            C[off] = v;
        }
    }
}

// ---------------- small-M (M<=8) GEMM ----------------
__global__ void __launch_bounds__(256) gemv8_kernel(
    const float* __restrict__ A, const float* __restrict__ W,
    const float* __restrict__ bias, float* __restrict__ C,
    int Mrows, int N, int K, int act)
{
    __shared__ float a_s[8 * 1024];
    __shared__ float red[4 * 64 * 8];
    int tid = threadIdx.x;
    for (int e = tid; e < 8 * K; e += 256) {
        int m = e / K;
        a_s[e] = (m < Mrows) ? A[e] : 0.f;
    }
    __syncthreads();

    int nl = tid & 63;
    int n  = blockIdx.x * 64 + nl;
    int ks = tid >> 6;
    float acc[8];
#pragma unroll
    for (int m = 0; m < 8; m++) acc[m] = 0.f;

    int kc = K >> 2;
    if (n < N) {
        int kbeg = ks * kc;
#pragma unroll 4
        for (int k = 0; k < kc; k++) {
            float w = W[(size_t)(kbeg + k) * N + n];
#pragma unroll
            for (int m = 0; m < 8; m++) acc[m] += a_s[m * K + kbeg + k] * w;
        }
    }
#pragma unroll
    for (int m = 0; m < 8; m++) red[tid * 8 + m] = acc[m];
    __syncthreads();
    if (ks == 0 && n < N) {
#pragma unroll
        for (int m = 0; m < 8; m++) {
            float v = red[(0 * 64 + nl) * 8 + m] + red[(1 * 64 + nl) * 8 + m] +
                      red[(2 * 64 + nl) * 8 + m] + red[(3 * 64 + nl) * 8 + m];
            if (bias) v += bias[n];
            if (act == 1) v = v / (1.f + expf(-v));
            if (m < Mrows) C[(size_t)m * N + n] = v;
        }
    }
}

// ---------------- rmsnorm (+optional ada gate) ----------------
__global__ void __launch_bounds__(256) rmsnorm_kernel(
    const float* __restrict__ x, const float* __restrict__ w,
    const float* __restrict__ ada, float* __restrict__ out)
{
    int row = blockIdx.x;
    int b = row / SEQ;
    const float* xr = x + (size_t)row * HDIM;
    __shared__ float red[256];
    float s = 0.f;
    for (int i = threadIdx.x; i < HDIM; i += 256) {
        float v = xr[i];
        s += v * v;
    }
    red[threadIdx.x] = s;
    __syncthreads();
    for (int st = 128; st > 0; st >>= 1) {
        if (threadIdx.x < st) red[threadIdx.x] += red[threadIdx.x + st];
        __syncthreads();
    }
    float r = rsqrtf(red[0] * (1.f / HDIM) + 1e-6f);
    for (int i = threadIdx.x; i < HDIM; i += 256) {
        float gmul = w[i];
        if (ada) gmul *= (1.f + ada[b * HDIM + i]);
        out[(size_t)row * HDIM + i] = xr[i] * r * gmul;
    }
}

// ---------------- rope ----------------
__global__ void rope_kernel(float* __restrict__ q, float* __restrict__ k)
{
    int idx = blockIdx.x * blockDim.x + threadIdx.x;
    const int total = MTOK * 9 * 128;
    if (idx >= total) return;
    int j = idx & 127;
    int rest = idx >> 7;
    int hh = rest % 9;
    int row = rest / 9;
    int b = row / SEQ, s = row % SEQ;
    float pos = (float)(g_plen[b] + s);
    float inv = powf(10000.f, -(float)j / 128.f);
    float fr = pos * inv;
    float sn, cs;
    sincosf(fr, &sn, &cs);
    float* p = (hh < 8) ? (q + ((size_t)row * 8 + hh) * 256) : (k + (size_t)row * 256);
    float x1 = p[j], x2 = p[j + 128];
    p[j]       = x1 * cs - x2 * sn;
    p[j + 128] = x2 * cs + x1 * sn;
}

// ---------------- attention scores ----------------
__global__ void __launch_bounds__(160) scores_kernel(
    const float* __restrict__ q, const float* __restrict__ knew,
    const float* __restrict__ kvc, int layer)
{
    __shared__ float Qs[32][52];
    __shared__ float Ks[32][68];
    int tid = threadIdx.x;
    int bh = blockIdx.y;
    int b = bh >> 3, h = bh & 7;
    int t0 = blockIdx.x * 64;
    const float* Kcache = kvc + ((size_t)(layer * 2) * BATCH + b) * (size_t)(PREF * HEADD);
    int sg = tid / 16;
    int tg = tid % 16;
    float acc[5][4];
#pragma unroll
    for (int i = 0; i < 5; i++)
#pragma unroll
        for (int j = 0; j < 4; j++) acc[i][j] = 0.f;

    for (int d0 = 0; d0 < HEADD; d0 += 32) {
        for (int e = tid; e < SEQ * 32; e += 160) {
            int s = e >> 5, dd = e & 31;
            Qs[dd][s] = q[(((size_t)(b * SEQ + s)) * 8 + h) * 256 + d0 + dd];
        }
        for (int e = tid; e < 64 * 32; e += 160) {
            int t = e >> 5, dd = e & 31;
            int tglob = t0 + t;
            float v = 0.f;
            if (tglob < PREF)      v = Kcache[(size_t)tglob * 256 + d0 + dd];
            else if (tglob < TTOT) v = knew[((size_t)(b * SEQ + (tglob - PREF))) * 256 + d0 + dd];
            Ks[dd][t] = v;
        }
        __syncthreads();
#pragma unroll 8
        for (int dd = 0; dd < 32; dd++) {
            float4 kv = *(const float4*)(&Ks[dd][tg << 2]);
#pragma unroll
            for (int i = 0; i < 5; i++) {
                float a = Qs[dd][sg * 5 + i];
                acc[i][0] += a * kv.x;
                acc[i][1] += a * kv.y;
                acc[i][2] += a * kv.z;
                acc[i][3] += a * kv.w;
            }
        }
        __syncthreads();
    }
    const float scale = 0.0625f;
#pragma unroll
    for (int i = 0; i < 5; i++) {
        int s = sg * 5 + i;
#pragma unroll
        for (int j = 0; j < 4; j++) {
            int tglob = t0 + (tg << 2) + j;
            if (tglob < TTOT) {
                float bias = (tglob < PREF) ? g_biasPref[b * PREF + tglob] : 0.f;
                g_sc[((size_t)bh * SEQ + s) * TPAD + tglob] = acc[i][j] * scale + bias;
            }
        }
    }
}

// ---------------- softmax ----------------
__global__ void __launch_bounds__(256) softmax_kernel()
{
    int row = blockIdx.x;
    float* p = g_sc + (size_t)row * TPAD;
    __shared__ float red[256];
    float mx = -1e30f;
    for (int i = threadIdx.x; i < TTOT; i += 256) mx = fmaxf(mx, p[i]);
    red[threadIdx.x] = mx;
    __syncthreads();
    for (int st = 128; st > 0; st >>= 1) {
        if (threadIdx.x < st) red[threadIdx.x] = fmaxf(red[threadIdx.x], red[threadIdx.x + st]);
        __syncthreads();
    }
    float m = red[0];
    __syncthreads();
    float s = 0.f;
    for (int i = threadIdx.x; i < TTOT; i += 256) {
        float e = expf(p[i] - m);
        p[i] = e;
        s += e;
    }
    red[threadIdx.x] = s;
    __syncthreads();
    for (int st = 128; st > 0; st >>= 1) {
        if (threadIdx.x < st) red[threadIdx.x] += red[threadIdx.x + st];
        __syncthreads();
    }
    float inv = 1.f / red[0];
    for (int i = threadIdx.x; i < TTOT; i += 256) p[i] *= inv;
}

// ---------------- PV ----------------
__global__ void __launch_bounds__(160) pv_kernel(
    const float* __restrict__ vnew, const float* __restrict__ kvc,
    int layer, float* __restrict__ out)
{
    __shared__ float Ps[32][52];
    __shared__ float Vs[32][68];
    int tid = threadIdx.x;
    int bh = blockIdx.y;
    int b = bh >> 3, h = bh & 7;
    int d0 = blockIdx.x * 64;
    const float* Vcache = kvc + ((size_t)(layer * 2 + 1) * BATCH + b) * (size_t)(PREF * HEADD);
    int sg = tid / 16;
    int dg = tid % 16;
    float acc[5][4];
#pragma unroll
    for (int i = 0; i < 5; i++)
#pragma unroll
        for (int j = 0; j < 4; j++) acc[i][j] = 0.f;

    for (int t0 = 0; t0 < TTOT; t0 += 32) {
        for (int e = tid; e < SEQ * 32; e += 160) {
            int s = e >> 5, tt = e & 31;
            int tglob = t0 + tt;
            Ps[tt][s] = (tglob < TTOT) ? g_sc[((size_t)bh * SEQ + s) * TPAD + tglob] : 0.f;
        }
        for (int e = tid; e < 32 * 64; e += 160) {
            int dd = e & 63, tt = e >> 6;
            int tglob = t0 + tt;
            float v = 0.f;
            if (tglob < PREF)      v = Vcache[(size_t)tglob * 256 + d0 + dd];
            else if (tglob < TTOT) v = vnew[((size_t)(b * SEQ + (tglob - PREF))) * 256 + d0 + dd];
            Vs[tt][dd] = v;
        }
        __syncthreads();
#pragma unroll 8
        for (int tt = 0; tt < 32; tt++) {
            float4 vv = *(const float4*)(&Vs[tt][dg << 2]);
#pragma unroll
            for (int i = 0; i < 5; i++) {
                float a = Ps[tt][sg * 5 + i];
                acc[i][0] += a * vv.x;
                acc[i][1] += a * vv.y;
                acc[i][2] += a * vv.z;
                acc[i][3] += a * vv.w;
            }
        }
        __syncthreads();
    }
#pragma unroll
    for (int i = 0; i < 5; i++) {
        int s = sg * 5 + i;
#pragma unroll
        for (int j = 0; j < 4; j++) {
            int d = d0 + (dg << 2) + j;
            out[(((size_t)(b * SEQ + s)) * 8 + h) * 256 + d] = acc[i][j];
        }
    }
}

// ---------------- gelu(g)*u -> g ----------------
__global__ void gelumul_kernel(float* __restrict__ gg, const float* __restrict__ uu, int n)
{
    int idx = blockIdx.x * blockDim.x + threadIdx.x;
    if (idx >= n) return;
    float x = gg[idx];
    float t = tanhf(0.7978845608028654f * (x + 0.044715f * x * x * x));
    gg[idx] = 0.5f * x * (1.f + t) * uu[idx];
}

// ---------------- host ----------------
static inline dim3 gemm_grid(int M, int N) { return dim3((N + 63) / 64, (M + 63) / 64); }
static inline dim3 tc_grid(int M, int N) { return dim3(N / 128, (M + 127) / 128); }

extern "C" void kernel_launch(void* const* d_in, const int* in_sizes, int n_in,
                              void* d_out, int out_size)
{
    const float* x_t      = (const float*)d_in[0];
    const float* timestep = (const float*)d_in[1];
    const void*  mask     = d_in[2];
    const float* kvc      = (const float*)d_in[3];
    const float* Wa_in    = (const float*)d_in[4];
    const float* ba_in    = (const float*)d_in[5];
    const float* Wt_in    = (const float*)d_in[6];
    const float* bt_in    = (const float*)d_in[7];
    const float* Wt_out   = (const float*)d_in[8];
    const float* bt_out   = (const float*)d_in[9];
    const float* Wq       = (const float*)d_in[10];
    const float* Wk       = (const float*)d_in[11];
    const float* Wv       = (const float*)d_in[12];
    const float* Wo       = (const float*)d_in[13];
    const float* Wg       = (const float*)d_in[14];
    const float* Wu       = (const float*)d_in[15];
    const float* Wd       = (const float*)d_in[16];
    const float* n1_w     = (const float*)d_in[17];
    const float* n2_w     = (const float*)d_in[18];
    const float* Wada1    = (const float*)d_in[19];
    const float* Wada2    = (const float*)d_in[20];
    const float* nf_w     = (const float*)d_in[21];
    const float* Wa_out   = (const float*)d_in[22];
    const float* ba_out   = (const float*)d_in[23];

    cudaFuncSetAttribute(mma_gemm_kernel,
                         cudaFuncAttributeMaxDynamicSharedMemorySize, SMEM_MMA_BYTES);

    void* p;
    cudaGetSymbolAddress(&p, g_x);    float* px    = (float*)p;
    cudaGetSymbolAddress(&p, g_h);    float* ph    = (float*)p;
    cudaGetSymbolAddress(&p, g_temb); float* ptemb = (float*)p;
    cudaGetSymbolAddress(&p, g_t1);   float* pt1   = (float*)p;
    cudaGetSymbolAddress(&p, g_tv);   float* ptv   = (float*)p;
    cudaGetSymbolAddress(&p, g_ada);  float* pada  = (float*)p;
    cudaGetSymbolAddress(&p, g_q);    float* pq    = (float*)p;
    cudaGetSymbolAddress(&p, g_k);    float* pk    = (float*)p;
    cudaGetSymbolAddress(&p, g_v);    float* pv    = (float*)p;
    cudaGetSymbolAddress(&p, g_ao);   float* pao   = (float*)p;
    cudaGetSymbolAddress(&p, g_gg);   float* pg    = (float*)p;
    cudaGetSymbolAddress(&p, g_uu);   float* pu    = (float*)p;

    prep_kernel<<<16, 512>>>(mask, timestep);

    gemv8_kernel<<<16, 256>>>(ptemb, Wt_in, bt_in, pt1, 8, HDIM, HDIM, 1);
    gemv8_kernel<<<16, 256>>>(pt1, Wt_out, bt_out, ptv, 8, HDIM, HDIM, 1);

    sgemm_kernel<<<gemm_grid(MTOK, HDIM), 256>>>(x_t, Wa_in, px, ba_in,
                                                 MTOK, HDIM, ADIM, ADIM, 0);

    for (int l = 0; l < NLAYER; l++) {
        const float* wq = Wq + (size_t)l * HDIM * (NHEAD * HEADD);
        const float* wk = Wk + (size_t)l * HDIM * HEADD;
        const float* wv = Wv + (size_t)l * HDIM * HEADD;
        const float* wo = Wo + (size_t)l * (NHEAD * HEADD) * HDIM;
        const float* wg = Wg + (size_t)l * HDIM * MLPD;
        const float* wu = Wu + (size_t)l * HDIM * MLPD;
        const float* wd = Wd + (size_t)l * MLPD * HDIM;
        const float* w1 = n1_w + (size_t)l * HDIM;
        const float* w2 = n2_w + (size_t)l * HDIM;
        const float* wa1 = Wada1 + (size_t)l * HDIM * HDIM;
        const float* wa2 = Wada2 + (size_t)l * HDIM * HDIM;

        gemv8_kernel<<<16, 256>>>(ptv, wa1, nullptr, pada, 8, HDIM, HDIM, 0);
        rmsnorm_kernel<<<MTOK, 256>>>(px, w1, pada, ph);

        mma_gemm_kernel<<<tc_grid(MTOK, NHEAD * HEADD), 256, SMEM_MMA_BYTES>>>(
            ph, wq, pq, MTOK, NHEAD * HEADD, HDIM, 0);
        mma_gemm_kernel<<<tc_grid(MTOK, HEADD), 256, SMEM_MMA_BYTES>>>(
            ph, wk, pk, MTOK, HEADD, HDIM, 0);
        mma_gemm_kernel<<<tc_grid(MTOK, HEADD), 256, SMEM_MMA_BYTES>>>(
            ph, wv, pv, MTOK, HEADD, HDIM, 0);
        rope_kernel<<<(MTOK * 9 * 128 + 255) / 256, 256>>>(pq, pk);

        scores_kernel<<<dim3((TTOT + 63) / 64, BATCH * NHEAD), 160>>>(pq, pk, kvc, l);
        softmax_kernel<<<BATCH * NHEAD * SEQ, 256>>>();
        pv_kernel<<<dim3(HEADD / 64, BATCH * NHEAD), 160>>>(pv, kvc, l, pao);

        mma_gemm_kernel<<<tc_grid(MTOK, HDIM), 256, SMEM_MMA_BYTES>>>(
            pao, wo, px, MTOK, HDIM, NHEAD * HEADD, 1);

        gemv8_kernel<<<16, 256>>>(ptv, wa2, nullptr, pada, 8, HDIM, HDIM, 0);
        rmsnorm_kernel<<<MTOK, 256>>>(px, w2, pada, ph);

        mma_gemm_kernel<<<tc_grid(MTOK, MLPD), 256, SMEM_MMA_BYTES>>>(
            ph, wg, pg, MTOK, MLPD, HDIM, 0);
        mma_gemm_kernel<<<tc_grid(MTOK, MLPD), 256, SMEM_MMA_BYTES>>>(
            ph, wu, pu, MTOK, MLPD, HDIM, 0);
        gelumul_kernel<<<(MTOK * MLPD + 255) / 256, 256>>>(pg, pu, MTOK * MLPD);
        mma_gemm_kernel<<<tc_grid(MTOK, HDIM), 256, SMEM_MMA_BYTES>>>(
            pg, wd, px, MTOK, HDIM, MLPD, 1);
    }

    rmsnorm_kernel<<<MTOK, 256>>>(px, nf_w, nullptr, ph);
    sgemm_kernel<<<gemm_grid(MTOK, ADIM), 256>>>(ph, Wa_out, (float*)d_out, ba_out,
                                                 MTOK, ADIM, HDIM, HDIM, 0);
}

// round 5
// speedup vs baseline: 1.8606x; 1.7845x over previous
#include <cuda_runtime.h>
#include <math.h>
#include <stdint.h>

// ---------------- problem dims ----------------
#define NLAYER 18
#define HDIM   1024
#define NHEAD  8
#define HEADD  256
#define MLPD   4096
#define BATCH  8
#define SEQ    50
#define PREF   800
#define ADIM   32
#define TTOT   850
#define TPAD   864
#define MTOK   400

// ---------------- device scratch ----------------
__device__ float g_x[MTOK * HDIM];
__device__ float g_h[MTOK * HDIM];
__device__ float g_temb[BATCH * HDIM];
__device__ float g_t1[BATCH * HDIM];
__device__ float g_tv[BATCH * HDIM];
__device__ float g_adaAll[2 * NLAYER * BATCH * HDIM];
__device__ float g_q[MTOK * NHEAD * HEADD];
__device__ float g_k[MTOK * HEADD];
__device__ float g_v[MTOK * HEADD];
__device__ float g_sc[BATCH * NHEAD * SEQ * TPAD];
__device__ float g_ao[MTOK * NHEAD * HEADD];
__device__ float g_gg[MTOK * MLPD];
__device__ float g_uu[MTOK * MLPD];
__device__ int   g_plen[BATCH];
__device__ float g_biasPref[BATCH * PREF];

// ---------------- bf16 split helpers ----------------
// word: lo 16 bits = bf16(lo_val) [even k], hi 16 bits = bf16(hi_val) [odd k]
__device__ __forceinline__ void split2(float lo, float hi, uint32_t& hw, uint32_t& lw) {
    asm("cvt.rn.bf16x2.f32 %0, %1, %2;" : "=r"(hw) : "f"(hi), "f"(lo));
    float hlo = __uint_as_float(hw << 16);
    float hhi = __uint_as_float(hw & 0xffff0000u);
    asm("cvt.rn.bf16x2.f32 %0, %1, %2;" : "=r"(lw) : "f"(hi - hhi), "f"(lo - hlo));
}
__device__ __forceinline__ void mma_bf16(
    float c[4], const uint32_t a[4], uint32_t b0, uint32_t b1)
{
    asm volatile(
        "mma.sync.aligned.m16n8k16.row.col.f32.bf16.bf16.f32 "
        "{%0,%1,%2,%3}, {%4,%5,%6,%7}, {%8,%9}, {%0,%1,%2,%3};"
        : "+f"(c[0]), "+f"(c[1]), "+f"(c[2]), "+f"(c[3])
        : "r"(a[0]), "r"(a[1]), "r"(a[2]), "r"(a[3]), "r"(b0), "r"(b1));
}
__device__ __forceinline__ float gelu_f(float x) {
    float t = tanhf(0.7978845608028654f * (x + 0.044715f * x * x * x));
    return 0.5f * x * (1.f + t);
}

// ============ split-bf16 (3-term) mma GEMM core ============
// Tile 128x128x32 (16 packed kw per chunk). 256 threads, 8 warps (2m x 4n).
// C[M,*] row stride Nw; colBase local to segment. K % 32 == 0, Nw seg % 128 == 0.
// epiMode: 0 store, 1 accumulate (+= C), 2 gated (v = gelu(Cg[off]) * v).
#define PADA 20
#define PADB 136
__device__ __forceinline__ void gemm_core(
    const float* __restrict__ A, const float* __restrict__ W,
    float* __restrict__ C, const float* __restrict__ Cg,
    int M, int Nw, int K, int rowBase, int colBase, int epiMode,
    uint32_t* AsHi, uint32_t* AsLo, uint32_t* BsHi, uint32_t* BsLo)
{
    const int tid  = threadIdx.x;
    const int lane = tid & 31;
    const int warp = tid >> 5;
    const int wm = (warp & 1) << 6;
    const int wn = (warp >> 1) << 5;

    const int aRow = tid >> 3;             // 0..31 (+32 per pass)
    const int aK4  = (tid & 7) << 2;       // k offset within chunk
    const int aKw  = (tid & 7) << 1;       // packed word offset
    const int bKw  = tid >> 4;             // 0..15
    const int bN   = (tid & 15) << 3;      // 0..120

    float c[4][4][4];
#pragma unroll
    for (int i = 0; i < 4; i++)
#pragma unroll
        for (int j = 0; j < 4; j++)
#pragma unroll
            for (int r = 0; r < 4; r++) c[i][j][r] = 0.f;

    float4 pa[4], pb[4];
    {
        // prefetch chunk 0
#pragma unroll
        for (int p = 0; p < 4; p++) {
            int gr = rowBase + aRow + (p << 5);
            pa[p] = make_float4(0.f, 0.f, 0.f, 0.f);
            if (gr < M) pa[p] = *(const float4*)(A + (size_t)gr * K + aK4);
        }
        const float* br0 = W + (size_t)(2 * bKw) * Nw + colBase + bN;
        pb[0] = *(const float4*)(br0);
        pb[1] = *(const float4*)(br0 + 4);
        pb[2] = *(const float4*)(br0 + Nw);
        pb[3] = *(const float4*)(br0 + Nw + 4);
    }

    const int nChunks = K >> 5;
    for (int i = 0; i < nChunks; i++) {
        // ---- store packed tiles ----
#pragma unroll
        for (int p = 0; p < 4; p++) {
            int r = aRow + (p << 5);
            uint32_t h0, l0, h1, l1;
            split2(pa[p].x, pa[p].y, h0, l0);
            split2(pa[p].z, pa[p].w, h1, l1);
            *(uint2*)(&AsHi[r * PADA + aKw]) = make_uint2(h0, h1);
            *(uint2*)(&AsLo[r * PADA + aKw]) = make_uint2(l0, l1);
        }
        {
            uint32_t hw[8], lw[8];
            const float* p0 = (const float*)&pb[0];
            const float* p1 = (const float*)&pb[2];
#pragma unroll
            for (int j = 0; j < 8; j++) split2(p0[j], p1[j], hw[j], lw[j]);
            *(uint4*)(&BsHi[bKw * PADB + bN])     = make_uint4(hw[0], hw[1], hw[2], hw[3]);
            *(uint4*)(&BsHi[bKw * PADB + bN + 4]) = make_uint4(hw[4], hw[5], hw[6], hw[7]);
            *(uint4*)(&BsLo[bKw * PADB + bN])     = make_uint4(lw[0], lw[1], lw[2], lw[3]);
            *(uint4*)(&BsLo[bKw * PADB + bN + 4]) = make_uint4(lw[4], lw[5], lw[6], lw[7]);
        }
        __syncthreads();

        // ---- prefetch next chunk ----
        if (i + 1 < nChunks) {
            int k0 = (i + 1) << 5;
#pragma unroll
            for (int p = 0; p < 4; p++) {
                int gr = rowBase + aRow + (p << 5);
                pa[p] = make_float4(0.f, 0.f, 0.f, 0.f);
                if (gr < M) pa[p] = *(const float4*)(A + (size_t)gr * K + k0 + aK4);
            }
            const float* br0 = W + (size_t)(k0 + 2 * bKw) * Nw + colBase + bN;
            pb[0] = *(const float4*)(br0);
            pb[1] = *(const float4*)(br0 + 4);
            pb[2] = *(const float4*)(br0 + Nw);
            pb[3] = *(const float4*)(br0 + Nw + 4);
        }

        // ---- compute: 2 k16-steps ----
#pragma unroll
        for (int ks = 0; ks < 2; ks++) {
            const int kf = (ks << 3) + (lane & 3);
            uint32_t bh[4][2], bl[4][2];
#pragma unroll
            for (int nf = 0; nf < 4; nf++) {
                int n0 = wn + (nf << 3) + (lane >> 2);
                bh[nf][0] = BsHi[kf * PADB + n0];
                bh[nf][1] = BsHi[(kf + 4) * PADB + n0];
                bl[nf][0] = BsLo[kf * PADB + n0];
                bl[nf][1] = BsLo[(kf + 4) * PADB + n0];
            }
#pragma unroll
            for (int mf = 0; mf < 4; mf++) {
                int m0 = wm + (mf << 4) + (lane >> 2);
                uint32_t ah[4], al[4];
                ah[0] = AsHi[m0 * PADA + kf];
                ah[1] = AsHi[(m0 + 8) * PADA + kf];
                ah[2] = AsHi[m0 * PADA + kf + 4];
                ah[3] = AsHi[(m0 + 8) * PADA + kf + 4];
                al[0] = AsLo[m0 * PADA + kf];
                al[1] = AsLo[(m0 + 8) * PADA + kf];
                al[2] = AsLo[m0 * PADA + kf + 4];
                al[3] = AsLo[(m0 + 8) * PADA + kf + 4];
#pragma unroll
                for (int nf = 0; nf < 4; nf++) {
                    mma_bf16(c[mf][nf], al, bh[nf][0], bh[nf][1]);
                    mma_bf16(c[mf][nf], ah, bl[nf][0], bl[nf][1]);
                    mma_bf16(c[mf][nf], ah, bh[nf][0], bh[nf][1]);
                }
            }
        }
        __syncthreads();
    }

    // ---- epilogue ----
#pragma unroll
    for (int mf = 0; mf < 4; mf++) {
        int r0 = rowBase + wm + (mf << 4) + (lane >> 2);
#pragma unroll
        for (int nf = 0; nf < 4; nf++) {
            int cc = colBase + wn + (nf << 3) + ((lane & 3) << 1);
#pragma unroll
            for (int half = 0; half < 2; half++) {
                int rr = r0 + half * 8;
                if (rr >= M) continue;
                size_t off = (size_t)rr * Nw + cc;
                float2 v = make_float2(c[mf][nf][half * 2], c[mf][nf][half * 2 + 1]);
                if (epiMode == 1) {
                    float2 old = *(float2*)(C + off);
                    v.x += old.x; v.y += old.y;
                } else if (epiMode == 2) {
                    float2 gg = *(const float2*)(Cg + off);
                    v.x *= gelu_f(gg.x); v.y *= gelu_f(gg.y);
                }
                *(float2*)(C + off) = v;
            }
        }
    }
}

#define GEMM_SHARED \
    __shared__ uint32_t AsHi[128 * PADA]; \
    __shared__ uint32_t AsLo[128 * PADA]; \
    __shared__ uint32_t BsHi[16 * PADB]; \
    __shared__ uint32_t BsLo[16 * PADB];

__global__ void __launch_bounds__(256) mma_gemm_kernel(
    const float* __restrict__ A, const float* __restrict__ W,
    float* __restrict__ C, const float* __restrict__ Cg,
    int M, int N, int K, int epiMode)
{
    GEMM_SHARED
    gemm_core(A, W, C, Cg, M, N, K, blockIdx.y * 128, blockIdx.x * 128, epiMode,
              AsHi, AsLo, BsHi, BsLo);
}

// fused QKV: grid.x = 20 (16 Q + 2 K + 2 V), grid.y = 4
__global__ void __launch_bounds__(256) qkv_kernel(
    const float* __restrict__ A,
    const float* __restrict__ Wq, const float* __restrict__ Wk, const float* __restrict__ Wv,
    float* __restrict__ oq, float* __restrict__ ok, float* __restrict__ ov)
{
    GEMM_SHARED
    int bx = blockIdx.x;
    const float* W; float* C; int Nw, colBase;
    if (bx < 16)      { W = Wq; C = oq; Nw = 2048; colBase = bx * 128; }
    else if (bx < 18) { W = Wk; C = ok; Nw = 256;  colBase = (bx - 16) * 128; }
    else              { W = Wv; C = ov; Nw = 256;  colBase = (bx - 18) * 128; }
    gemm_core(A, W, C, nullptr, MTOK, Nw, HDIM, blockIdx.y * 128, colBase, 0,
              AsHi, AsLo, BsHi, BsLo);
}

// ---------------- prep: mask -> plen/bias, time embedding ----------------
__global__ void prep_kernel(const void* __restrict__ maskp,
                            const float* __restrict__ ts)
{
    int bb = blockIdx.x;
    if (bb < BATCH) {
        int b = bb;
        const int* mi = (const int*)maskp;
        const unsigned char* mu = (const unsigned char*)maskp;
        int w0 = mi[0];
        bool is_i32 = (w0 == 0 || w0 == 1);
        __shared__ int cnt;
        if (threadIdx.x == 0) cnt = 0;
        __syncthreads();
        int local = 0;
        for (int t = threadIdx.x; t < PREF; t += blockDim.x) {
            int m = is_i32 ? mi[b * PREF + t] : (int)mu[b * PREF + t];
            bool on = (m != 0);
            g_biasPref[b * PREF + t] = on ? 0.f : -1e9f;
            if (on) local++;
        }
        atomicAdd(&cnt, local);
        __syncthreads();
        if (threadIdx.x == 0) g_plen[b] = cnt;
    } else {
        int b = bb - BATCH;
        float tsb = ts[b];
        for (int i = threadIdx.x; i < 512; i += blockDim.x) {
            float frac = (float)i / 511.f;
            float period = 4e-3f * powf(1000.f, frac);
            float arg = (6.283185307179586f / period) * tsb;
            float sv, cv;
            sincosf(arg, &sv, &cv);
            g_temb[b * HDIM + i]       = sv;
            g_temb[b * HDIM + 512 + i] = cv;
        }
    }
}

// ---------------- SIMT SGEMM (small GEMMs only) ----------------
__global__ void __launch_bounds__(256) sgemm_kernel(
    const float* __restrict__ A, const float* __restrict__ W,
    float* __restrict__ C, const float* __restrict__ bias,
    int M, int N, int K, int lda, int accumulate)
{
    __shared__ float As[16][64];
    __shared__ float Bs[16][64];
    const int tid = threadIdx.x;
    const int tx = tid & 15;
    const int ty = tid >> 4;
    const int rowBase = blockIdx.y * 64;
    const int colBase = blockIdx.x * 64;

    const int lm  = tid >> 2;
    const int lk  = (tid & 3) << 2;
    const int lkr = tid >> 4;
    const int ln  = (tid & 15) << 2;

    float acc[4][4];
#pragma unroll
    for (int i = 0; i < 4; i++)
#pragma unroll
        for (int j = 0; j < 4; j++) acc[i][j] = 0.f;

    for (int k0 = 0; k0 < K; k0 += 16) {
        float4 av = make_float4(0.f, 0.f, 0.f, 0.f);
        int ar = rowBase + lm;
        if (ar < M) av = *(const float4*)(A + (size_t)ar * lda + (k0 + lk));
        As[lk + 0][lm] = av.x;
        As[lk + 1][lm] = av.y;
        As[lk + 2][lm] = av.z;
        As[lk + 3][lm] = av.w;

        float4 bv;
        int bn = colBase + ln;
        const float* wrow = W + (size_t)(k0 + lkr) * N;
        if (bn + 3 < N) {
            bv = *(const float4*)(wrow + bn);
        } else {
            bv.x = (bn + 0 < N) ? wrow[bn + 0] : 0.f;
            bv.y = (bn + 1 < N) ? wrow[bn + 1] : 0.f;
            bv.z = (bn + 2 < N) ? wrow[bn + 2] : 0.f;
            bv.w = (bn + 3 < N) ? wrow[bn + 3] : 0.f;
        }
        *(float4*)(&Bs[lkr][ln]) = bv;
        __syncthreads();

#pragma unroll
        for (int kk = 0; kk < 16; kk++) {
            float4 a = *(const float4*)(&As[kk][ty << 2]);
            float4 b = *(const float4*)(&Bs[kk][tx << 2]);
            acc[0][0] += a.x * b.x; acc[0][1] += a.x * b.y; acc[0][2] += a.x * b.z; acc[0][3] += a.x * b.w;
            acc[1][0] += a.y * b.x; acc[1][1] += a.y * b.y; acc[1][2] += a.y * b.z; acc[1][3] += a.y * b.w;
            acc[2][0] += a.z * b.x; acc[2][1] += a.z * b.y; acc[2][2] += a.z * b.z; acc[2][3] += a.z * b.w;
            acc[3][0] += a.w * b.x; acc[3][1] += a.w * b.y; acc[3][2] += a.w * b.z; acc[3][3] += a.w * b.w;
        }
        __syncthreads();
    }

#pragma unroll
    for (int i = 0; i < 4; i++) {
        int r = rowBase + (ty << 2) + i;
        if (r >= M) continue;
#pragma unroll
        for (int j = 0; j < 4; j++) {
            int cx = colBase + (tx << 2) + j;
            if (cx >= N) continue;
            float v = acc[i][j];
            if (bias) v += bias[cx];
            size_t off = (size_t)r * N + cx;
            if (accumulate) v += C[off];
            C[off] = v;
        }
    }
}

// ---------------- small-M (M<=8) GEMM core ----------------
__device__ __forceinline__ void gemv8_core(
    const float* __restrict__ A, const float* __restrict__ W,
    const float* __restrict__ bias, float* __restrict__ C,
    int N, int K, int act, int bx)
{
    __shared__ float a_s[8 * 1024];
    __shared__ float red[4 * 64 * 8];
    int tid = threadIdx.x;
    for (int e = tid; e < 8 * K; e += 256) a_s[e] = A[e];
    __syncthreads();

    int nl = tid & 63;
    int n  = bx * 64 + nl;
    int ks = tid >> 6;
    float acc[8];
#pragma unroll
    for (int m = 0; m < 8; m++) acc[m] = 0.f;

    int kc = K >> 2;
    if (n < N) {
        int kbeg = ks * kc;
#pragma unroll 4
        for (int k = 0; k < kc; k++) {
            float w = W[(size_t)(kbeg + k) * N + n];
#pragma unroll
            for (int m = 0; m < 8; m++) acc[m] += a_s[m * K + kbeg + k] * w;
        }
    }
#pragma unroll
    for (int m = 0; m < 8; m++) red[tid * 8 + m] = acc[m];
    __syncthreads();
    if (ks == 0 && n < N) {
#pragma unroll
        for (int m = 0; m < 8; m++) {
            float v = red[(0 * 64 + nl) * 8 + m] + red[(1 * 64 + nl) * 8 + m] +
                      red[(2 * 64 + nl) * 8 + m] + red[(3 * 64 + nl) * 8 + m];
            if (bias) v += bias[n];
            if (act == 1) v = v / (1.f + expf(-v));
            C[(size_t)m * N + n] = v;
        }
    }
}

__global__ void __launch_bounds__(256) gemv8_kernel(
    const float* __restrict__ A, const float* __restrict__ W,
    const float* __restrict__ bias, float* __restrict__ C,
    int N, int K, int act)
{
    gemv8_core(A, W, bias, C, N, K, act, blockIdx.x);
}

// all 36 ada projections in one launch: grid (16, 36)
__global__ void __launch_bounds__(256) adaall_kernel(
    const float* __restrict__ tvec,
    const float* __restrict__ Wada1, const float* __restrict__ Wada2,
    float* __restrict__ out)
{
    int li = blockIdx.y;
    const float* W = (li < NLAYER) ? (Wada1 + (size_t)li * HDIM * HDIM)
                                   : (Wada2 + (size_t)(li - NLAYER) * HDIM * HDIM);
    gemv8_core(tvec, W, nullptr, out + (size_t)li * BATCH * HDIM,
               HDIM, HDIM, 0, blockIdx.x);
}

// ---------------- rmsnorm (+optional ada gate) ----------------
__global__ void __launch_bounds__(256) rmsnorm_kernel(
    const float* __restrict__ x, const float* __restrict__ w,
    const float* __restrict__ ada, float* __restrict__ out)
{
    int row = blockIdx.x;
    int b = row / SEQ;
    const float* xr = x + (size_t)row * HDIM;
    __shared__ float red[256];
    float s = 0.f;
    for (int i = threadIdx.x; i < HDIM; i += 256) {
        float v = xr[i];
        s += v * v;
    }
    red[threadIdx.x] = s;
    __syncthreads();
    for (int st = 128; st > 0; st >>= 1) {
        if (threadIdx.x < st) red[threadIdx.x] += red[threadIdx.x + st];
        __syncthreads();
    }
    float r = rsqrtf(red[0] * (1.f / HDIM) + 1e-6f);
    for (int i = threadIdx.x; i < HDIM; i += 256) {
        float gmul = w[i];
        if (ada) gmul *= (1.f + ada[b * HDIM + i]);
        out[(size_t)row * HDIM + i] = xr[i] * r * gmul;
    }
}

// ---------------- rope ----------------
__global__ void rope_kernel(float* __restrict__ q, float* __restrict__ k)
{
    int idx = blockIdx.x * blockDim.x + threadIdx.x;
    const int total = MTOK * 9 * 128;
    if (idx >= total) return;
    int j = idx & 127;
    int rest = idx >> 7;
    int hh = rest % 9;
    int row = rest / 9;
    int b = row / SEQ, s = row % SEQ;
    float pos = (float)(g_plen[b] + s);
    float inv = powf(10000.f, -(float)j / 128.f);
    float fr = pos * inv;
    float sn, cs;
    sincosf(fr, &sn, &cs);
    float* p = (hh < 8) ? (q + ((size_t)row * 8 + hh) * 256) : (k + (size_t)row * 256);
    float x1 = p[j], x2 = p[j + 128];
    p[j]       = x1 * cs - x2 * sn;
    p[j + 128] = x2 * cs + x1 * sn;
}

// ---------------- attention scores ----------------
__global__ void __launch_bounds__(160) scores_kernel(
    const float* __restrict__ q, const float* __restrict__ knew,
    const float* __restrict__ kvc, int layer)
{
    __shared__ float Qs[32][52];
    __shared__ float Ks[32][68];
    int tid = threadIdx.x;
    int bh = blockIdx.y;
    int b = bh >> 3, h = bh & 7;
    int t0 = blockIdx.x * 64;
    const float* Kcache = kvc + ((size_t)(layer * 2) * BATCH + b) * (size_t)(PREF * HEADD);
    int sg = tid / 16;
    int tg = tid % 16;
    float acc[5][4];
#pragma unroll
    for (int i = 0; i < 5; i++)
#pragma unroll
        for (int j = 0; j < 4; j++) acc[i][j] = 0.f;

    for (int d0 = 0; d0 < HEADD; d0 += 32) {
        for (int e = tid; e < SEQ * 32; e += 160) {
            int s = e >> 5, dd = e & 31;
            Qs[dd][s] = q[(((size_t)(b * SEQ + s)) * 8 + h) * 256 + d0 + dd];
        }
        for (int e = tid; e < 64 * 32; e += 160) {
            int t = e >> 5, dd = e & 31;
            int tglob = t0 + t;
            float v = 0.f;
            if (tglob < PREF)      v = Kcache[(size_t)tglob * 256 + d0 + dd];
            else if (tglob < TTOT) v = knew[((size_t)(b * SEQ + (tglob - PREF))) * 256 + d0 + dd];
            Ks[dd][t] = v;
        }
        __syncthreads();
#pragma unroll 8
        for (int dd = 0; dd < 32; dd++) {
            float4 kv = *(const float4*)(&Ks[dd][tg << 2]);
#pragma unroll
            for (int i = 0; i < 5; i++) {
                float a = Qs[dd][sg * 5 + i];
                acc[i][0] += a * kv.x;
                acc[i][1] += a * kv.y;
                acc[i][2] += a * kv.z;
                acc[i][3] += a * kv.w;
            }
        }
        __syncthreads();
    }
    const float scale = 0.0625f;
#pragma unroll
    for (int i = 0; i < 5; i++) {
        int s = sg * 5 + i;
#pragma unroll
        for (int j = 0; j < 4; j++) {
            int tglob = t0 + (tg << 2) + j;
            if (tglob < TTOT) {
                float bias = (tglob < PREF) ? g_biasPref[b * PREF + tglob] : 0.f;
                g_sc[((size_t)bh * SEQ + s) * TPAD + tglob] = acc[i][j] * scale + bias;
            }
        }
    }
}

// ---------------- softmax ----------------
__global__ void __launch_bounds__(256) softmax_kernel()
{
    int row = blockIdx.x;
    float* p = g_sc + (size_t)row * TPAD;
    __shared__ float red[256];
    float mx = -1e30f;
    for (int i = threadIdx.x; i < TTOT; i += 256) mx = fmaxf(mx, p[i]);
    red[threadIdx.x] = mx;
    __syncthreads();
    for (int st = 128; st > 0; st >>= 1) {
        if (threadIdx.x < st) red[threadIdx.x] = fmaxf(red[threadIdx.x], red[threadIdx.x + st]);
        __syncthreads();
    }
    float m = red[0];
    __syncthreads();
    float s = 0.f;
    for (int i = threadIdx.x; i < TTOT; i += 256) {
        float e = expf(p[i] - m);
        p[i] = e;
        s += e;
    }
    red[threadIdx.x] = s;
    __syncthreads();
    for (int st = 128; st > 0; st >>= 1) {
        if (threadIdx.x < st) red[threadIdx.x] += red[threadIdx.x + st];
        __syncthreads();
    }
    float inv = 1.f / red[0];
    for (int i = threadIdx.x; i < TTOT; i += 256) p[i] *= inv;
}

// ---------------- PV ----------------
__global__ void __launch_bounds__(160) pv_kernel(
    const float* __restrict__ vnew, const float* __restrict__ kvc,
    int layer, float* __restrict__ out)
{
    __shared__ float Ps[32][52];
    __shared__ float Vs[32][68];
    int tid = threadIdx.x;
    int bh = blockIdx.y;
    int b = bh >> 3, h = bh & 7;
    int d0 = blockIdx.x * 64;
    const float* Vcache = kvc + ((size_t)(layer * 2 + 1) * BATCH + b) * (size_t)(PREF * HEADD);
    int sg = tid / 16;
    int dg = tid % 16;
    float acc[5][4];
#pragma unroll
    for (int i = 0; i < 5; i++)
#pragma unroll
        for (int j = 0; j < 4; j++) acc[i][j] = 0.f;

    for (int t0 = 0; t0 < TTOT; t0 += 32) {
        for (int e = tid; e < SEQ * 32; e += 160) {
            int s = e >> 5, tt = e & 31;
            int tglob = t0 + tt;
            Ps[tt][s] = (tglob < TTOT) ? g_sc[((size_t)bh * SEQ + s) * TPAD + tglob] : 0.f;
        }
        for (int e = tid; e < 32 * 64; e += 160) {
            int dd = e & 63, tt = e >> 6;
            int tglob = t0 + tt;
            float v = 0.f;
            if (tglob < PREF)      v = Vcache[(size_t)tglob * 256 + d0 + dd];
            else if (tglob < TTOT) v = vnew[((size_t)(b * SEQ + (tglob - PREF))) * 256 + d0 + dd];
            Vs[tt][dd] = v;
        }
        __syncthreads();
#pragma unroll 8
        for (int tt = 0; tt < 32; tt++) {
            float4 vv = *(const float4*)(&Vs[tt][dg << 2]);
#pragma unroll
            for (int i = 0; i < 5; i++) {
                float a = Ps[tt][sg * 5 + i];
                acc[i][0] += a * vv.x;
                acc[i][1] += a * vv.y;
                acc[i][2] += a * vv.z;
                acc[i][3] += a * vv.w;
            }
        }
        __syncthreads();
    }
#pragma unroll
    for (int i = 0; i < 5; i++) {
        int s = sg * 5 + i;
#pragma unroll
        for (int j = 0; j < 4; j++) {
            int d = d0 + (dg << 2) + j;
            out[(((size_t)(b * SEQ + s)) * 8 + h) * 256 + d] = acc[i][j];
        }
    }
}

// ---------------- host ----------------
static inline dim3 gemm_grid(int M, int N) { return dim3((N + 63) / 64, (M + 63) / 64); }
static inline dim3 tc_grid(int M, int N) { return dim3(N / 128, (M + 127) / 128); }

extern "C" void kernel_launch(void* const* d_in, const int* in_sizes, int n_in,
                              void* d_out, int out_size)
{
    const float* x_t      = (const float*)d_in[0];
    const float* timestep = (const float*)d_in[1];
    const void*  mask     = d_in[2];
    const float* kvc      = (const float*)d_in[3];
    const float* Wa_in    = (const float*)d_in[4];
    const float* ba_in    = (const float*)d_in[5];
    const float* Wt_in    = (const float*)d_in[6];
    const float* bt_in    = (const float*)d_in[7];
    const float* Wt_out   = (const float*)d_in[8];
    const float* bt_out   = (const float*)d_in[9];
    const float* Wq       = (const float*)d_in[10];
    const float* Wk       = (const float*)d_in[11];
    const float* Wv       = (const float*)d_in[12];
    const float* Wo       = (const float*)d_in[13];
    const float* Wg       = (const float*)d_in[14];
    const float* Wu       = (const float*)d_in[15];
    const float* Wd       = (const float*)d_in[16];
    const float* n1_w     = (const float*)d_in[17];
    const float* n2_w     = (const float*)d_in[18];
    const float* Wada1    = (const float*)d_in[19];
    const float* Wada2    = (const float*)d_in[20];
    const float* nf_w     = (const float*)d_in[21];
    const float* Wa_out   = (const float*)d_in[22];
    const float* ba_out   = (const float*)d_in[23];

    void* p;
    cudaGetSymbolAddress(&p, g_x);      float* px    = (float*)p;
    cudaGetSymbolAddress(&p, g_h);      float* ph    = (float*)p;
    cudaGetSymbolAddress(&p, g_temb);   float* ptemb = (float*)p;
    cudaGetSymbolAddress(&p, g_t1);     float* pt1   = (float*)p;
    cudaGetSymbolAddress(&p, g_tv);     float* ptv   = (float*)p;
    cudaGetSymbolAddress(&p, g_adaAll); float* padaA = (float*)p;
    cudaGetSymbolAddress(&p, g_q);      float* pq    = (float*)p;
    cudaGetSymbolAddress(&p, g_k);      float* pk    = (float*)p;
    cudaGetSymbolAddress(&p, g_v);      float* pv    = (float*)p;
    cudaGetSymbolAddress(&p, g_ao);     float* pao   = (float*)p;
    cudaGetSymbolAddress(&p, g_gg);     float* pg    = (float*)p;
    cudaGetSymbolAddress(&p, g_uu);     float* pu    = (float*)p;

    prep_kernel<<<16, 512>>>(mask, timestep);

    // time MLP, then ALL ada projections batched
    gemv8_kernel<<<16, 256>>>(ptemb, Wt_in, bt_in, pt1, HDIM, HDIM, 1);
    gemv8_kernel<<<16, 256>>>(pt1, Wt_out, bt_out, ptv, HDIM, HDIM, 1);
    adaall_kernel<<<dim3(16, 2 * NLAYER), 256>>>(ptv, Wada1, Wada2, padaA);

    // x = x_t @ Wa_in + ba_in
    sgemm_kernel<<<gemm_grid(MTOK, HDIM), 256>>>(x_t, Wa_in, px, ba_in,
                                                 MTOK, HDIM, ADIM, ADIM, 0);

    for (int l = 0; l < NLAYER; l++) {
        const float* wq = Wq + (size_t)l * HDIM * (NHEAD * HEADD);
        const float* wk = Wk + (size_t)l * HDIM * HEADD;
        const float* wv = Wv + (size_t)l * HDIM * HEADD;
        const float* wo = Wo + (size_t)l * (NHEAD * HEADD) * HDIM;
        const float* wg = Wg + (size_t)l * HDIM * MLPD;
        const float* wu = Wu + (size_t)l * HDIM * MLPD;
        const float* wd = Wd + (size_t)l * MLPD * HDIM;
        const float* w1 = n1_w + (size_t)l * HDIM;
        const float* w2 = n2_w + (size_t)l * HDIM;
        const float* ada1 = padaA + (size_t)l * BATCH * HDIM;
        const float* ada2 = padaA + (size_t)(NLAYER + l) * BATCH * HDIM;

        rmsnorm_kernel<<<MTOK, 256>>>(px, w1, ada1, ph);

        qkv_kernel<<<dim3(20, 4), 256>>>(ph, wq, wk, wv, pq, pk, pv);
        rope_kernel<<<(MTOK * 9 * 128 + 255) / 256, 256>>>(pq, pk);

        scores_kernel<<<dim3((TTOT + 63) / 64, BATCH * NHEAD), 160>>>(pq, pk, kvc, l);
        softmax_kernel<<<BATCH * NHEAD * SEQ, 256>>>();
        pv_kernel<<<dim3(HEADD / 64, BATCH * NHEAD), 160>>>(pv, kvc, l, pao);

        mma_gemm_kernel<<<tc_grid(MTOK, HDIM), 256>>>(
            pao, wo, px, nullptr, MTOK, HDIM, NHEAD * HEADD, 1);

        rmsnorm_kernel<<<MTOK, 256>>>(px, w2, ada2, ph);

        mma_gemm_kernel<<<tc_grid(MTOK, MLPD), 256>>>(
            ph, wg, pg, nullptr, MTOK, MLPD, HDIM, 0);
        // u GEMM with fused epilogue: pu = gelu(pg) * u
        mma_gemm_kernel<<<tc_grid(MTOK, MLPD), 256>>>(
            ph, wu, pu, pg, MTOK, MLPD, HDIM, 2);
        mma_gemm_kernel<<<tc_grid(MTOK, HDIM), 256>>>(
            pu, wd, px, nullptr, MTOK, HDIM, MLPD, 1);
    }

    rmsnorm_kernel<<<MTOK, 256>>>(px, nf_w, nullptr, ph);
    sgemm_kernel<<<gemm_grid(MTOK, ADIM), 256>>>(ph, Wa_out, (float*)d_out, ba_out,
                                                 MTOK, ADIM, HDIM, HDIM, 0);
}

// round 6
// speedup vs baseline: 2.5736x; 1.3832x over previous
#include <cuda_runtime.h>
#include <math.h>
#include <stdint.h>

// ---------------- problem dims ----------------
#define NLAYER 18
#define HDIM   1024
#define NHEAD  8
#define HEADD  256
#define MLPD   4096
#define BATCH  8
#define SEQ    50
#define PREF   800
#define ADIM   32
#define TTOT   850
#define TPAD   864
#define MTOK   400

// ---------------- device scratch ----------------
__device__ float g_x[MTOK * HDIM];
__device__ float g_h[MTOK * HDIM];
__device__ float g_temb[BATCH * HDIM];
__device__ float g_t1[BATCH * HDIM];
__device__ float g_tv[BATCH * HDIM];
__device__ float g_adaAll[2 * NLAYER * BATCH * HDIM];
__device__ float g_q[MTOK * NHEAD * HEADD];
__device__ float g_k[MTOK * HEADD];
__device__ float g_v[MTOK * HEADD];
__device__ float g_sc[BATCH * NHEAD * SEQ * TPAD];
__device__ float g_vt[BATCH * HEADD * TPAD];
__device__ float g_ao[MTOK * NHEAD * HEADD];
__device__ float g_gg[MTOK * MLPD];
__device__ float g_uu[MTOK * MLPD];
__device__ int   g_plen[BATCH];
__device__ float g_biasPref[BATCH * PREF];

// ---------------- bf16 split helpers ----------------
__device__ __forceinline__ void split2(float lo, float hi, uint32_t& hw, uint32_t& lw) {
    asm("cvt.rn.bf16x2.f32 %0, %1, %2;" : "=r"(hw) : "f"(hi), "f"(lo));
    float hlo = __uint_as_float(hw << 16);
    float hhi = __uint_as_float(hw & 0xffff0000u);
    asm("cvt.rn.bf16x2.f32 %0, %1, %2;" : "=r"(lw) : "f"(hi - hhi), "f"(lo - hlo));
}
__device__ __forceinline__ void mma_bf16(
    float c[4], const uint32_t a[4], uint32_t b0, uint32_t b1)
{
    asm volatile(
        "mma.sync.aligned.m16n8k16.row.col.f32.bf16.bf16.f32 "
        "{%0,%1,%2,%3}, {%4,%5,%6,%7}, {%8,%9}, {%0,%1,%2,%3};"
        : "+f"(c[0]), "+f"(c[1]), "+f"(c[2]), "+f"(c[3])
        : "r"(a[0]), "r"(a[1]), "r"(a[2]), "r"(a[3]), "r"(b0), "r"(b1));
}
__device__ __forceinline__ float gelu_f(float x) {
    float t = tanhf(0.7978845608028654f * (x + 0.044715f * x * x * x));
    return 0.5f * x * (1.f + t);
}

// ============ split-bf16 (3-term) mma GEMM core (W k-major) ============
#define PADA 20
#define PADB 136
__device__ __forceinline__ void gemm_core(
    const float* __restrict__ A, const float* __restrict__ W,
    float* __restrict__ C, const float* __restrict__ Cg,
    int M, int Nw, int K, int rowBase, int colBase, int epiMode,
    uint32_t* AsHi, uint32_t* AsLo, uint32_t* BsHi, uint32_t* BsLo)
{
    const int tid  = threadIdx.x;
    const int lane = tid & 31;
    const int warp = tid >> 5;
    const int wm = (warp & 1) << 6;
    const int wn = (warp >> 1) << 5;

    const int aRow = tid >> 3;
    const int aK4  = (tid & 7) << 2;
    const int aKw  = (tid & 7) << 1;
    const int bKw  = tid >> 4;
    const int bN   = (tid & 15) << 3;

    float c[4][4][4];
#pragma unroll
    for (int i = 0; i < 4; i++)
#pragma unroll
        for (int j = 0; j < 4; j++)
#pragma unroll
            for (int r = 0; r < 4; r++) c[i][j][r] = 0.f;

    float4 pa[4], pb[4];
    {
#pragma unroll
        for (int p = 0; p < 4; p++) {
            int gr = rowBase + aRow + (p << 5);
            pa[p] = make_float4(0.f, 0.f, 0.f, 0.f);
            if (gr < M) pa[p] = *(const float4*)(A + (size_t)gr * K + aK4);
        }
        const float* br0 = W + (size_t)(2 * bKw) * Nw + colBase + bN;
        pb[0] = *(const float4*)(br0);
        pb[1] = *(const float4*)(br0 + 4);
        pb[2] = *(const float4*)(br0 + Nw);
        pb[3] = *(const float4*)(br0 + Nw + 4);
    }

    const int nChunks = K >> 5;
    for (int i = 0; i < nChunks; i++) {
#pragma unroll
        for (int p = 0; p < 4; p++) {
            int r = aRow + (p << 5);
            uint32_t h0, l0, h1, l1;
            split2(pa[p].x, pa[p].y, h0, l0);
            split2(pa[p].z, pa[p].w, h1, l1);
            *(uint2*)(&AsHi[r * PADA + aKw]) = make_uint2(h0, h1);
            *(uint2*)(&AsLo[r * PADA + aKw]) = make_uint2(l0, l1);
        }
        {
            uint32_t hw[8], lw[8];
            const float* p0 = (const float*)&pb[0];
            const float* p1 = (const float*)&pb[2];
#pragma unroll
            for (int j = 0; j < 8; j++) split2(p0[j], p1[j], hw[j], lw[j]);
            *(uint4*)(&BsHi[bKw * PADB + bN])     = make_uint4(hw[0], hw[1], hw[2], hw[3]);
            *(uint4*)(&BsHi[bKw * PADB + bN + 4]) = make_uint4(hw[4], hw[5], hw[6], hw[7]);
            *(uint4*)(&BsLo[bKw * PADB + bN])     = make_uint4(lw[0], lw[1], lw[2], lw[3]);
            *(uint4*)(&BsLo[bKw * PADB + bN + 4]) = make_uint4(lw[4], lw[5], lw[6], lw[7]);
        }
        __syncthreads();

        if (i + 1 < nChunks) {
            int k0 = (i + 1) << 5;
#pragma unroll
            for (int p = 0; p < 4; p++) {
                int gr = rowBase + aRow + (p << 5);
                pa[p] = make_float4(0.f, 0.f, 0.f, 0.f);
                if (gr < M) pa[p] = *(const float4*)(A + (size_t)gr * K + k0 + aK4);
            }
            const float* br0 = W + (size_t)(k0 + 2 * bKw) * Nw + colBase + bN;
            pb[0] = *(const float4*)(br0);
            pb[1] = *(const float4*)(br0 + 4);
            pb[2] = *(const float4*)(br0 + Nw);
            pb[3] = *(const float4*)(br0 + Nw + 4);
        }

#pragma unroll
        for (int ks = 0; ks < 2; ks++) {
            const int kf = (ks << 3) + (lane & 3);
            uint32_t bh[4][2], bl[4][2];
#pragma unroll
            for (int nf = 0; nf < 4; nf++) {
                int n0 = wn + (nf << 3) + (lane >> 2);
                bh[nf][0] = BsHi[kf * PADB + n0];
                bh[nf][1] = BsHi[(kf + 4) * PADB + n0];
                bl[nf][0] = BsLo[kf * PADB + n0];
                bl[nf][1] = BsLo[(kf + 4) * PADB + n0];
            }
#pragma unroll
            for (int mf = 0; mf < 4; mf++) {
                int m0 = wm + (mf << 4) + (lane >> 2);
                uint32_t ah[4], al[4];
                ah[0] = AsHi[m0 * PADA + kf];
                ah[1] = AsHi[(m0 + 8) * PADA + kf];
                ah[2] = AsHi[m0 * PADA + kf + 4];
                ah[3] = AsHi[(m0 + 8) * PADA + kf + 4];
                al[0] = AsLo[m0 * PADA + kf];
                al[1] = AsLo[(m0 + 8) * PADA + kf];
                al[2] = AsLo[m0 * PADA + kf + 4];
                al[3] = AsLo[(m0 + 8) * PADA + kf + 4];
#pragma unroll
                for (int nf = 0; nf < 4; nf++) {
                    mma_bf16(c[mf][nf], al, bh[nf][0], bh[nf][1]);
                    mma_bf16(c[mf][nf], ah, bl[nf][0], bl[nf][1]);
                    mma_bf16(c[mf][nf], ah, bh[nf][0], bh[nf][1]);
                }
            }
        }
        __syncthreads();
    }

#pragma unroll
    for (int mf = 0; mf < 4; mf++) {
        int r0 = rowBase + wm + (mf << 4) + (lane >> 2);
#pragma unroll
        for (int nf = 0; nf < 4; nf++) {
            int cc = colBase + wn + (nf << 3) + ((lane & 3) << 1);
#pragma unroll
            for (int half = 0; half < 2; half++) {
                int rr = r0 + half * 8;
                if (rr >= M) continue;
                size_t off = (size_t)rr * Nw + cc;
                float2 v = make_float2(c[mf][nf][half * 2], c[mf][nf][half * 2 + 1]);
                if (epiMode == 1) {
                    float2 old = *(float2*)(C + off);
                    v.x += old.x; v.y += old.y;
                } else if (epiMode == 2) {
                    float2 gg = *(const float2*)(Cg + off);
                    v.x *= gelu_f(gg.x); v.y *= gelu_f(gg.y);
                }
                *(float2*)(C + off) = v;
            }
        }
    }
}

#define GEMM_SHARED \
    __shared__ uint32_t AsHi[128 * PADA]; \
    __shared__ uint32_t AsLo[128 * PADA]; \
    __shared__ uint32_t BsHi[16 * PADB]; \
    __shared__ uint32_t BsLo[16 * PADB];

__global__ void __launch_bounds__(256) mma_gemm_kernel(
    const float* __restrict__ A, const float* __restrict__ W,
    float* __restrict__ C, const float* __restrict__ Cg,
    int M, int N, int K, int epiMode)
{
    GEMM_SHARED
    gemm_core(A, W, C, Cg, M, N, K, blockIdx.y * 128, blockIdx.x * 128, epiMode,
              AsHi, AsLo, BsHi, BsLo);
}

// fused QKV: grid.x = 20 (16 Q + 2 K + 2 V), grid.y = 4
__global__ void __launch_bounds__(256) qkv_kernel(
    const float* __restrict__ A,
    const float* __restrict__ Wq, const float* __restrict__ Wk, const float* __restrict__ Wv,
    float* __restrict__ oq, float* __restrict__ ok, float* __restrict__ ov)
{
    GEMM_SHARED
    int bx = blockIdx.x;
    const float* W; float* C; int Nw, colBase;
    if (bx < 16)      { W = Wq; C = oq; Nw = 2048; colBase = bx * 128; }
    else if (bx < 18) { W = Wk; C = ok; Nw = 256;  colBase = (bx - 16) * 128; }
    else              { W = Wv; C = ov; Nw = 256;  colBase = (bx - 18) * 128; }
    gemm_core(A, W, C, nullptr, MTOK, Nw, HDIM, blockIdx.y * 128, colBase, 0,
              AsHi, AsLo, BsHi, BsLo);
}

// ============ attention scores via split-bf16 MMA ============
// grid (7, 4, 8) = (tTile128, rTile128, b). S = Q @ K^T * 1/16 + bias.
// B operand (K rows) is natively k-contiguous -> n-major smem, PADA layout.
__global__ void __launch_bounds__(256) attn_scores_kernel(
    const float* __restrict__ q, const float* __restrict__ knew,
    const float* __restrict__ kvc, int layer)
{
    __shared__ uint32_t AsHi[128 * PADA];
    __shared__ uint32_t AsLo[128 * PADA];
    __shared__ uint32_t BsHi[128 * PADA];
    __shared__ uint32_t BsLo[128 * PADA];

    const int tid  = threadIdx.x;
    const int lane = tid & 31;
    const int warp = tid >> 5;
    const int wm = (warp & 1) << 6;
    const int wn = (warp >> 1) << 5;
    const int b = blockIdx.z;
    const int rowBase = blockIdx.y * 128;
    const int colBase = blockIdx.x * 128;

    const float* Kc = kvc + ((size_t)(layer * 2) * BATCH + b) * (size_t)(PREF * HEADD);
    const float* Ab = q + (size_t)b * 400 * 256;

    const int aRow = tid >> 3;
    const int aK4  = (tid & 7) << 2;
    const int aKw  = (tid & 7) << 1;

    float c[4][4][4];
#pragma unroll
    for (int i = 0; i < 4; i++)
#pragma unroll
        for (int j = 0; j < 4; j++)
#pragma unroll
            for (int r = 0; r < 4; r++) c[i][j][r] = 0.f;

    float4 pa[4], pb[4];
#pragma unroll
    for (int p = 0; p < 4; p++) {
        int gr = rowBase + aRow + (p << 5);
        pa[p] = make_float4(0.f, 0.f, 0.f, 0.f);
        if (gr < 400) pa[p] = *(const float4*)(Ab + (size_t)gr * 256 + aK4);
        int t = colBase + aRow + (p << 5);
        pb[p] = make_float4(0.f, 0.f, 0.f, 0.f);
        if (t < PREF)      pb[p] = *(const float4*)(Kc + (size_t)t * 256 + aK4);
        else if (t < TTOT) pb[p] = *(const float4*)(knew + ((size_t)(b * SEQ + t - PREF)) * 256 + aK4);
    }

#pragma unroll 1
    for (int i = 0; i < 8; i++) {
#pragma unroll
        for (int p = 0; p < 4; p++) {
            int r = aRow + (p << 5);
            uint32_t h0, l0, h1, l1;
            split2(pa[p].x, pa[p].y, h0, l0);
            split2(pa[p].z, pa[p].w, h1, l1);
            *(uint2*)(&AsHi[r * PADA + aKw]) = make_uint2(h0, h1);
            *(uint2*)(&AsLo[r * PADA + aKw]) = make_uint2(l0, l1);
            split2(pb[p].x, pb[p].y, h0, l0);
            split2(pb[p].z, pb[p].w, h1, l1);
            *(uint2*)(&BsHi[r * PADA + aKw]) = make_uint2(h0, h1);
            *(uint2*)(&BsLo[r * PADA + aKw]) = make_uint2(l0, l1);
        }
        __syncthreads();

        if (i + 1 < 8) {
            int k0 = (i + 1) << 5;
#pragma unroll
            for (int p = 0; p < 4; p++) {
                int gr = rowBase + aRow + (p << 5);
                pa[p] = make_float4(0.f, 0.f, 0.f, 0.f);
                if (gr < 400) pa[p] = *(const float4*)(Ab + (size_t)gr * 256 + k0 + aK4);
                int t = colBase + aRow + (p << 5);
                pb[p] = make_float4(0.f, 0.f, 0.f, 0.f);
                if (t < PREF)      pb[p] = *(const float4*)(Kc + (size_t)t * 256 + k0 + aK4);
                else if (t < TTOT) pb[p] = *(const float4*)(knew + ((size_t)(b * SEQ + t - PREF)) * 256 + k0 + aK4);
            }
        }

#pragma unroll
        for (int ks = 0; ks < 2; ks++) {
            const int kf = (ks << 3) + (lane & 3);
            uint32_t bh[4][2], bl[4][2];
#pragma unroll
            for (int nf = 0; nf < 4; nf++) {
                int n0 = wn + (nf << 3) + (lane >> 2);
                bh[nf][0] = BsHi[n0 * PADA + kf];
                bh[nf][1] = BsHi[n0 * PADA + kf + 4];
                bl[nf][0] = BsLo[n0 * PADA + kf];
                bl[nf][1] = BsLo[n0 * PADA + kf + 4];
            }
#pragma unroll
            for (int mf = 0; mf < 4; mf++) {
                int m0 = wm + (mf << 4) + (lane >> 2);
                uint32_t ah[4], al[4];
                ah[0] = AsHi[m0 * PADA + kf];
                ah[1] = AsHi[(m0 + 8) * PADA + kf];
                ah[2] = AsHi[m0 * PADA + kf + 4];
                ah[3] = AsHi[(m0 + 8) * PADA + kf + 4];
                al[0] = AsLo[m0 * PADA + kf];
                al[1] = AsLo[(m0 + 8) * PADA + kf];
                al[2] = AsLo[m0 * PADA + kf + 4];
                al[3] = AsLo[(m0 + 8) * PADA + kf + 4];
#pragma unroll
                for (int nf = 0; nf < 4; nf++) {
                    mma_bf16(c[mf][nf], al, bh[nf][0], bh[nf][1]);
                    mma_bf16(c[mf][nf], ah, bl[nf][0], bl[nf][1]);
                    mma_bf16(c[mf][nf], ah, bh[nf][0], bh[nf][1]);
                }
            }
        }
        __syncthreads();
    }

    const float scale = 0.0625f;
#pragma unroll
    for (int mf = 0; mf < 4; mf++) {
        int r0 = rowBase + wm + (mf << 4) + (lane >> 2);
#pragma unroll
        for (int nf = 0; nf < 4; nf++) {
            int t = colBase + wn + (nf << 3) + ((lane & 3) << 1);
            if (t >= TTOT) continue;
            float2 bias;
            bias.x = (t < PREF) ? g_biasPref[b * PREF + t] : 0.f;
            bias.y = (t + 1 < PREF) ? g_biasPref[b * PREF + t + 1] : 0.f;
#pragma unroll
            for (int half = 0; half < 2; half++) {
                int rr = r0 + half * 8;
                if (rr >= 400) continue;
                int h = rr & 7, s = rr >> 3;
                size_t off = ((size_t)(b * 8 + h) * SEQ + s) * TPAD + t;
                float2 v = make_float2(c[mf][nf][half * 2] * scale + bias.x,
                                       c[mf][nf][half * 2 + 1] * scale + bias.y);
                *(float2*)(g_sc + off) = v;
            }
        }
    }
}

// ============ attention PV via split-bf16 MMA ============
// grid (2, 4, 8) = (dTile128, rTile128, b). O = P @ Vt^T (Vt[b][d][t]).
__global__ void __launch_bounds__(256) attn_pv_kernel(
    const float* __restrict__ vt, float* __restrict__ out)
{
    __shared__ uint32_t AsHi[128 * PADA];
    __shared__ uint32_t AsLo[128 * PADA];
    __shared__ uint32_t BsHi[128 * PADA];
    __shared__ uint32_t BsLo[128 * PADA];

    const int tid  = threadIdx.x;
    const int lane = tid & 31;
    const int warp = tid >> 5;
    const int wm = (warp & 1) << 6;
    const int wn = (warp >> 1) << 5;
    const int b = blockIdx.z;
    const int rowBase = blockIdx.y * 128;
    const int colBase = blockIdx.x * 128;

    const float* Ab = g_sc + (size_t)b * 400 * TPAD;
    const float* Bb = vt + (size_t)b * HEADD * TPAD;

    const int aRow = tid >> 3;
    const int aK4  = (tid & 7) << 2;
    const int aKw  = (tid & 7) << 1;

    float c[4][4][4];
#pragma unroll
    for (int i = 0; i < 4; i++)
#pragma unroll
        for (int j = 0; j < 4; j++)
#pragma unroll
            for (int r = 0; r < 4; r++) c[i][j][r] = 0.f;

    float4 pa[4], pb[4];
#pragma unroll
    for (int p = 0; p < 4; p++) {
        int gr = rowBase + aRow + (p << 5);
        pa[p] = make_float4(0.f, 0.f, 0.f, 0.f);
        if (gr < 400) pa[p] = *(const float4*)(Ab + (size_t)gr * TPAD + aK4);
        int d = colBase + aRow + (p << 5);
        pb[p] = *(const float4*)(Bb + (size_t)d * TPAD + aK4);
    }

    const int nChunks = TPAD >> 5;   // 27
#pragma unroll 1
    for (int i = 0; i < nChunks; i++) {
#pragma unroll
        for (int p = 0; p < 4; p++) {
            int r = aRow + (p << 5);
            uint32_t h0, l0, h1, l1;
            split2(pa[p].x, pa[p].y, h0, l0);
            split2(pa[p].z, pa[p].w, h1, l1);
            *(uint2*)(&AsHi[r * PADA + aKw]) = make_uint2(h0, h1);
            *(uint2*)(&AsLo[r * PADA + aKw]) = make_uint2(l0, l1);
            split2(pb[p].x, pb[p].y, h0, l0);
            split2(pb[p].z, pb[p].w, h1, l1);
            *(uint2*)(&BsHi[r * PADA + aKw]) = make_uint2(h0, h1);
            *(uint2*)(&BsLo[r * PADA + aKw]) = make_uint2(l0, l1);
        }
        __syncthreads();

        if (i + 1 < nChunks) {
            int k0 = (i + 1) << 5;
#pragma unroll
            for (int p = 0; p < 4; p++) {
                int gr = rowBase + aRow + (p << 5);
                pa[p] = make_float4(0.f, 0.f, 0.f, 0.f);
                if (gr < 400) pa[p] = *(const float4*)(Ab + (size_t)gr * TPAD + k0 + aK4);
                int d = colBase + aRow + (p << 5);
                pb[p] = *(const float4*)(Bb + (size_t)d * TPAD + k0 + aK4);
            }
        }

#pragma unroll
        for (int ks = 0; ks < 2; ks++) {
            const int kf = (ks << 3) + (lane & 3);
            uint32_t bh[4][2], bl[4][2];
#pragma unroll
            for (int nf = 0; nf < 4; nf++) {
                int n0 = wn + (nf << 3) + (lane >> 2);
                bh[nf][0] = BsHi[n0 * PADA + kf];
                bh[nf][1] = BsHi[n0 * PADA + kf + 4];
                bl[nf][0] = BsLo[n0 * PADA + kf];
                bl[nf][1] = BsLo[n0 * PADA + kf + 4];
            }
#pragma unroll
            for (int mf = 0; mf < 4; mf++) {
                int m0 = wm + (mf << 4) + (lane >> 2);
                uint32_t ah[4], al[4];
                ah[0] = AsHi[m0 * PADA + kf];
                ah[1] = AsHi[(m0 + 8) * PADA + kf];
                ah[2] = AsHi[m0 * PADA + kf + 4];
                ah[3] = AsHi[(m0 + 8) * PADA + kf + 4];
                al[0] = AsLo[m0 * PADA + kf];
                al[1] = AsLo[(m0 + 8) * PADA + kf];
                al[2] = AsLo[m0 * PADA + kf + 4];
                al[3] = AsLo[(m0 + 8) * PADA + kf + 4];
#pragma unroll
                for (int nf = 0; nf < 4; nf++) {
                    mma_bf16(c[mf][nf], al, bh[nf][0], bh[nf][1]);
                    mma_bf16(c[mf][nf], ah, bl[nf][0], bl[nf][1]);
                    mma_bf16(c[mf][nf], ah, bh[nf][0], bh[nf][1]);
                }
            }
        }
        __syncthreads();
    }

#pragma unroll
    for (int mf = 0; mf < 4; mf++) {
        int r0 = rowBase + wm + (mf << 4) + (lane >> 2);
#pragma unroll
        for (int nf = 0; nf < 4; nf++) {
            int d = colBase + wn + (nf << 3) + ((lane & 3) << 1);
#pragma unroll
            for (int half = 0; half < 2; half++) {
                int rr = r0 + half * 8;
                if (rr >= 400) continue;
                int h = rr / SEQ, s = rr % SEQ;
                size_t off = (((size_t)(b * SEQ + s)) * 8 + h) * 256 + d;
                *(float2*)(out + off) = make_float2(c[mf][nf][half * 2],
                                                    c[mf][nf][half * 2 + 1]);
            }
        }
    }
}

// ---------------- V transpose: Vt[b][d][t] = Vfull[b][t][d] ----------------
// grid (27, 8, 8) = (tTile32, dTile32, b), block (32, 8)
__global__ void vtrans_kernel(const float* __restrict__ vnew,
                              const float* __restrict__ kvc, int layer,
                              float* __restrict__ vt)
{
    __shared__ float tile[32][33];
    int b = blockIdx.z;
    int t0 = blockIdx.x * 32;
    int d0 = blockIdx.y * 32;
    int tx = threadIdx.x, ty = threadIdx.y;
    const float* Vc = kvc + ((size_t)(layer * 2 + 1) * BATCH + b) * (size_t)(PREF * HEADD);
#pragma unroll
    for (int j = 0; j < 4; j++) {
        int t = t0 + ty + j * 8;
        float v = 0.f;
        if (t < PREF)      v = Vc[(size_t)t * 256 + d0 + tx];
        else if (t < TTOT) v = vnew[((size_t)(b * SEQ + t - PREF)) * 256 + d0 + tx];
        tile[ty + j * 8][tx] = v;
    }
    __syncthreads();
#pragma unroll
    for (int j = 0; j < 4; j++) {
        int d = d0 + ty + j * 8;
        vt[((size_t)b * HEADD + d) * TPAD + t0 + tx] = tile[tx][ty + j * 8];
    }
}

// ---------------- prep ----------------
__global__ void prep_kernel(const void* __restrict__ maskp,
                            const float* __restrict__ ts)
{
    int bb = blockIdx.x;
    if (bb < BATCH) {
        int b = bb;
        const int* mi = (const int*)maskp;
        const unsigned char* mu = (const unsigned char*)maskp;
        int w0 = mi[0];
        bool is_i32 = (w0 == 0 || w0 == 1);
        __shared__ int cnt;
        if (threadIdx.x == 0) cnt = 0;
        __syncthreads();
        int local = 0;
        for (int t = threadIdx.x; t < PREF; t += blockDim.x) {
            int m = is_i32 ? mi[b * PREF + t] : (int)mu[b * PREF + t];
            bool on = (m != 0);
            g_biasPref[b * PREF + t] = on ? 0.f : -1e9f;
            if (on) local++;
        }
        atomicAdd(&cnt, local);
        __syncthreads();
        if (threadIdx.x == 0) g_plen[b] = cnt;
    } else {
        int b = bb - BATCH;
        float tsb = ts[b];
        for (int i = threadIdx.x; i < 512; i += blockDim.x) {
            float frac = (float)i / 511.f;
            float period = 4e-3f * powf(1000.f, frac);
            float arg = (6.283185307179586f / period) * tsb;
            float sv, cv;
            sincosf(arg, &sv, &cv);
            g_temb[b * HDIM + i]       = sv;
            g_temb[b * HDIM + 512 + i] = cv;
        }
    }
}

// ---------------- SIMT SGEMM (small GEMMs only) ----------------
__global__ void __launch_bounds__(256) sgemm_kernel(
    const float* __restrict__ A, const float* __restrict__ W,
    float* __restrict__ C, const float* __restrict__ bias,
    int M, int N, int K, int lda, int accumulate)
{
    __shared__ float As[16][64];
    __shared__ float Bs[16][64];
    const int tid = threadIdx.x;
    const int tx = tid & 15;
    const int ty = tid >> 4;
    const int rowBase = blockIdx.y * 64;
    const int colBase = blockIdx.x * 64;

    const int lm  = tid >> 2;
    const int lk  = (tid & 3) << 2;
    const int lkr = tid >> 4;
    const int ln  = (tid & 15) << 2;

    float acc[4][4];
#pragma unroll
    for (int i = 0; i < 4; i++)
#pragma unroll
        for (int j = 0; j < 4; j++) acc[i][j] = 0.f;

    for (int k0 = 0; k0 < K; k0 += 16) {
        float4 av = make_float4(0.f, 0.f, 0.f, 0.f);
        int ar = rowBase + lm;
        if (ar < M) av = *(const float4*)(A + (size_t)ar * lda + (k0 + lk));
        As[lk + 0][lm] = av.x;
        As[lk + 1][lm] = av.y;
        As[lk + 2][lm] = av.z;
        As[lk + 3][lm] = av.w;

        float4 bv;
        int bn = colBase + ln;
        const float* wrow = W + (size_t)(k0 + lkr) * N;
        if (bn + 3 < N) {
            bv = *(const float4*)(wrow + bn);
        } else {
            bv.x = (bn + 0 < N) ? wrow[bn + 0] : 0.f;
            bv.y = (bn + 1 < N) ? wrow[bn + 1] : 0.f;
            bv.z = (bn + 2 < N) ? wrow[bn + 2] : 0.f;
            bv.w = (bn + 3 < N) ? wrow[bn + 3] : 0.f;
        }
        *(float4*)(&Bs[lkr][ln]) = bv;
        __syncthreads();

#pragma unroll
        for (int kk = 0; kk < 16; kk++) {
            float4 a = *(const float4*)(&As[kk][ty << 2]);
            float4 b = *(const float4*)(&Bs[kk][tx << 2]);
            acc[0][0] += a.x * b.x; acc[0][1] += a.x * b.y; acc[0][2] += a.x * b.z; acc[0][3] += a.x * b.w;
            acc[1][0] += a.y * b.x; acc[1][1] += a.y * b.y; acc[1][2] += a.y * b.z; acc[1][3] += a.y * b.w;
            acc[2][0] += a.z * b.x; acc[2][1] += a.z * b.y; acc[2][2] += a.z * b.z; acc[2][3] += a.z * b.w;
            acc[3][0] += a.w * b.x; acc[3][1] += a.w * b.y; acc[3][2] += a.w * b.z; acc[3][3] += a.w * b.w;
        }
        __syncthreads();
    }

#pragma unroll
    for (int i = 0; i < 4; i++) {
        int r = rowBase + (ty << 2) + i;
        if (r >= M) continue;
#pragma unroll
        for (int j = 0; j < 4; j++) {
            int cx = colBase + (tx << 2) + j;
            if (cx >= N) continue;
            float v = acc[i][j];
            if (bias) v += bias[cx];
            size_t off = (size_t)r * N + cx;
            if (accumulate) v += C[off];
            C[off] = v;
        }
    }
}

// ---------------- small-M (M<=8) GEMM core ----------------
__device__ __forceinline__ void gemv8_core(
    const float* __restrict__ A, const float* __restrict__ W,
    const float* __restrict__ bias, float* __restrict__ C,
    int N, int K, int act, int bx)
{
    __shared__ float a_s[8 * 1024];
    __shared__ float red[4 * 64 * 8];
    int tid = threadIdx.x;
    for (int e = tid; e < 8 * K; e += 256) a_s[e] = A[e];
    __syncthreads();

    int nl = tid & 63;
    int n  = bx * 64 + nl;
    int ks = tid >> 6;
    float acc[8];
#pragma unroll
    for (int m = 0; m < 8; m++) acc[m] = 0.f;

    int kc = K >> 2;
    if (n < N) {
        int kbeg = ks * kc;
#pragma unroll 4
        for (int k = 0; k < kc; k++) {
            float w = W[(size_t)(kbeg + k) * N + n];
#pragma unroll
            for (int m = 0; m < 8; m++) acc[m] += a_s[m * K + kbeg + k] * w;
        }
    }
#pragma unroll
    for (int m = 0; m < 8; m++) red[tid * 8 + m] = acc[m];
    __syncthreads();
    if (ks == 0 && n < N) {
#pragma unroll
        for (int m = 0; m < 8; m++) {
            float v = red[(0 * 64 + nl) * 8 + m] + red[(1 * 64 + nl) * 8 + m] +
                      red[(2 * 64 + nl) * 8 + m] + red[(3 * 64 + nl) * 8 + m];
            if (bias) v += bias[n];
            if (act == 1) v = v / (1.f + expf(-v));
            C[(size_t)m * N + n] = v;
        }
    }
}

__global__ void __launch_bounds__(256) gemv8_kernel(
    const float* __restrict__ A, const float* __restrict__ W,
    const float* __restrict__ bias, float* __restrict__ C,
    int N, int K, int act)
{
    gemv8_core(A, W, bias, C, N, K, act, blockIdx.x);
}

__global__ void __launch_bounds__(256) adaall_kernel(
    const float* __restrict__ tvec,
    const float* __restrict__ Wada1, const float* __restrict__ Wada2,
    float* __restrict__ out)
{
    int li = blockIdx.y;
    const float* W = (li < NLAYER) ? (Wada1 + (size_t)li * HDIM * HDIM)
                                   : (Wada2 + (size_t)(li - NLAYER) * HDIM * HDIM);
    gemv8_core(tvec, W, nullptr, out + (size_t)li * BATCH * HDIM,
               HDIM, HDIM, 0, blockIdx.x);
}

// ---------------- rmsnorm ----------------
__global__ void __launch_bounds__(256) rmsnorm_kernel(
    const float* __restrict__ x, const float* __restrict__ w,
    const float* __restrict__ ada, float* __restrict__ out)
{
    int row = blockIdx.x;
    int b = row / SEQ;
    const float* xr = x + (size_t)row * HDIM;
    __shared__ float red[256];
    float s = 0.f;
    for (int i = threadIdx.x; i < HDIM; i += 256) {
        float v = xr[i];
        s += v * v;
    }
    red[threadIdx.x] = s;
    __syncthreads();
    for (int st = 128; st > 0; st >>= 1) {
        if (threadIdx.x < st) red[threadIdx.x] += red[threadIdx.x + st];
        __syncthreads();
    }
    float r = rsqrtf(red[0] * (1.f / HDIM) + 1e-6f);
    for (int i = threadIdx.x; i < HDIM; i += 256) {
        float gmul = w[i];
        if (ada) gmul *= (1.f + ada[b * HDIM + i]);
        out[(size_t)row * HDIM + i] = xr[i] * r * gmul;
    }
}

// ---------------- rope ----------------
__global__ void rope_kernel(float* __restrict__ q, float* __restrict__ k)
{
    int idx = blockIdx.x * blockDim.x + threadIdx.x;
    const int total = MTOK * 9 * 128;
    if (idx >= total) return;
    int j = idx & 127;
    int rest = idx >> 7;
    int hh = rest % 9;
    int row = rest / 9;
    int b = row / SEQ, s = row % SEQ;
    float pos = (float)(g_plen[b] + s);
    float inv = powf(10000.f, -(float)j / 128.f);
    float fr = pos * inv;
    float sn, cs;
    sincosf(fr, &sn, &cs);
    float* p = (hh < 8) ? (q + ((size_t)row * 8 + hh) * 256) : (k + (size_t)row * 256);
    float x1 = p[j], x2 = p[j + 128];
    p[j]       = x1 * cs - x2 * sn;
    p[j + 128] = x2 * cs + x1 * sn;
}

// ---------------- softmax (zero-pads [TTOT, TPAD)) ----------------
__global__ void __launch_bounds__(256) softmax_kernel()
{
    int row = blockIdx.x;
    float* p = g_sc + (size_t)row * TPAD;
    __shared__ float red[256];
    float mx = -1e30f;
    for (int i = threadIdx.x; i < TTOT; i += 256) mx = fmaxf(mx, p[i]);
    red[threadIdx.x] = mx;
    __syncthreads();
    for (int st = 128; st > 0; st >>= 1) {
        if (threadIdx.x < st) red[threadIdx.x] = fmaxf(red[threadIdx.x], red[threadIdx.x + st]);
        __syncthreads();
    }
    float m = red[0];
    __syncthreads();
    float s = 0.f;
    for (int i = threadIdx.x; i < TTOT; i += 256) {
        float e = expf(p[i] - m);
        p[i] = e;
        s += e;
    }
    red[threadIdx.x] = s;
    __syncthreads();
    for (int st = 128; st > 0; st >>= 1) {
        if (threadIdx.x < st) red[threadIdx.x] += red[threadIdx.x + st];
        __syncthreads();
    }
    float inv = 1.f / red[0];
    for (int i = threadIdx.x; i < TTOT; i += 256) p[i] *= inv;
    if (threadIdx.x < TPAD - TTOT) p[TTOT + threadIdx.x] = 0.f;
}

// ---------------- host ----------------
static inline dim3 gemm_grid(int M, int N) { return dim3((N + 63) / 64, (M + 63) / 64); }
static inline dim3 tc_grid(int M, int N) { return dim3(N / 128, (M + 127) / 128); }

extern "C" void kernel_launch(void* const* d_in, const int* in_sizes, int n_in,
                              void* d_out, int out_size)
{
    const float* x_t      = (const float*)d_in[0];
    const float* timestep = (const float*)d_in[1];
    const void*  mask     = d_in[2];
    const float* kvc      = (const float*)d_in[3];
    const float* Wa_in    = (const float*)d_in[4];
    const float* ba_in    = (const float*)d_in[5];
    const float* Wt_in    = (const float*)d_in[6];
    const float* bt_in    = (const float*)d_in[7];
    const float* Wt_out   = (const float*)d_in[8];
    const float* bt_out   = (const float*)d_in[9];
    const float* Wq       = (const float*)d_in[10];
    const float* Wk       = (const float*)d_in[11];
    const float* Wv       = (const float*)d_in[12];
    const float* Wo       = (const float*)d_in[13];
    const float* Wg       = (const float*)d_in[14];
    const float* Wu       = (const float*)d_in[15];
    const float* Wd       = (const float*)d_in[16];
    const float* n1_w     = (const float*)d_in[17];
    const float* n2_w     = (const float*)d_in[18];
    const float* Wada1    = (const float*)d_in[19];
    const float* Wada2    = (const float*)d_in[20];
    const float* nf_w     = (const float*)d_in[21];
    const float* Wa_out   = (const float*)d_in[22];
    const float* ba_out   = (const float*)d_in[23];

    void* p;
    cudaGetSymbolAddress(&p, g_x);      float* px    = (float*)p;
    cudaGetSymbolAddress(&p, g_h);      float* ph    = (float*)p;
    cudaGetSymbolAddress(&p, g_temb);   float* ptemb = (float*)p;
    cudaGetSymbolAddress(&p, g_t1);     float* pt1   = (float*)p;
    cudaGetSymbolAddress(&p, g_tv);     float* ptv   = (float*)p;
    cudaGetSymbolAddress(&p, g_adaAll); float* padaA = (float*)p;
    cudaGetSymbolAddress(&p, g_q);      float* pq    = (float*)p;
    cudaGetSymbolAddress(&p, g_k);      float* pk    = (float*)p;
    cudaGetSymbolAddress(&p, g_v);      float* pv    = (float*)p;
    cudaGetSymbolAddress(&p, g_vt);     float* pvt   = (float*)p;
    cudaGetSymbolAddress(&p, g_ao);     float* pao   = (float*)p;
    cudaGetSymbolAddress(&p, g_gg);     float* pg    = (float*)p;
    cudaGetSymbolAddress(&p, g_uu);     float* pu    = (float*)p;

    prep_kernel<<<16, 512>>>(mask, timestep);

    gemv8_kernel<<<16, 256>>>(ptemb, Wt_in, bt_in, pt1, HDIM, HDIM, 1);
    gemv8_kernel<<<16, 256>>>(pt1, Wt_out, bt_out, ptv, HDIM, HDIM, 1);
    adaall_kernel<<<dim3(16, 2 * NLAYER), 256>>>(ptv, Wada1, Wada2, padaA);

    sgemm_kernel<<<gemm_grid(MTOK, HDIM), 256>>>(x_t, Wa_in, px, ba_in,
                                                 MTOK, HDIM, ADIM, ADIM, 0);

    for (int l = 0; l < NLAYER; l++) {
        const float* wq = Wq + (size_t)l * HDIM * (NHEAD * HEADD);
        const float* wk = Wk + (size_t)l * HDIM * HEADD;
        const float* wv = Wv + (size_t)l * HDIM * HEADD;
        const float* wo = Wo + (size_t)l * (NHEAD * HEADD) * HDIM;
        const float* wg = Wg + (size_t)l * HDIM * MLPD;
        const float* wu = Wu + (size_t)l * HDIM * MLPD;
        const float* wd = Wd + (size_t)l * MLPD * HDIM;
        const float* w1 = n1_w + (size_t)l * HDIM;
        const float* w2 = n2_w + (size_t)l * HDIM;
        const float* ada1 = padaA + (size_t)l * BATCH * HDIM;
        const float* ada2 = padaA + (size_t)(NLAYER + l) * BATCH * HDIM;

        rmsnorm_kernel<<<MTOK, 256>>>(px, w1, ada1, ph);

        qkv_kernel<<<dim3(20, 4), 256>>>(ph, wq, wk, wv, pq, pk, pv);
        vtrans_kernel<<<dim3(27, 8, 8), dim3(32, 8)>>>(pv, kvc, l, pvt);
        rope_kernel<<<(MTOK * 9 * 128 + 255) / 256, 256>>>(pq, pk);

        attn_scores_kernel<<<dim3(7, 4, 8), 256>>>(pq, pk, kvc, l);
        softmax_kernel<<<BATCH * NHEAD * SEQ, 256>>>();
        attn_pv_kernel<<<dim3(2, 4, 8), 256>>>(pvt, pao);

        mma_gemm_kernel<<<tc_grid(MTOK, HDIM), 256>>>(
            pao, wo, px, nullptr, MTOK, HDIM, NHEAD * HEADD, 1);

        rmsnorm_kernel<<<MTOK, 256>>>(px, w2, ada2, ph);

        mma_gemm_kernel<<<tc_grid(MTOK, MLPD), 256>>>(
            ph, wg, pg, nullptr, MTOK, MLPD, HDIM, 0);
        mma_gemm_kernel<<<tc_grid(MTOK, MLPD), 256>>>(
            ph, wu, pu, pg, MTOK, MLPD, HDIM, 2);
        mma_gemm_kernel<<<tc_grid(MTOK, HDIM), 256>>>(
            pu, wd, px, nullptr, MTOK, HDIM, MLPD, 1);
    }

    rmsnorm_kernel<<<MTOK, 256>>>(px, nf_w, nullptr, ph);
    sgemm_kernel<<<gemm_grid(MTOK, ADIM), 256>>>(ph, Wa_out, (float*)d_out, ba_out,
                                                 MTOK, ADIM, HDIM, HDIM, 0);
}

// round 7
// speedup vs baseline: 3.3326x; 1.2949x over previous
#include <cuda_runtime.h>
#include <math.h>
#include <stdint.h>

// ---------------- problem dims ----------------
#define NLAYER 18
#define HDIM   1024
#define NHEAD  8
#define HEADD  256
#define MLPD   4096
#define BATCH  8
#define SEQ    50
#define PREF   800
#define ADIM   32
#define TTOT   850
#define TPAD   864
#define MTOK   400

// ---------------- device scratch ----------------
__device__ float g_x[MTOK * HDIM];
__device__ float g_h[MTOK * HDIM];
__device__ float g_temb[BATCH * HDIM];
__device__ float g_t1[BATCH * HDIM];
__device__ float g_tv[BATCH * HDIM];
__device__ float g_adaAll[2 * NLAYER * BATCH * HDIM];
__device__ float g_q[MTOK * NHEAD * HEADD];
__device__ float g_k[MTOK * HEADD];
__device__ float g_v[MTOK * HEADD];
__device__ float g_sc[BATCH * NHEAD * SEQ * TPAD];
__device__ float g_vt[BATCH * HEADD * TPAD];
__device__ float g_ao[MTOK * NHEAD * HEADD];
__device__ float g_gg[MTOK * MLPD];
__device__ float g_uu[MTOK * MLPD];
__device__ int   g_plen[BATCH];
__device__ float g_biasPref[BATCH * PREF];

// ---------------- bf16 split helpers ----------------
__device__ __forceinline__ void split2(float lo, float hi, uint32_t& hw, uint32_t& lw) {
    asm("cvt.rn.bf16x2.f32 %0, %1, %2;" : "=r"(hw) : "f"(hi), "f"(lo));
    float hlo = __uint_as_float(hw << 16);
    float hhi = __uint_as_float(hw & 0xffff0000u);
    asm("cvt.rn.bf16x2.f32 %0, %1, %2;" : "=r"(lw) : "f"(hi - hhi), "f"(lo - hlo));
}
__device__ __forceinline__ void mma_bf16(
    float c[4], const uint32_t a[4], uint32_t b0, uint32_t b1)
{
    asm volatile(
        "mma.sync.aligned.m16n8k16.row.col.f32.bf16.bf16.f32 "
        "{%0,%1,%2,%3}, {%4,%5,%6,%7}, {%8,%9}, {%0,%1,%2,%3};"
        : "+f"(c[0]), "+f"(c[1]), "+f"(c[2]), "+f"(c[3])
        : "r"(a[0]), "r"(a[1]), "r"(a[2]), "r"(a[3]), "r"(b0), "r"(b1));
}
__device__ __forceinline__ float gelu_f(float x) {
    float t = tanhf(0.7978845608028654f * (x + 0.044715f * x * x * x));
    return 0.5f * x * (1.f + t);
}

// ============ split-bf16 (3-term) mma GEMM core, M-tile 64 ============
// Tile 64x128x32. 256 threads, 8 warps (2m x 4n), warp tile 32x32.
#define PADA 20
#define PADB 136
__device__ __forceinline__ void gemm_core(
    const float* __restrict__ A, const float* __restrict__ W,
    float* __restrict__ C, const float* __restrict__ Cg,
    int M, int Nw, int K, int rowBase, int colBase, int epiMode,
    uint32_t* AsHi, uint32_t* AsLo, uint32_t* BsHi, uint32_t* BsLo)
{
    const int tid  = threadIdx.x;
    const int lane = tid & 31;
    const int warp = tid >> 5;
    const int wm = (warp & 1) << 5;        // 0 or 32
    const int wn = (warp >> 1) << 5;       // 0,32,64,96

    const int aRow = tid >> 3;             // 0..31
    const int aK4  = (tid & 7) << 2;
    const int aKw  = (tid & 7) << 1;
    const int bKw  = tid >> 4;             // 0..15
    const int bN   = (tid & 15) << 3;      // 0..120

    float c[2][4][4];
#pragma unroll
    for (int i = 0; i < 2; i++)
#pragma unroll
        for (int j = 0; j < 4; j++)
#pragma unroll
            for (int r = 0; r < 4; r++) c[i][j][r] = 0.f;

    float4 pa[2], pb[4];
    {
#pragma unroll
        for (int p = 0; p < 2; p++) {
            int gr = rowBase + aRow + (p << 5);
            pa[p] = make_float4(0.f, 0.f, 0.f, 0.f);
            if (gr < M) pa[p] = *(const float4*)(A + (size_t)gr * K + aK4);
        }
        const float* br0 = W + (size_t)(2 * bKw) * Nw + colBase + bN;
        pb[0] = *(const float4*)(br0);
        pb[1] = *(const float4*)(br0 + 4);
        pb[2] = *(const float4*)(br0 + Nw);
        pb[3] = *(const float4*)(br0 + Nw + 4);
    }

    const int nChunks = K >> 5;
    for (int i = 0; i < nChunks; i++) {
#pragma unroll
        for (int p = 0; p < 2; p++) {
            int r = aRow + (p << 5);
            uint32_t h0, l0, h1, l1;
            split2(pa[p].x, pa[p].y, h0, l0);
            split2(pa[p].z, pa[p].w, h1, l1);
            *(uint2*)(&AsHi[r * PADA + aKw]) = make_uint2(h0, h1);
            *(uint2*)(&AsLo[r * PADA + aKw]) = make_uint2(l0, l1);
        }
        {
            uint32_t hw[8], lw[8];
            const float* p0 = (const float*)&pb[0];
            const float* p1 = (const float*)&pb[2];
#pragma unroll
            for (int j = 0; j < 8; j++) split2(p0[j], p1[j], hw[j], lw[j]);
            *(uint4*)(&BsHi[bKw * PADB + bN])     = make_uint4(hw[0], hw[1], hw[2], hw[3]);
            *(uint4*)(&BsHi[bKw * PADB + bN + 4]) = make_uint4(hw[4], hw[5], hw[6], hw[7]);
            *(uint4*)(&BsLo[bKw * PADB + bN])     = make_uint4(lw[0], lw[1], lw[2], lw[3]);
            *(uint4*)(&BsLo[bKw * PADB + bN + 4]) = make_uint4(lw[4], lw[5], lw[6], lw[7]);
        }
        __syncthreads();

        if (i + 1 < nChunks) {
            int k0 = (i + 1) << 5;
#pragma unroll
            for (int p = 0; p < 2; p++) {
                int gr = rowBase + aRow + (p << 5);
                pa[p] = make_float4(0.f, 0.f, 0.f, 0.f);
                if (gr < M) pa[p] = *(const float4*)(A + (size_t)gr * K + k0 + aK4);
            }
            const float* br0 = W + (size_t)(k0 + 2 * bKw) * Nw + colBase + bN;
            pb[0] = *(const float4*)(br0);
            pb[1] = *(const float4*)(br0 + 4);
            pb[2] = *(const float4*)(br0 + Nw);
            pb[3] = *(const float4*)(br0 + Nw + 4);
        }

#pragma unroll
        for (int ks = 0; ks < 2; ks++) {
            const int kf = (ks << 3) + (lane & 3);
            uint32_t bh[4][2], bl[4][2];
#pragma unroll
            for (int nf = 0; nf < 4; nf++) {
                int n0 = wn + (nf << 3) + (lane >> 2);
                bh[nf][0] = BsHi[kf * PADB + n0];
                bh[nf][1] = BsHi[(kf + 4) * PADB + n0];
                bl[nf][0] = BsLo[kf * PADB + n0];
                bl[nf][1] = BsLo[(kf + 4) * PADB + n0];
            }
#pragma unroll
            for (int mf = 0; mf < 2; mf++) {
                int m0 = wm + (mf << 4) + (lane >> 2);
                uint32_t ah[4], al[4];
                ah[0] = AsHi[m0 * PADA + kf];
                ah[1] = AsHi[(m0 + 8) * PADA + kf];
                ah[2] = AsHi[m0 * PADA + kf + 4];
                ah[3] = AsHi[(m0 + 8) * PADA + kf + 4];
                al[0] = AsLo[m0 * PADA + kf];
                al[1] = AsLo[(m0 + 8) * PADA + kf];
                al[2] = AsLo[m0 * PADA + kf + 4];
                al[3] = AsLo[(m0 + 8) * PADA + kf + 4];
#pragma unroll
                for (int nf = 0; nf < 4; nf++) {
                    mma_bf16(c[mf][nf], al, bh[nf][0], bh[nf][1]);
                    mma_bf16(c[mf][nf], ah, bl[nf][0], bl[nf][1]);
                    mma_bf16(c[mf][nf], ah, bh[nf][0], bh[nf][1]);
                }
            }
        }
        __syncthreads();
    }

#pragma unroll
    for (int mf = 0; mf < 2; mf++) {
        int r0 = rowBase + wm + (mf << 4) + (lane >> 2);
#pragma unroll
        for (int nf = 0; nf < 4; nf++) {
            int cc = colBase + wn + (nf << 3) + ((lane & 3) << 1);
#pragma unroll
            for (int half = 0; half < 2; half++) {
                int rr = r0 + half * 8;
                if (rr >= M) continue;
                size_t off = (size_t)rr * Nw + cc;
                float2 v = make_float2(c[mf][nf][half * 2], c[mf][nf][half * 2 + 1]);
                if (epiMode == 1) {
                    float2 old = *(float2*)(C + off);
                    v.x += old.x; v.y += old.y;
                } else if (epiMode == 2) {
                    float2 gg = *(const float2*)(Cg + off);
                    v.x *= gelu_f(gg.x); v.y *= gelu_f(gg.y);
                }
                *(float2*)(C + off) = v;
            }
        }
    }
}

#define GEMM_SHARED \
    __shared__ uint32_t AsHi[64 * PADA]; \
    __shared__ uint32_t AsLo[64 * PADA]; \
    __shared__ uint32_t BsHi[16 * PADB]; \
    __shared__ uint32_t BsLo[16 * PADB];

__global__ void __launch_bounds__(256, 2) mma_gemm_kernel(
    const float* __restrict__ A, const float* __restrict__ W,
    float* __restrict__ C, const float* __restrict__ Cg,
    int M, int N, int K, int epiMode)
{
    GEMM_SHARED
    gemm_core(A, W, C, Cg, M, N, K, blockIdx.y * 64, blockIdx.x * 128, epiMode,
              AsHi, AsLo, BsHi, BsLo);
}

// fused QKV: grid.x = 20 (16 Q + 2 K + 2 V), grid.y = 7
__global__ void __launch_bounds__(256, 2) qkv_kernel(
    const float* __restrict__ A,
    const float* __restrict__ Wq, const float* __restrict__ Wk, const float* __restrict__ Wv,
    float* __restrict__ oq, float* __restrict__ ok, float* __restrict__ ov)
{
    GEMM_SHARED
    int bx = blockIdx.x;
    const float* W; float* C; int Nw, colBase;
    if (bx < 16)      { W = Wq; C = oq; Nw = 2048; colBase = bx * 128; }
    else if (bx < 18) { W = Wk; C = ok; Nw = 256;  colBase = (bx - 16) * 128; }
    else              { W = Wv; C = ov; Nw = 256;  colBase = (bx - 18) * 128; }
    gemm_core(A, W, C, nullptr, MTOK, Nw, HDIM, blockIdx.y * 64, colBase, 0,
              AsHi, AsLo, BsHi, BsLo);
}

// ============ attention scores via split-bf16 MMA, M-tile 64 ============
// grid (7, 7, 8) = (tTile128, rTile64, b). S = Q @ K^T * 1/16 + bias.
__global__ void __launch_bounds__(256, 2) attn_scores_kernel(
    const float* __restrict__ q, const float* __restrict__ knew,
    const float* __restrict__ kvc, int layer)
{
    __shared__ uint32_t AsHi[64 * PADA];
    __shared__ uint32_t AsLo[64 * PADA];
    __shared__ uint32_t BsHi[128 * PADA];
    __shared__ uint32_t BsLo[128 * PADA];

    const int tid  = threadIdx.x;
    const int lane = tid & 31;
    const int warp = tid >> 5;
    const int wm = (warp & 1) << 5;
    const int wn = (warp >> 1) << 5;
    const int b = blockIdx.z;
    const int rowBase = blockIdx.y * 64;
    const int colBase = blockIdx.x * 128;

    const float* Kc = kvc + ((size_t)(layer * 2) * BATCH + b) * (size_t)(PREF * HEADD);
    const float* Ab = q + (size_t)b * 400 * 256;

    const int aRow = tid >> 3;
    const int aK4  = (tid & 7) << 2;
    const int aKw  = (tid & 7) << 1;

    float c[2][4][4];
#pragma unroll
    for (int i = 0; i < 2; i++)
#pragma unroll
        for (int j = 0; j < 4; j++)
#pragma unroll
            for (int r = 0; r < 4; r++) c[i][j][r] = 0.f;

    float4 pa[2], pb[4];
#pragma unroll
    for (int p = 0; p < 2; p++) {
        int gr = rowBase + aRow + (p << 5);
        pa[p] = make_float4(0.f, 0.f, 0.f, 0.f);
        if (gr < 400) pa[p] = *(const float4*)(Ab + (size_t)gr * 256 + aK4);
    }
#pragma unroll
    for (int p = 0; p < 4; p++) {
        int t = colBase + aRow + (p << 5);
        pb[p] = make_float4(0.f, 0.f, 0.f, 0.f);
        if (t < PREF)      pb[p] = *(const float4*)(Kc + (size_t)t * 256 + aK4);
        else if (t < TTOT) pb[p] = *(const float4*)(knew + ((size_t)(b * SEQ + t - PREF)) * 256 + aK4);
    }

#pragma unroll 1
    for (int i = 0; i < 8; i++) {
#pragma unroll
        for (int p = 0; p < 2; p++) {
            int r = aRow + (p << 5);
            uint32_t h0, l0, h1, l1;
            split2(pa[p].x, pa[p].y, h0, l0);
            split2(pa[p].z, pa[p].w, h1, l1);
            *(uint2*)(&AsHi[r * PADA + aKw]) = make_uint2(h0, h1);
            *(uint2*)(&AsLo[r * PADA + aKw]) = make_uint2(l0, l1);
        }
#pragma unroll
        for (int p = 0; p < 4; p++) {
            int r = aRow + (p << 5);
            uint32_t h0, l0, h1, l1;
            split2(pb[p].x, pb[p].y, h0, l0);
            split2(pb[p].z, pb[p].w, h1, l1);
            *(uint2*)(&BsHi[r * PADA + aKw]) = make_uint2(h0, h1);
            *(uint2*)(&BsLo[r * PADA + aKw]) = make_uint2(l0, l1);
        }
        __syncthreads();

        if (i + 1 < 8) {
            int k0 = (i + 1) << 5;
#pragma unroll
            for (int p = 0; p < 2; p++) {
                int gr = rowBase + aRow + (p << 5);
                pa[p] = make_float4(0.f, 0.f, 0.f, 0.f);
                if (gr < 400) pa[p] = *(const float4*)(Ab + (size_t)gr * 256 + k0 + aK4);
            }
#pragma unroll
            for (int p = 0; p < 4; p++) {
                int t = colBase + aRow + (p << 5);
                pb[p] = make_float4(0.f, 0.f, 0.f, 0.f);
                if (t < PREF)      pb[p] = *(const float4*)(Kc + (size_t)t * 256 + k0 + aK4);
                else if (t < TTOT) pb[p] = *(const float4*)(knew + ((size_t)(b * SEQ + t - PREF)) * 256 + k0 + aK4);
            }
        }

#pragma unroll
        for (int ks = 0; ks < 2; ks++) {
            const int kf = (ks << 3) + (lane & 3);
            uint32_t bh[4][2], bl[4][2];
#pragma unroll
            for (int nf = 0; nf < 4; nf++) {
                int n0 = wn + (nf << 3) + (lane >> 2);
                bh[nf][0] = BsHi[n0 * PADA + kf];
                bh[nf][1] = BsHi[n0 * PADA + kf + 4];
                bl[nf][0] = BsLo[n0 * PADA + kf];
                bl[nf][1] = BsLo[n0 * PADA + kf + 4];
            }
#pragma unroll
            for (int mf = 0; mf < 2; mf++) {
                int m0 = wm + (mf << 4) + (lane >> 2);
                uint32_t ah[4], al[4];
                ah[0] = AsHi[m0 * PADA + kf];
                ah[1] = AsHi[(m0 + 8) * PADA + kf];
                ah[2] = AsHi[m0 * PADA + kf + 4];
                ah[3] = AsHi[(m0 + 8) * PADA + kf + 4];
                al[0] = AsLo[m0 * PADA + kf];
                al[1] = AsLo[(m0 + 8) * PADA + kf];
                al[2] = AsLo[m0 * PADA + kf + 4];
                al[3] = AsLo[(m0 + 8) * PADA + kf + 4];
#pragma unroll
                for (int nf = 0; nf < 4; nf++) {
                    mma_bf16(c[mf][nf], al, bh[nf][0], bh[nf][1]);
                    mma_bf16(c[mf][nf], ah, bl[nf][0], bl[nf][1]);
                    mma_bf16(c[mf][nf], ah, bh[nf][0], bh[nf][1]);
                }
            }
        }
        __syncthreads();
    }

    const float scale = 0.0625f;
#pragma unroll
    for (int mf = 0; mf < 2; mf++) {
        int r0 = rowBase + wm + (mf << 4) + (lane >> 2);
#pragma unroll
        for (int nf = 0; nf < 4; nf++) {
            int t = colBase + wn + (nf << 3) + ((lane & 3) << 1);
            if (t >= TTOT) continue;
            float2 bias;
            bias.x = (t < PREF) ? g_biasPref[b * PREF + t] : 0.f;
            bias.y = (t + 1 < PREF) ? g_biasPref[b * PREF + t + 1] : 0.f;
#pragma unroll
            for (int half = 0; half < 2; half++) {
                int rr = r0 + half * 8;
                if (rr >= 400) continue;
                int h = rr & 7, s = rr >> 3;
                size_t off = ((size_t)(b * 8 + h) * SEQ + s) * TPAD + t;
                float2 v = make_float2(c[mf][nf][half * 2] * scale + bias.x,
                                       c[mf][nf][half * 2 + 1] * scale + bias.y);
                *(float2*)(g_sc + off) = v;
            }
        }
    }
}

// ============ attention PV via split-bf16 MMA, M-tile 64 ============
// grid (2, 7, 8) = (dTile128, rTile64, b). O = P @ Vt^T (Vt[b][d][t]).
__global__ void __launch_bounds__(256, 2) attn_pv_kernel(
    const float* __restrict__ vt, float* __restrict__ out)
{
    __shared__ uint32_t AsHi[64 * PADA];
    __shared__ uint32_t AsLo[64 * PADA];
    __shared__ uint32_t BsHi[128 * PADA];
    __shared__ uint32_t BsLo[128 * PADA];

    const int tid  = threadIdx.x;
    const int lane = tid & 31;
    const int warp = tid >> 5;
    const int wm = (warp & 1) << 5;
    const int wn = (warp >> 1) << 5;
    const int b = blockIdx.z;
    const int rowBase = blockIdx.y * 64;
    const int colBase = blockIdx.x * 128;

    const float* Ab = g_sc + (size_t)b * 400 * TPAD;
    const float* Bb = vt + (size_t)b * HEADD * TPAD;

    const int aRow = tid >> 3;
    const int aK4  = (tid & 7) << 2;
    const int aKw  = (tid & 7) << 1;

    float c[2][4][4];
#pragma unroll
    for (int i = 0; i < 2; i++)
#pragma unroll
        for (int j = 0; j < 4; j++)
#pragma unroll
            for (int r = 0; r < 4; r++) c[i][j][r] = 0.f;

    float4 pa[2], pb[4];
#pragma unroll
    for (int p = 0; p < 2; p++) {
        int gr = rowBase + aRow + (p << 5);
        pa[p] = make_float4(0.f, 0.f, 0.f, 0.f);
        if (gr < 400) pa[p] = *(const float4*)(Ab + (size_t)gr * TPAD + aK4);
    }
#pragma unroll
    for (int p = 0; p < 4; p++) {
        int d = colBase + aRow + (p << 5);
        pb[p] = *(const float4*)(Bb + (size_t)d * TPAD + aK4);
    }

    const int nChunks = TPAD >> 5;   // 27
#pragma unroll 1
    for (int i = 0; i < nChunks; i++) {
#pragma unroll
        for (int p = 0; p < 2; p++) {
            int r = aRow + (p << 5);
            uint32_t h0, l0, h1, l1;
            split2(pa[p].x, pa[p].y, h0, l0);
            split2(pa[p].z, pa[p].w, h1, l1);
            *(uint2*)(&AsHi[r * PADA + aKw]) = make_uint2(h0, h1);
            *(uint2*)(&AsLo[r * PADA + aKw]) = make_uint2(l0, l1);
        }
#pragma unroll
        for (int p = 0; p < 4; p++) {
            int r = aRow + (p << 5);
            uint32_t h0, l0, h1, l1;
            split2(pb[p].x, pb[p].y, h0, l0);
            split2(pb[p].z, pb[p].w, h1, l1);
            *(uint2*)(&BsHi[r * PADA + aKw]) = make_uint2(h0, h1);
            *(uint2*)(&BsLo[r * PADA + aKw]) = make_uint2(l0, l1);
        }
        __syncthreads();

        if (i + 1 < nChunks) {
            int k0 = (i + 1) << 5;
#pragma unroll
            for (int p = 0; p < 2; p++) {
                int gr = rowBase + aRow + (p << 5);
                pa[p] = make_float4(0.f, 0.f, 0.f, 0.f);
                if (gr < 400) pa[p] = *(const float4*)(Ab + (size_t)gr * TPAD + k0 + aK4);
            }
#pragma unroll
            for (int p = 0; p < 4; p++) {
                int d = colBase + aRow + (p << 5);
                pb[p] = *(const float4*)(Bb + (size_t)d * TPAD + k0 + aK4);
            }
        }

#pragma unroll
        for (int ks = 0; ks < 2; ks++) {
            const int kf = (ks << 3) + (lane & 3);
            uint32_t bh[4][2], bl[4][2];
#pragma unroll
            for (int nf = 0; nf < 4; nf++) {
                int n0 = wn + (nf << 3) + (lane >> 2);
                bh[nf][0] = BsHi[n0 * PADA + kf];
                bh[nf][1] = BsHi[n0 * PADA + kf + 4];
                bl[nf][0] = BsLo[n0 * PADA + kf];
                bl[nf][1] = BsLo[n0 * PADA + kf + 4];
            }
#pragma unroll
            for (int mf = 0; mf < 2; mf++) {
                int m0 = wm + (mf << 4) + (lane >> 2);
                uint32_t ah[4], al[4];
                ah[0] = AsHi[m0 * PADA + kf];
                ah[1] = AsHi[(m0 + 8) * PADA + kf];
                ah[2] = AsHi[m0 * PADA + kf + 4];
                ah[3] = AsHi[(m0 + 8) * PADA + kf + 4];
                al[0] = AsLo[m0 * PADA + kf];
                al[1] = AsLo[(m0 + 8) * PADA + kf];
                al[2] = AsLo[m0 * PADA + kf + 4];
                al[3] = AsLo[(m0 + 8) * PADA + kf + 4];
#pragma unroll
                for (int nf = 0; nf < 4; nf++) {
                    mma_bf16(c[mf][nf], al, bh[nf][0], bh[nf][1]);
                    mma_bf16(c[mf][nf], ah, bl[nf][0], bl[nf][1]);
                    mma_bf16(c[mf][nf], ah, bh[nf][0], bh[nf][1]);
                }
            }
        }
        __syncthreads();
    }

#pragma unroll
    for (int mf = 0; mf < 2; mf++) {
        int r0 = rowBase + wm + (mf << 4) + (lane >> 2);
#pragma unroll
        for (int nf = 0; nf < 4; nf++) {
            int d = colBase + wn + (nf << 3) + ((lane & 3) << 1);
#pragma unroll
            for (int half = 0; half < 2; half++) {
                int rr = r0 + half * 8;
                if (rr >= 400) continue;
                int h = rr / SEQ, s = rr % SEQ;
                size_t off = (((size_t)(b * SEQ + s)) * 8 + h) * 256 + d;
                *(float2*)(out + off) = make_float2(c[mf][nf][half * 2],
                                                    c[mf][nf][half * 2 + 1]);
            }
        }
    }
}

// ---------------- V transpose: Vt[b][d][t] = Vfull[b][t][d] ----------------
__global__ void vtrans_kernel(const float* __restrict__ vnew,
                              const float* __restrict__ kvc, int layer,
                              float* __restrict__ vt)
{
    __shared__ float tile[32][33];
    int b = blockIdx.z;
    int t0 = blockIdx.x * 32;
    int d0 = blockIdx.y * 32;
    int tx = threadIdx.x, ty = threadIdx.y;
    const float* Vc = kvc + ((size_t)(layer * 2 + 1) * BATCH + b) * (size_t)(PREF * HEADD);
#pragma unroll
    for (int j = 0; j < 4; j++) {
        int t = t0 + ty + j * 8;
        float v = 0.f;
        if (t < PREF)      v = Vc[(size_t)t * 256 + d0 + tx];
        else if (t < TTOT) v = vnew[((size_t)(b * SEQ + t - PREF)) * 256 + d0 + tx];
        tile[ty + j * 8][tx] = v;
    }
    __syncthreads();
#pragma unroll
    for (int j = 0; j < 4; j++) {
        int d = d0 + ty + j * 8;
        vt[((size_t)b * HEADD + d) * TPAD + t0 + tx] = tile[tx][ty + j * 8];
    }
}

// ---------------- prep ----------------
__global__ void prep_kernel(const void* __restrict__ maskp,
                            const float* __restrict__ ts)
{
    int bb = blockIdx.x;
    if (bb < BATCH) {
        int b = bb;
        const int* mi = (const int*)maskp;
        const unsigned char* mu = (const unsigned char*)maskp;
        int w0 = mi[0];
        bool is_i32 = (w0 == 0 || w0 == 1);
        __shared__ int cnt;
        if (threadIdx.x == 0) cnt = 0;
        __syncthreads();
        int local = 0;
        for (int t = threadIdx.x; t < PREF; t += blockDim.x) {
            int m = is_i32 ? mi[b * PREF + t] : (int)mu[b * PREF + t];
            bool on = (m != 0);
            g_biasPref[b * PREF + t] = on ? 0.f : -1e9f;
            if (on) local++;
        }
        atomicAdd(&cnt, local);
        __syncthreads();
        if (threadIdx.x == 0) g_plen[b] = cnt;
    } else {
        int b = bb - BATCH;
        float tsb = ts[b];
        for (int i = threadIdx.x; i < 512; i += blockDim.x) {
            float frac = (float)i / 511.f;
            float period = 4e-3f * powf(1000.f, frac);
            float arg = (6.283185307179586f / period) * tsb;
            float sv, cv;
            sincosf(arg, &sv, &cv);
            g_temb[b * HDIM + i]       = sv;
            g_temb[b * HDIM + 512 + i] = cv;
        }
    }
}

// ---------------- SIMT SGEMM (small GEMMs only) ----------------
__global__ void __launch_bounds__(256) sgemm_kernel(
    const float* __restrict__ A, const float* __restrict__ W,
    float* __restrict__ C, const float* __restrict__ bias,
    int M, int N, int K, int lda, int accumulate)
{
    __shared__ float As[16][64];
    __shared__ float Bs[16][64];
    const int tid = threadIdx.x;
    const int tx = tid & 15;
    const int ty = tid >> 4;
    const int rowBase = blockIdx.y * 64;
    const int colBase = blockIdx.x * 64;

    const int lm  = tid >> 2;
    const int lk  = (tid & 3) << 2;
    const int lkr = tid >> 4;
    const int ln  = (tid & 15) << 2;

    float acc[4][4];
#pragma unroll
    for (int i = 0; i < 4; i++)
#pragma unroll
        for (int j = 0; j < 4; j++) acc[i][j] = 0.f;

    for (int k0 = 0; k0 < K; k0 += 16) {
        float4 av = make_float4(0.f, 0.f, 0.f, 0.f);
        int ar = rowBase + lm;
        if (ar < M) av = *(const float4*)(A + (size_t)ar * lda + (k0 + lk));
        As[lk + 0][lm] = av.x;
        As[lk + 1][lm] = av.y;
        As[lk + 2][lm] = av.z;
        As[lk + 3][lm] = av.w;

        float4 bv;
        int bn = colBase + ln;
        const float* wrow = W + (size_t)(k0 + lkr) * N;
        if (bn + 3 < N) {
            bv = *(const float4*)(wrow + bn);
        } else {
            bv.x = (bn + 0 < N) ? wrow[bn + 0] : 0.f;
            bv.y = (bn + 1 < N) ? wrow[bn + 1] : 0.f;
            bv.z = (bn + 2 < N) ? wrow[bn + 2] : 0.f;
            bv.w = (bn + 3 < N) ? wrow[bn + 3] : 0.f;
        }
        *(float4*)(&Bs[lkr][ln]) = bv;
        __syncthreads();

#pragma unroll
        for (int kk = 0; kk < 16; kk++) {
            float4 a = *(const float4*)(&As[kk][ty << 2]);
            float4 b = *(const float4*)(&Bs[kk][tx << 2]);
            acc[0][0] += a.x * b.x; acc[0][1] += a.x * b.y; acc[0][2] += a.x * b.z; acc[0][3] += a.x * b.w;
            acc[1][0] += a.y * b.x; acc[1][1] += a.y * b.y; acc[1][2] += a.y * b.z; acc[1][3] += a.y * b.w;
            acc[2][0] += a.z * b.x; acc[2][1] += a.z * b.y; acc[2][2] += a.z * b.z; acc[2][3] += a.z * b.w;
            acc[3][0] += a.w * b.x; acc[3][1] += a.w * b.y; acc[3][2] += a.w * b.z; acc[3][3] += a.w * b.w;
        }
        __syncthreads();
    }

#pragma unroll
    for (int i = 0; i < 4; i++) {
        int r = rowBase + (ty << 2) + i;
        if (r >= M) continue;
#pragma unroll
        for (int j = 0; j < 4; j++) {
            int cx = colBase + (tx << 2) + j;
            if (cx >= N) continue;
            float v = acc[i][j];
            if (bias) v += bias[cx];
            size_t off = (size_t)r * N + cx;
            if (accumulate) v += C[off];
            C[off] = v;
        }
    }
}

// ---------------- small-M (M<=8) GEMM core ----------------
__device__ __forceinline__ void gemv8_core(
    const float* __restrict__ A, const float* __restrict__ W,
    const float* __restrict__ bias, float* __restrict__ C,
    int N, int K, int act, int bx)
{
    __shared__ float a_s[8 * 1024];
    __shared__ float red[4 * 64 * 8];
    int tid = threadIdx.x;
    for (int e = tid; e < 8 * K; e += 256) a_s[e] = A[e];
    __syncthreads();

    int nl = tid & 63;
    int n  = bx * 64 + nl;
    int ks = tid >> 6;
    float acc[8];
#pragma unroll
    for (int m = 0; m < 8; m++) acc[m] = 0.f;

    int kc = K >> 2;
    if (n < N) {
        int kbeg = ks * kc;
#pragma unroll 4
        for (int k = 0; k < kc; k++) {
            float w = W[(size_t)(kbeg + k) * N + n];
#pragma unroll
            for (int m = 0; m < 8; m++) acc[m] += a_s[m * K + kbeg + k] * w;
        }
    }
#pragma unroll
    for (int m = 0; m < 8; m++) red[tid * 8 + m] = acc[m];
    __syncthreads();
    if (ks == 0 && n < N) {
#pragma unroll
        for (int m = 0; m < 8; m++) {
            float v = red[(0 * 64 + nl) * 8 + m] + red[(1 * 64 + nl) * 8 + m] +
                      red[(2 * 64 + nl) * 8 + m] + red[(3 * 64 + nl) * 8 + m];
            if (bias) v += bias[n];
            if (act == 1) v = v / (1.f + expf(-v));
            C[(size_t)m * N + n] = v;
        }
    }
}

__global__ void __launch_bounds__(256) gemv8_kernel(
    const float* __restrict__ A, const float* __restrict__ W,
    const float* __restrict__ bias, float* __restrict__ C,
    int N, int K, int act)
{
    gemv8_core(A, W, bias, C, N, K, act, blockIdx.x);
}

__global__ void __launch_bounds__(256) adaall_kernel(
    const float* __restrict__ tvec,
    const float* __restrict__ Wada1, const float* __restrict__ Wada2,
    float* __restrict__ out)
{
    int li = blockIdx.y;
    const float* W = (li < NLAYER) ? (Wada1 + (size_t)li * HDIM * HDIM)
                                   : (Wada2 + (size_t)(li - NLAYER) * HDIM * HDIM);
    gemv8_core(tvec, W, nullptr, out + (size_t)li * BATCH * HDIM,
               HDIM, HDIM, 0, blockIdx.x);
}

// ---------------- rmsnorm ----------------
__global__ void __launch_bounds__(256) rmsnorm_kernel(
    const float* __restrict__ x, const float* __restrict__ w,
    const float* __restrict__ ada, float* __restrict__ out)
{
    int row = blockIdx.x;
    int b = row / SEQ;
    const float* xr = x + (size_t)row * HDIM;
    __shared__ float red[256];
    float s = 0.f;
    for (int i = threadIdx.x; i < HDIM; i += 256) {
        float v = xr[i];
        s += v * v;
    }
    red[threadIdx.x] = s;
    __syncthreads();
    for (int st = 128; st > 0; st >>= 1) {
        if (threadIdx.x < st) red[threadIdx.x] += red[threadIdx.x + st];
        __syncthreads();
    }
    float r = rsqrtf(red[0] * (1.f / HDIM) + 1e-6f);
    for (int i = threadIdx.x; i < HDIM; i += 256) {
        float gmul = w[i];
        if (ada) gmul *= (1.f + ada[b * HDIM + i]);
        out[(size_t)row * HDIM + i] = xr[i] * r * gmul;
    }
}

// ---------------- rope ----------------
__global__ void rope_kernel(float* __restrict__ q, float* __restrict__ k)
{
    int idx = blockIdx.x * blockDim.x + threadIdx.x;
    const int total = MTOK * 9 * 128;
    if (idx >= total) return;
    int j = idx & 127;
    int rest = idx >> 7;
    int hh = rest % 9;
    int row = rest / 9;
    int b = row / SEQ, s = row % SEQ;
    float pos = (float)(g_plen[b] + s);
    float inv = powf(10000.f, -(float)j / 128.f);
    float fr = pos * inv;
    float sn, cs;
    sincosf(fr, &sn, &cs);
    float* p = (hh < 8) ? (q + ((size_t)row * 8 + hh) * 256) : (k + (size_t)row * 256);
    float x1 = p[j], x2 = p[j + 128];
    p[j]       = x1 * cs - x2 * sn;
    p[j + 128] = x2 * cs + x1 * sn;
}

// ---------------- softmax (zero-pads [TTOT, TPAD)) ----------------
__global__ void __launch_bounds__(256) softmax_kernel()
{
    int row = blockIdx.x;
    float* p = g_sc + (size_t)row * TPAD;
    __shared__ float red[256];
    float mx = -1e30f;
    for (int i = threadIdx.x; i < TTOT; i += 256) mx = fmaxf(mx, p[i]);
    red[threadIdx.x] = mx;
    __syncthreads();
    for (int st = 128; st > 0; st >>= 1) {
        if (threadIdx.x < st) red[threadIdx.x] = fmaxf(red[threadIdx.x], red[threadIdx.x + st]);
        __syncthreads();
    }
    float m = red[0];
    __syncthreads();
    float s = 0.f;
    for (int i = threadIdx.x; i < TTOT; i += 256) {
        float e = expf(p[i] - m);
        p[i] = e;
        s += e;
    }
    red[threadIdx.x] = s;
    __syncthreads();
    for (int st = 128; st > 0; st >>= 1) {
        if (threadIdx.x < st) red[threadIdx.x] += red[threadIdx.x + st];
        __syncthreads();
    }
    float inv = 1.f / red[0];
    for (int i = threadIdx.x; i < TTOT; i += 256) p[i] *= inv;
    if (threadIdx.x < TPAD - TTOT) p[TTOT + threadIdx.x] = 0.f;
}

// ---------------- host ----------------
static inline dim3 gemm_grid(int M, int N) { return dim3((N + 63) / 64, (M + 63) / 64); }
static inline dim3 tc_grid(int M, int N) { return dim3(N / 128, (M + 63) / 64); }

extern "C" void kernel_launch(void* const* d_in, const int* in_sizes, int n_in,
                              void* d_out, int out_size)
{
    const float* x_t      = (const float*)d_in[0];
    const float* timestep = (const float*)d_in[1];
    const void*  mask     = d_in[2];
    const float* kvc      = (const float*)d_in[3];
    const float* Wa_in    = (const float*)d_in[4];
    const float* ba_in    = (const float*)d_in[5];
    const float* Wt_in    = (const float*)d_in[6];
    const float* bt_in    = (const float*)d_in[7];
    const float* Wt_out   = (const float*)d_in[8];
    const float* bt_out   = (const float*)d_in[9];
    const float* Wq       = (const float*)d_in[10];
    const float* Wk       = (const float*)d_in[11];
    const float* Wv       = (const float*)d_in[12];
    const float* Wo       = (const float*)d_in[13];
    const float* Wg       = (const float*)d_in[14];
    const float* Wu       = (const float*)d_in[15];
    const float* Wd       = (const float*)d_in[16];
    const float* n1_w     = (const float*)d_in[17];
    const float* n2_w     = (const float*)d_in[18];
    const float* Wada1    = (const float*)d_in[19];
    const float* Wada2    = (const float*)d_in[20];
    const float* nf_w     = (const float*)d_in[21];
    const float* Wa_out   = (const float*)d_in[22];
    const float* ba_out   = (const float*)d_in[23];

    void* p;
    cudaGetSymbolAddress(&p, g_x);      float* px    = (float*)p;
    cudaGetSymbolAddress(&p, g_h);      float* ph    = (float*)p;
    cudaGetSymbolAddress(&p, g_temb);   float* ptemb = (float*)p;
    cudaGetSymbolAddress(&p, g_t1);     float* pt1   = (float*)p;
    cudaGetSymbolAddress(&p, g_tv);     float* ptv   = (float*)p;
    cudaGetSymbolAddress(&p, g_adaAll); float* padaA = (float*)p;
    cudaGetSymbolAddress(&p, g_q);      float* pq    = (float*)p;
    cudaGetSymbolAddress(&p, g_k);      float* pk    = (float*)p;
    cudaGetSymbolAddress(&p, g_v);      float* pv    = (float*)p;
    cudaGetSymbolAddress(&p, g_vt);     float* pvt   = (float*)p;
    cudaGetSymbolAddress(&p, g_ao);     float* pao   = (float*)p;
    cudaGetSymbolAddress(&p, g_gg);     float* pg    = (float*)p;
    cudaGetSymbolAddress(&p, g_uu);     float* pu    = (float*)p;

    prep_kernel<<<16, 512>>>(mask, timestep);

    gemv8_kernel<<<16, 256>>>(ptemb, Wt_in, bt_in, pt1, HDIM, HDIM, 1);
    gemv8_kernel<<<16, 256>>>(pt1, Wt_out, bt_out, ptv, HDIM, HDIM, 1);
    adaall_kernel<<<dim3(16, 2 * NLAYER), 256>>>(ptv, Wada1, Wada2, padaA);

    sgemm_kernel<<<gemm_grid(MTOK, HDIM), 256>>>(x_t, Wa_in, px, ba_in,
                                                 MTOK, HDIM, ADIM, ADIM, 0);

    for (int l = 0; l < NLAYER; l++) {
        const float* wq = Wq + (size_t)l * HDIM * (NHEAD * HEADD);
        const float* wk = Wk + (size_t)l * HDIM * HEADD;
        const float* wv = Wv + (size_t)l * HDIM * HEADD;
        const float* wo = Wo + (size_t)l * (NHEAD * HEADD) * HDIM;
        const float* wg = Wg + (size_t)l * HDIM * MLPD;
        const float* wu = Wu + (size_t)l * HDIM * MLPD;
        const float* wd = Wd + (size_t)l * MLPD * HDIM;
        const float* w1 = n1_w + (size_t)l * HDIM;
        const float* w2 = n2_w + (size_t)l * HDIM;
        const float* ada1 = padaA + (size_t)l * BATCH * HDIM;
        const float* ada2 = padaA + (size_t)(NLAYER + l) * BATCH * HDIM;

        rmsnorm_kernel<<<MTOK, 256>>>(px, w1, ada1, ph);

        qkv_kernel<<<dim3(20, 7), 256>>>(ph, wq, wk, wv, pq, pk, pv);
        vtrans_kernel<<<dim3(27, 8, 8), dim3(32, 8)>>>(pv, kvc, l, pvt);
        rope_kernel<<<(MTOK * 9 * 128 + 255) / 256, 256>>>(pq, pk);

        attn_scores_kernel<<<dim3(7, 7, 8), 256>>>(pq, pk, kvc, l);
        softmax_kernel<<<BATCH * NHEAD * SEQ, 256>>>();
        attn_pv_kernel<<<dim3(2, 7, 8), 256>>>(pvt, pao);

        mma_gemm_kernel<<<tc_grid(MTOK, HDIM), 256>>>(
            pao, wo, px, nullptr, MTOK, HDIM, NHEAD * HEADD, 1);

        rmsnorm_kernel<<<MTOK, 256>>>(px, w2, ada2, ph);

        mma_gemm_kernel<<<tc_grid(MTOK, MLPD), 256>>>(
            ph, wg, pg, nullptr, MTOK, MLPD, HDIM, 0);
        mma_gemm_kernel<<<tc_grid(MTOK, MLPD), 256>>>(
            ph, wu, pu, pg, MTOK, MLPD, HDIM, 2);
        mma_gemm_kernel<<<tc_grid(MTOK, HDIM), 256>>>(
            pu, wd, px, nullptr, MTOK, HDIM, MLPD, 1);
    }

    rmsnorm_kernel<<<MTOK, 256>>>(px, nf_w, nullptr, ph);
    sgemm_kernel<<<gemm_grid(MTOK, ADIM), 256>>>(ph, Wa_out, (float*)d_out, ba_out,
                                                 MTOK, ADIM, HDIM, HDIM, 0);
}

// round 8
// speedup vs baseline: 4.2413x; 1.2727x over previous
#include <cuda_runtime.h>
#include <math.h>
#include <stdint.h>

// ---------------- problem dims ----------------
#define NLAYER 18
#define HDIM   1024
#define NHEAD  8
#define HEADD  256
#define MLPD   4096
#define BATCH  8
#define SEQ    50
#define PREF   800
#define ADIM   32
#define TTOT   850
#define TPAD   864
#define MTOK   400

// ---------------- device scratch ----------------
__device__ float g_x[MTOK * HDIM];
__device__ float g_h[MTOK * HDIM];
__device__ float g_temb[BATCH * HDIM];
__device__ float g_t1[BATCH * HDIM];
__device__ float g_tv[BATCH * HDIM];
__device__ float g_adaAll[2 * NLAYER * BATCH * HDIM];
__device__ float g_q[MTOK * NHEAD * HEADD];
__device__ float g_k[MTOK * HEADD];
__device__ float g_v[MTOK * HEADD];
__device__ float g_sc[BATCH * NHEAD * SEQ * TPAD];
__device__ float g_vt[BATCH * HEADD * TPAD];
__device__ float g_ao[MTOK * NHEAD * HEADD];
__device__ float g_gg[MTOK * MLPD];
__device__ float g_uu[MTOK * MLPD];
__device__ int   g_plen[BATCH];
__device__ float g_biasPref[BATCH * PREF];

// ---------------- bf16 split helpers ----------------
__device__ __forceinline__ void split2(float lo, float hi, uint32_t& hw, uint32_t& lw) {
    asm("cvt.rn.bf16x2.f32 %0, %1, %2;" : "=r"(hw) : "f"(hi), "f"(lo));
    float hlo = __uint_as_float(hw << 16);
    float hhi = __uint_as_float(hw & 0xffff0000u);
    asm("cvt.rn.bf16x2.f32 %0, %1, %2;" : "=r"(lw) : "f"(hi - hhi), "f"(lo - hlo));
}
__device__ __forceinline__ void mma_bf16(
    float c[4], const uint32_t a[4], uint32_t b0, uint32_t b1)
{
    asm volatile(
        "mma.sync.aligned.m16n8k16.row.col.f32.bf16.bf16.f32 "
        "{%0,%1,%2,%3}, {%4,%5,%6,%7}, {%8,%9}, {%0,%1,%2,%3};"
        : "+f"(c[0]), "+f"(c[1]), "+f"(c[2]), "+f"(c[3])
        : "r"(a[0]), "r"(a[1]), "r"(a[2]), "r"(a[3]), "r"(b0), "r"(b1));
}
__device__ __forceinline__ float gelu_f(float x) {
    float t = tanhf(0.7978845608028654f * (x + 0.044715f * x * x * x));
    return 0.5f * x * (1.f + t);
}

// ============ split-bf16 (3-term) mma GEMM core, M-tile 64, split-K ============
// Tile 64x128x(32*nChunks) starting at kBase. 256 threads, 8 warps (2m x 4n).
// epiMode: 0 store, 1 accumulate, 2 gated gelu, 3 atomicAdd.
#define PADA 20
#define PADB 136
__device__ __forceinline__ void gemm_core(
    const float* __restrict__ A, const float* __restrict__ W,
    float* __restrict__ C, const float* __restrict__ Cg,
    int M, int Nw, int Kstride, int kBase, int nChunks,
    int rowBase, int colBase, int epiMode,
    uint32_t* AsHi, uint32_t* AsLo, uint32_t* BsHi, uint32_t* BsLo)
{
    const int tid  = threadIdx.x;
    const int lane = tid & 31;
    const int warp = tid >> 5;
    const int wm = (warp & 1) << 5;
    const int wn = (warp >> 1) << 5;

    const int aRow = tid >> 3;
    const int aK4  = (tid & 7) << 2;
    const int aKw  = (tid & 7) << 1;
    const int bKw  = tid >> 4;
    const int bN   = (tid & 15) << 3;

    float c[2][4][4];
#pragma unroll
    for (int i = 0; i < 2; i++)
#pragma unroll
        for (int j = 0; j < 4; j++)
#pragma unroll
            for (int r = 0; r < 4; r++) c[i][j][r] = 0.f;

    float4 pa[2], pb[4];
    {
#pragma unroll
        for (int p = 0; p < 2; p++) {
            int gr = rowBase + aRow + (p << 5);
            pa[p] = make_float4(0.f, 0.f, 0.f, 0.f);
            if (gr < M) pa[p] = *(const float4*)(A + (size_t)gr * Kstride + kBase + aK4);
        }
        const float* br0 = W + (size_t)(kBase + 2 * bKw) * Nw + colBase + bN;
        pb[0] = *(const float4*)(br0);
        pb[1] = *(const float4*)(br0 + 4);
        pb[2] = *(const float4*)(br0 + Nw);
        pb[3] = *(const float4*)(br0 + Nw + 4);
    }

    for (int i = 0; i < nChunks; i++) {
#pragma unroll
        for (int p = 0; p < 2; p++) {
            int r = aRow + (p << 5);
            uint32_t h0, l0, h1, l1;
            split2(pa[p].x, pa[p].y, h0, l0);
            split2(pa[p].z, pa[p].w, h1, l1);
            *(uint2*)(&AsHi[r * PADA + aKw]) = make_uint2(h0, h1);
            *(uint2*)(&AsLo[r * PADA + aKw]) = make_uint2(l0, l1);
        }
        {
            uint32_t hw[8], lw[8];
            const float* p0 = (const float*)&pb[0];
            const float* p1 = (const float*)&pb[2];
#pragma unroll
            for (int j = 0; j < 8; j++) split2(p0[j], p1[j], hw[j], lw[j]);
            *(uint4*)(&BsHi[bKw * PADB + bN])     = make_uint4(hw[0], hw[1], hw[2], hw[3]);
            *(uint4*)(&BsHi[bKw * PADB + bN + 4]) = make_uint4(hw[4], hw[5], hw[6], hw[7]);
            *(uint4*)(&BsLo[bKw * PADB + bN])     = make_uint4(lw[0], lw[1], lw[2], lw[3]);
            *(uint4*)(&BsLo[bKw * PADB + bN + 4]) = make_uint4(lw[4], lw[5], lw[6], lw[7]);
        }
        __syncthreads();

        if (i + 1 < nChunks) {
            int k0 = kBase + ((i + 1) << 5);
#pragma unroll
            for (int p = 0; p < 2; p++) {
                int gr = rowBase + aRow + (p << 5);
                pa[p] = make_float4(0.f, 0.f, 0.f, 0.f);
                if (gr < M) pa[p] = *(const float4*)(A + (size_t)gr * Kstride + k0 + aK4);
            }
            const float* br0 = W + (size_t)(k0 + 2 * bKw) * Nw + colBase + bN;
            pb[0] = *(const float4*)(br0);
            pb[1] = *(const float4*)(br0 + 4);
            pb[2] = *(const float4*)(br0 + Nw);
            pb[3] = *(const float4*)(br0 + Nw + 4);
        }

#pragma unroll
        for (int ks = 0; ks < 2; ks++) {
            const int kf = (ks << 3) + (lane & 3);
            uint32_t bh[4][2], bl[4][2];
#pragma unroll
            for (int nf = 0; nf < 4; nf++) {
                int n0 = wn + (nf << 3) + (lane >> 2);
                bh[nf][0] = BsHi[kf * PADB + n0];
                bh[nf][1] = BsHi[(kf + 4) * PADB + n0];
                bl[nf][0] = BsLo[kf * PADB + n0];
                bl[nf][1] = BsLo[(kf + 4) * PADB + n0];
            }
#pragma unroll
            for (int mf = 0; mf < 2; mf++) {
                int m0 = wm + (mf << 4) + (lane >> 2);
                uint32_t ah[4], al[4];
                ah[0] = AsHi[m0 * PADA + kf];
                ah[1] = AsHi[(m0 + 8) * PADA + kf];
                ah[2] = AsHi[m0 * PADA + kf + 4];
                ah[3] = AsHi[(m0 + 8) * PADA + kf + 4];
                al[0] = AsLo[m0 * PADA + kf];
                al[1] = AsLo[(m0 + 8) * PADA + kf];
                al[2] = AsLo[m0 * PADA + kf + 4];
                al[3] = AsLo[(m0 + 8) * PADA + kf + 4];
#pragma unroll
                for (int nf = 0; nf < 4; nf++) {
                    mma_bf16(c[mf][nf], al, bh[nf][0], bh[nf][1]);
                    mma_bf16(c[mf][nf], ah, bl[nf][0], bl[nf][1]);
                    mma_bf16(c[mf][nf], ah, bh[nf][0], bh[nf][1]);
                }
            }
        }
        __syncthreads();
    }

#pragma unroll
    for (int mf = 0; mf < 2; mf++) {
        int r0 = rowBase + wm + (mf << 4) + (lane >> 2);
#pragma unroll
        for (int nf = 0; nf < 4; nf++) {
            int cc = colBase + wn + (nf << 3) + ((lane & 3) << 1);
#pragma unroll
            for (int half = 0; half < 2; half++) {
                int rr = r0 + half * 8;
                if (rr >= M) continue;
                size_t off = (size_t)rr * Nw + cc;
                float2 v = make_float2(c[mf][nf][half * 2], c[mf][nf][half * 2 + 1]);
                if (epiMode == 3) {
                    atomicAdd(C + off, v.x);
                    atomicAdd(C + off + 1, v.y);
                    continue;
                }
                if (epiMode == 1) {
                    float2 old = *(float2*)(C + off);
                    v.x += old.x; v.y += old.y;
                } else if (epiMode == 2) {
                    float2 gg = *(const float2*)(Cg + off);
                    v.x *= gelu_f(gg.x); v.y *= gelu_f(gg.y);
                }
                *(float2*)(C + off) = v;
            }
        }
    }
}

#define GEMM_SHARED \
    __shared__ uint32_t AsHi[64 * PADA]; \
    __shared__ uint32_t AsLo[64 * PADA]; \
    __shared__ uint32_t BsHi[16 * PADB]; \
    __shared__ uint32_t BsLo[16 * PADB];

// splitK via gridDim.z; if z-split, epilogue is atomicAdd.
__global__ void __launch_bounds__(256, 2) mma_gemm_kernel(
    const float* __restrict__ A, const float* __restrict__ W,
    float* __restrict__ C, const float* __restrict__ Cg,
    int M, int N, int K, int epiMode)
{
    GEMM_SHARED
    int splits = gridDim.z;
    int kLen = K / splits;
    int kBase = blockIdx.z * kLen;
    int em = (splits > 1) ? 3 : epiMode;
    gemm_core(A, W, C, Cg, M, N, K, kBase, kLen >> 5,
              blockIdx.y * 64, blockIdx.x * 128, em,
              AsHi, AsLo, BsHi, BsLo);
}

// fused QKV: grid (20, 7, 2) split-K, atomicAdd into zeroed outputs
__global__ void __launch_bounds__(256, 2) qkv_kernel(
    const float* __restrict__ A,
    const float* __restrict__ Wq, const float* __restrict__ Wk, const float* __restrict__ Wv,
    float* __restrict__ oq, float* __restrict__ ok, float* __restrict__ ov)
{
    GEMM_SHARED
    int bx = blockIdx.x;
    const float* W; float* C; int Nw, colBase;
    if (bx < 16)      { W = Wq; C = oq; Nw = 2048; colBase = bx * 128; }
    else if (bx < 18) { W = Wk; C = ok; Nw = 256;  colBase = (bx - 16) * 128; }
    else              { W = Wv; C = ov; Nw = 256;  colBase = (bx - 18) * 128; }
    int kBase = blockIdx.z << 9;     // 0 or 512
    gemm_core(A, W, C, nullptr, MTOK, Nw, HDIM, kBase, 16,
              blockIdx.y * 64, colBase, 3, AsHi, AsLo, BsHi, BsLo);
}

// ============ attention scores via split-bf16 MMA, M-tile 64 ============
__global__ void __launch_bounds__(256, 2) attn_scores_kernel(
    const float* __restrict__ q, const float* __restrict__ knew,
    const float* __restrict__ kvc, int layer)
{
    __shared__ uint32_t AsHi[64 * PADA];
    __shared__ uint32_t AsLo[64 * PADA];
    __shared__ uint32_t BsHi[128 * PADA];
    __shared__ uint32_t BsLo[128 * PADA];

    const int tid  = threadIdx.x;
    const int lane = tid & 31;
    const int warp = tid >> 5;
    const int wm = (warp & 1) << 5;
    const int wn = (warp >> 1) << 5;
    const int b = blockIdx.z;
    const int rowBase = blockIdx.y * 64;
    const int colBase = blockIdx.x * 128;

    const float* Kc = kvc + ((size_t)(layer * 2) * BATCH + b) * (size_t)(PREF * HEADD);
    const float* Ab = q + (size_t)b * 400 * 256;

    const int aRow = tid >> 3;
    const int aK4  = (tid & 7) << 2;
    const int aKw  = (tid & 7) << 1;

    float c[2][4][4];
#pragma unroll
    for (int i = 0; i < 2; i++)
#pragma unroll
        for (int j = 0; j < 4; j++)
#pragma unroll
            for (int r = 0; r < 4; r++) c[i][j][r] = 0.f;

    float4 pa[2], pb[4];
#pragma unroll
    for (int p = 0; p < 2; p++) {
        int gr = rowBase + aRow + (p << 5);
        pa[p] = make_float4(0.f, 0.f, 0.f, 0.f);
        if (gr < 400) pa[p] = *(const float4*)(Ab + (size_t)gr * 256 + aK4);
    }
#pragma unroll
    for (int p = 0; p < 4; p++) {
        int t = colBase + aRow + (p << 5);
        pb[p] = make_float4(0.f, 0.f, 0.f, 0.f);
        if (t < PREF)      pb[p] = *(const float4*)(Kc + (size_t)t * 256 + aK4);
        else if (t < TTOT) pb[p] = *(const float4*)(knew + ((size_t)(b * SEQ + t - PREF)) * 256 + aK4);
    }

#pragma unroll 1
    for (int i = 0; i < 8; i++) {
#pragma unroll
        for (int p = 0; p < 2; p++) {
            int r = aRow + (p << 5);
            uint32_t h0, l0, h1, l1;
            split2(pa[p].x, pa[p].y, h0, l0);
            split2(pa[p].z, pa[p].w, h1, l1);
            *(uint2*)(&AsHi[r * PADA + aKw]) = make_uint2(h0, h1);
            *(uint2*)(&AsLo[r * PADA + aKw]) = make_uint2(l0, l1);
        }
#pragma unroll
        for (int p = 0; p < 4; p++) {
            int r = aRow + (p << 5);
            uint32_t h0, l0, h1, l1;
            split2(pb[p].x, pb[p].y, h0, l0);
            split2(pb[p].z, pb[p].w, h1, l1);
            *(uint2*)(&BsHi[r * PADA + aKw]) = make_uint2(h0, h1);
            *(uint2*)(&BsLo[r * PADA + aKw]) = make_uint2(l0, l1);
        }
        __syncthreads();

        if (i + 1 < 8) {
            int k0 = (i + 1) << 5;
#pragma unroll
            for (int p = 0; p < 2; p++) {
                int gr = rowBase + aRow + (p << 5);
                pa[p] = make_float4(0.f, 0.f, 0.f, 0.f);
                if (gr < 400) pa[p] = *(const float4*)(Ab + (size_t)gr * 256 + k0 + aK4);
            }
#pragma unroll
            for (int p = 0; p < 4; p++) {
                int t = colBase + aRow + (p << 5);
                pb[p] = make_float4(0.f, 0.f, 0.f, 0.f);
                if (t < PREF)      pb[p] = *(const float4*)(Kc + (size_t)t * 256 + k0 + aK4);
                else if (t < TTOT) pb[p] = *(const float4*)(knew + ((size_t)(b * SEQ + t - PREF)) * 256 + k0 + aK4);
            }
        }

#pragma unroll
        for (int ks = 0; ks < 2; ks++) {
            const int kf = (ks << 3) + (lane & 3);
            uint32_t bh[4][2], bl[4][2];
#pragma unroll
            for (int nf = 0; nf < 4; nf++) {
                int n0 = wn + (nf << 3) + (lane >> 2);
                bh[nf][0] = BsHi[n0 * PADA + kf];
                bh[nf][1] = BsHi[n0 * PADA + kf + 4];
                bl[nf][0] = BsLo[n0 * PADA + kf];
                bl[nf][1] = BsLo[n0 * PADA + kf + 4];
            }
#pragma unroll
            for (int mf = 0; mf < 2; mf++) {
                int m0 = wm + (mf << 4) + (lane >> 2);
                uint32_t ah[4], al[4];
                ah[0] = AsHi[m0 * PADA + kf];
                ah[1] = AsHi[(m0 + 8) * PADA + kf];
                ah[2] = AsHi[m0 * PADA + kf + 4];
                ah[3] = AsHi[(m0 + 8) * PADA + kf + 4];
                al[0] = AsLo[m0 * PADA + kf];
                al[1] = AsLo[(m0 + 8) * PADA + kf];
                al[2] = AsLo[m0 * PADA + kf + 4];
                al[3] = AsLo[(m0 + 8) * PADA + kf + 4];
#pragma unroll
                for (int nf = 0; nf < 4; nf++) {
                    mma_bf16(c[mf][nf], al, bh[nf][0], bh[nf][1]);
                    mma_bf16(c[mf][nf], ah, bl[nf][0], bl[nf][1]);
                    mma_bf16(c[mf][nf], ah, bh[nf][0], bh[nf][1]);
                }
            }
        }
        __syncthreads();
    }

    const float scale = 0.0625f;
#pragma unroll
    for (int mf = 0; mf < 2; mf++) {
        int r0 = rowBase + wm + (mf << 4) + (lane >> 2);
#pragma unroll
        for (int nf = 0; nf < 4; nf++) {
            int t = colBase + wn + (nf << 3) + ((lane & 3) << 1);
            if (t >= TTOT) continue;
            float2 bias;
            bias.x = (t < PREF) ? g_biasPref[b * PREF + t] : 0.f;
            bias.y = (t + 1 < PREF) ? g_biasPref[b * PREF + t + 1] : 0.f;
#pragma unroll
            for (int half = 0; half < 2; half++) {
                int rr = r0 + half * 8;
                if (rr >= 400) continue;
                int h = rr & 7, s = rr >> 3;
                size_t off = ((size_t)(b * 8 + h) * SEQ + s) * TPAD + t;
                float2 v = make_float2(c[mf][nf][half * 2] * scale + bias.x,
                                       c[mf][nf][half * 2 + 1] * scale + bias.y);
                *(float2*)(g_sc + off) = v;
            }
        }
    }
}

// ============ attention PV via split-bf16 MMA, M-tile 64, split-T ============
// grid (2, 7, 2): z splits T: z0 = chunks [0,14), z1 = [14,27). atomicAdd into zeroed out.
__global__ void __launch_bounds__(256, 2) attn_pv_kernel(
    const float* __restrict__ vt, float* __restrict__ out)
{
    __shared__ uint32_t AsHi[64 * PADA];
    __shared__ uint32_t AsLo[64 * PADA];
    __shared__ uint32_t BsHi[128 * PADA];
    __shared__ uint32_t BsLo[128 * PADA];

    const int tid  = threadIdx.x;
    const int lane = tid & 31;
    const int warp = tid >> 5;
    const int wm = (warp & 1) << 5;
    const int wn = (warp >> 1) << 5;
    const int bz = blockIdx.z;
    const int b = bz >> 1;
    const int zs = bz & 1;
    const int kBase = zs ? 448 : 0;
    const int nChunks = zs ? 13 : 14;
    const int rowBase = blockIdx.y * 64;
    const int colBase = blockIdx.x * 128;

    const float* Ab = g_sc + (size_t)b * 400 * TPAD;
    const float* Bb = vt + (size_t)b * HEADD * TPAD;

    const int aRow = tid >> 3;
    const int aK4  = (tid & 7) << 2;
    const int aKw  = (tid & 7) << 1;

    float c[2][4][4];
#pragma unroll
    for (int i = 0; i < 2; i++)
#pragma unroll
        for (int j = 0; j < 4; j++)
#pragma unroll
            for (int r = 0; r < 4; r++) c[i][j][r] = 0.f;

    float4 pa[2], pb[4];
#pragma unroll
    for (int p = 0; p < 2; p++) {
        int gr = rowBase + aRow + (p << 5);
        pa[p] = make_float4(0.f, 0.f, 0.f, 0.f);
        if (gr < 400) pa[p] = *(const float4*)(Ab + (size_t)gr * TPAD + kBase + aK4);
    }
#pragma unroll
    for (int p = 0; p < 4; p++) {
        int d = colBase + aRow + (p << 5);
        pb[p] = *(const float4*)(Bb + (size_t)d * TPAD + kBase + aK4);
    }

#pragma unroll 1
    for (int i = 0; i < nChunks; i++) {
#pragma unroll
        for (int p = 0; p < 2; p++) {
            int r = aRow + (p << 5);
            uint32_t h0, l0, h1, l1;
            split2(pa[p].x, pa[p].y, h0, l0);
            split2(pa[p].z, pa[p].w, h1, l1);
            *(uint2*)(&AsHi[r * PADA + aKw]) = make_uint2(h0, h1);
            *(uint2*)(&AsLo[r * PADA + aKw]) = make_uint2(l0, l1);
        }
#pragma unroll
        for (int p = 0; p < 4; p++) {
            int r = aRow + (p << 5);
            uint32_t h0, l0, h1, l1;
            split2(pb[p].x, pb[p].y, h0, l0);
            split2(pb[p].z, pb[p].w, h1, l1);
            *(uint2*)(&BsHi[r * PADA + aKw]) = make_uint2(h0, h1);
            *(uint2*)(&BsLo[r * PADA + aKw]) = make_uint2(l0, l1);
        }
        __syncthreads();

        if (i + 1 < nChunks) {
            int k0 = kBase + ((i + 1) << 5);
#pragma unroll
            for (int p = 0; p < 2; p++) {
                int gr = rowBase + aRow + (p << 5);
                pa[p] = make_float4(0.f, 0.f, 0.f, 0.f);
                if (gr < 400) pa[p] = *(const float4*)(Ab + (size_t)gr * TPAD + k0 + aK4);
            }
#pragma unroll
            for (int p = 0; p < 4; p++) {
                int d = colBase + aRow + (p << 5);
                pb[p] = *(const float4*)(Bb + (size_t)d * TPAD + k0 + aK4);
            }
        }

#pragma unroll
        for (int ks = 0; ks < 2; ks++) {
            const int kf = (ks << 3) + (lane & 3);
            uint32_t bh[4][2], bl[4][2];
#pragma unroll
            for (int nf = 0; nf < 4; nf++) {
                int n0 = wn + (nf << 3) + (lane >> 2);
                bh[nf][0] = BsHi[n0 * PADA + kf];
                bh[nf][1] = BsHi[n0 * PADA + kf + 4];
                bl[nf][0] = BsLo[n0 * PADA + kf];
                bl[nf][1] = BsLo[n0 * PADA + kf + 4];
            }
#pragma unroll
            for (int mf = 0; mf < 2; mf++) {
                int m0 = wm + (mf << 4) + (lane >> 2);
                uint32_t ah[4], al[4];
                ah[0] = AsHi[m0 * PADA + kf];
                ah[1] = AsHi[(m0 + 8) * PADA + kf];
                ah[2] = AsHi[m0 * PADA + kf + 4];
                ah[3] = AsHi[(m0 + 8) * PADA + kf + 4];
                al[0] = AsLo[m0 * PADA + kf];
                al[1] = AsLo[(m0 + 8) * PADA + kf];
                al[2] = AsLo[m0 * PADA + kf + 4];
                al[3] = AsLo[(m0 + 8) * PADA + kf + 4];
#pragma unroll
                for (int nf = 0; nf < 4; nf++) {
                    mma_bf16(c[mf][nf], al, bh[nf][0], bh[nf][1]);
                    mma_bf16(c[mf][nf], ah, bl[nf][0], bl[nf][1]);
                    mma_bf16(c[mf][nf], ah, bh[nf][0], bh[nf][1]);
                }
            }
        }
        __syncthreads();
    }

#pragma unroll
    for (int mf = 0; mf < 2; mf++) {
        int r0 = rowBase + wm + (mf << 4) + (lane >> 2);
#pragma unroll
        for (int nf = 0; nf < 4; nf++) {
            int d = colBase + wn + (nf << 3) + ((lane & 3) << 1);
#pragma unroll
            for (int half = 0; half < 2; half++) {
                int rr = r0 + half * 8;
                if (rr >= 400) continue;
                int h = rr / SEQ, s = rr % SEQ;
                size_t off = (((size_t)(b * SEQ + s)) * 8 + h) * 256 + d;
                atomicAdd(out + off,     c[mf][nf][half * 2]);
                atomicAdd(out + off + 1, c[mf][nf][half * 2 + 1]);
            }
        }
    }
}

// ---------------- V transpose ----------------
__global__ void vtrans_kernel(const float* __restrict__ vnew,
                              const float* __restrict__ kvc, int layer,
                              float* __restrict__ vt)
{
    __shared__ float tile[32][33];
    int b = blockIdx.z;
    int t0 = blockIdx.x * 32;
    int d0 = blockIdx.y * 32;
    int tx = threadIdx.x, ty = threadIdx.y;
    const float* Vc = kvc + ((size_t)(layer * 2 + 1) * BATCH + b) * (size_t)(PREF * HEADD);
#pragma unroll
    for (int j = 0; j < 4; j++) {
        int t = t0 + ty + j * 8;
        float v = 0.f;
        if (t < PREF)      v = Vc[(size_t)t * 256 + d0 + tx];
        else if (t < TTOT) v = vnew[((size_t)(b * SEQ + t - PREF)) * 256 + d0 + tx];
        tile[ty + j * 8][tx] = v;
    }
    __syncthreads();
#pragma unroll
    for (int j = 0; j < 4; j++) {
        int d = d0 + ty + j * 8;
        vt[((size_t)b * HEADD + d) * TPAD + t0 + tx] = tile[tx][ty + j * 8];
    }
}

// ---------------- prep ----------------
__global__ void prep_kernel(const void* __restrict__ maskp,
                            const float* __restrict__ ts)
{
    int bb = blockIdx.x;
    if (bb < BATCH) {
        int b = bb;
        const int* mi = (const int*)maskp;
        const unsigned char* mu = (const unsigned char*)maskp;
        int w0 = mi[0];
        bool is_i32 = (w0 == 0 || w0 == 1);
        __shared__ int cnt;
        if (threadIdx.x == 0) cnt = 0;
        __syncthreads();
        int local = 0;
        for (int t = threadIdx.x; t < PREF; t += blockDim.x) {
            int m = is_i32 ? mi[b * PREF + t] : (int)mu[b * PREF + t];
            bool on = (m != 0);
            g_biasPref[b * PREF + t] = on ? 0.f : -1e9f;
            if (on) local++;
        }
        atomicAdd(&cnt, local);
        __syncthreads();
        if (threadIdx.x == 0) g_plen[b] = cnt;
    } else {
        int b = bb - BATCH;
        float tsb = ts[b];
        for (int i = threadIdx.x; i < 512; i += blockDim.x) {
            float frac = (float)i / 511.f;
            float period = 4e-3f * powf(1000.f, frac);
            float arg = (6.283185307179586f / period) * tsb;
            float sv, cv;
            sincosf(arg, &sv, &cv);
            g_temb[b * HDIM + i]       = sv;
            g_temb[b * HDIM + 512 + i] = cv;
        }
    }
}

// ---------------- SIMT SGEMM (small GEMMs only) ----------------
__global__ void __launch_bounds__(256) sgemm_kernel(
    const float* __restrict__ A, const float* __restrict__ W,
    float* __restrict__ C, const float* __restrict__ bias,
    int M, int N, int K, int lda, int accumulate)
{
    __shared__ float As[16][64];
    __shared__ float Bs[16][64];
    const int tid = threadIdx.x;
    const int tx = tid & 15;
    const int ty = tid >> 4;
    const int rowBase = blockIdx.y * 64;
    const int colBase = blockIdx.x * 64;

    const int lm  = tid >> 2;
    const int lk  = (tid & 3) << 2;
    const int lkr = tid >> 4;
    const int ln  = (tid & 15) << 2;

    float acc[4][4];
#pragma unroll
    for (int i = 0; i < 4; i++)
#pragma unroll
        for (int j = 0; j < 4; j++) acc[i][j] = 0.f;

    for (int k0 = 0; k0 < K; k0 += 16) {
        float4 av = make_float4(0.f, 0.f, 0.f, 0.f);
        int ar = rowBase + lm;
        if (ar < M) av = *(const float4*)(A + (size_t)ar * lda + (k0 + lk));
        As[lk + 0][lm] = av.x;
        As[lk + 1][lm] = av.y;
        As[lk + 2][lm] = av.z;
        As[lk + 3][lm] = av.w;

        float4 bv;
        int bn = colBase + ln;
        const float* wrow = W + (size_t)(k0 + lkr) * N;
        if (bn + 3 < N) {
            bv = *(const float4*)(wrow + bn);
        } else {
            bv.x = (bn + 0 < N) ? wrow[bn + 0] : 0.f;
            bv.y = (bn + 1 < N) ? wrow[bn + 1] : 0.f;
            bv.z = (bn + 2 < N) ? wrow[bn + 2] : 0.f;
            bv.w = (bn + 3 < N) ? wrow[bn + 3] : 0.f;
        }
        *(float4*)(&Bs[lkr][ln]) = bv;
        __syncthreads();

#pragma unroll
        for (int kk = 0; kk < 16; kk++) {
            float4 a = *(const float4*)(&As[kk][ty << 2]);
            float4 b = *(const float4*)(&Bs[kk][tx << 2]);
            acc[0][0] += a.x * b.x; acc[0][1] += a.x * b.y; acc[0][2] += a.x * b.z; acc[0][3] += a.x * b.w;
            acc[1][0] += a.y * b.x; acc[1][1] += a.y * b.y; acc[1][2] += a.y * b.z; acc[1][3] += a.y * b.w;
            acc[2][0] += a.z * b.x; acc[2][1] += a.z * b.y; acc[2][2] += a.z * b.z; acc[2][3] += a.z * b.w;
            acc[3][0] += a.w * b.x; acc[3][1] += a.w * b.y; acc[3][2] += a.w * b.z; acc[3][3] += a.w * b.w;
        }
        __syncthreads();
    }

#pragma unroll
    for (int i = 0; i < 4; i++) {
        int r = rowBase + (ty << 2) + i;
        if (r >= M) continue;
#pragma unroll
        for (int j = 0; j < 4; j++) {
            int cx = colBase + (tx << 2) + j;
            if (cx >= N) continue;
            float v = acc[i][j];
            if (bias) v += bias[cx];
            size_t off = (size_t)r * N + cx;
            if (accumulate) v += C[off];
            C[off] = v;
        }
    }
}

// ---------------- small-M (M<=8) GEMM core ----------------
__device__ __forceinline__ void gemv8_core(
    const float* __restrict__ A, const float* __restrict__ W,
    const float* __restrict__ bias, float* __restrict__ C,
    int N, int K, int act, int bx)
{
    __shared__ float a_s[8 * 1024];
    __shared__ float red[4 * 64 * 8];
    int tid = threadIdx.x;
    for (int e = tid; e < 8 * K; e += 256) a_s[e] = A[e];
    __syncthreads();

    int nl = tid & 63;
    int n  = bx * 64 + nl;
    int ks = tid >> 6;
    float acc[8];
#pragma unroll
    for (int m = 0; m < 8; m++) acc[m] = 0.f;

    int kc = K >> 2;
    if (n < N) {
        int kbeg = ks * kc;
#pragma unroll 4
        for (int k = 0; k < kc; k++) {
            float w = W[(size_t)(kbeg + k) * N + n];
#pragma unroll
            for (int m = 0; m < 8; m++) acc[m] += a_s[m * K + kbeg + k] * w;
        }
    }
#pragma unroll
    for (int m = 0; m < 8; m++) red[tid * 8 + m] = acc[m];
    __syncthreads();
    if (ks == 0 && n < N) {
#pragma unroll
        for (int m = 0; m < 8; m++) {
            float v = red[(0 * 64 + nl) * 8 + m] + red[(1 * 64 + nl) * 8 + m] +
                      red[(2 * 64 + nl) * 8 + m] + red[(3 * 64 + nl) * 8 + m];
            if (bias) v += bias[n];
            if (act == 1) v = v / (1.f + expf(-v));
            C[(size_t)m * N + n] = v;
        }
    }
}

__global__ void __launch_bounds__(256) gemv8_kernel(
    const float* __restrict__ A, const float* __restrict__ W,
    const float* __restrict__ bias, float* __restrict__ C,
    int N, int K, int act)
{
    gemv8_core(A, W, bias, C, N, K, act, blockIdx.x);
}

__global__ void __launch_bounds__(256) adaall_kernel(
    const float* __restrict__ tvec,
    const float* __restrict__ Wada1, const float* __restrict__ Wada2,
    float* __restrict__ out)
{
    int li = blockIdx.y;
    const float* W = (li < NLAYER) ? (Wada1 + (size_t)li * HDIM * HDIM)
                                   : (Wada2 + (size_t)(li - NLAYER) * HDIM * HDIM);
    gemv8_core(tvec, W, nullptr, out + (size_t)li * BATCH * HDIM,
               HDIM, HDIM, 0, blockIdx.x);
}

// ---------------- rmsnorm ----------------
__global__ void __launch_bounds__(256) rmsnorm_kernel(
    const float* __restrict__ x, const float* __restrict__ w,
    const float* __restrict__ ada, float* __restrict__ out)
{
    int row = blockIdx.x;
    int b = row / SEQ;
    const float* xr = x + (size_t)row * HDIM;
    __shared__ float red[256];
    float s = 0.f;
    for (int i = threadIdx.x; i < HDIM; i += 256) {
        float v = xr[i];
        s += v * v;
    }
    red[threadIdx.x] = s;
    __syncthreads();
    for (int st = 128; st > 0; st >>= 1) {
        if (threadIdx.x < st) red[threadIdx.x] += red[threadIdx.x + st];
        __syncthreads();
    }
    float r = rsqrtf(red[0] * (1.f / HDIM) + 1e-6f);
    for (int i = threadIdx.x; i < HDIM; i += 256) {
        float gmul = w[i];
        if (ada) gmul *= (1.f + ada[b * HDIM + i]);
        out[(size_t)row * HDIM + i] = xr[i] * r * gmul;
    }
}

// ---------------- rope ----------------
__global__ void rope_kernel(float* __restrict__ q, float* __restrict__ k)
{
    int idx = blockIdx.x * blockDim.x + threadIdx.x;
    const int total = MTOK * 9 * 128;
    if (idx >= total) return;
    int j = idx & 127;
    int rest = idx >> 7;
    int hh = rest % 9;
    int row = rest / 9;
    int b = row / SEQ, s = row % SEQ;
    float pos = (float)(g_plen[b] + s);
    float inv = powf(10000.f, -(float)j / 128.f);
    float fr = pos * inv;
    float sn, cs;
    sincosf(fr, &sn, &cs);
    float* p = (hh < 8) ? (q + ((size_t)row * 8 + hh) * 256) : (k + (size_t)row * 256);
    float x1 = p[j], x2 = p[j + 128];
    p[j]       = x1 * cs - x2 * sn;
    p[j + 128] = x2 * cs + x1 * sn;
}

// ---------------- softmax (zero-pads [TTOT, TPAD)) ----------------
__global__ void __launch_bounds__(256) softmax_kernel()
{
    int row = blockIdx.x;
    float* p = g_sc + (size_t)row * TPAD;
    __shared__ float red[256];
    float mx = -1e30f;
    for (int i = threadIdx.x; i < TTOT; i += 256) mx = fmaxf(mx, p[i]);
    red[threadIdx.x] = mx;
    __syncthreads();
    for (int st = 128; st > 0; st >>= 1) {
        if (threadIdx.x < st) red[threadIdx.x] = fmaxf(red[threadIdx.x], red[threadIdx.x + st]);
        __syncthreads();
    }
    float m = red[0];
    __syncthreads();
    float s = 0.f;
    for (int i = threadIdx.x; i < TTOT; i += 256) {
        float e = expf(p[i] - m);
        p[i] = e;
        s += e;
    }
    red[threadIdx.x] = s;
    __syncthreads();
    for (int st = 128; st > 0; st >>= 1) {
        if (threadIdx.x < st) red[threadIdx.x] += red[threadIdx.x + st];
        __syncthreads();
    }
    float inv = 1.f / red[0];
    for (int i = threadIdx.x; i < TTOT; i += 256) p[i] *= inv;
    if (threadIdx.x < TPAD - TTOT) p[TTOT + threadIdx.x] = 0.f;
}

// ---------------- host ----------------
static inline dim3 gemm_grid(int M, int N) { return dim3((N + 63) / 64, (M + 63) / 64); }

extern "C" void kernel_launch(void* const* d_in, const int* in_sizes, int n_in,
                              void* d_out, int out_size)
{
    const float* x_t      = (const float*)d_in[0];
    const float* timestep = (const float*)d_in[1];
    const void*  mask     = d_in[2];
    const float* kvc      = (const float*)d_in[3];
    const float* Wa_in    = (const float*)d_in[4];
    const float* ba_in    = (const float*)d_in[5];
    const float* Wt_in    = (const float*)d_in[6];
    const float* bt_in    = (const float*)d_in[7];
    const float* Wt_out   = (const float*)d_in[8];
    const float* bt_out   = (const float*)d_in[9];
    const float* Wq       = (const float*)d_in[10];
    const float* Wk       = (const float*)d_in[11];
    const float* Wv       = (const float*)d_in[12];
    const float* Wo       = (const float*)d_in[13];
    const float* Wg       = (const float*)d_in[14];
    const float* Wu       = (const float*)d_in[15];
    const float* Wd       = (const float*)d_in[16];
    const float* n1_w     = (const float*)d_in[17];
    const float* n2_w     = (const float*)d_in[18];
    const float* Wada1    = (const float*)d_in[19];
    const float* Wada2    = (const float*)d_in[20];
    const float* nf_w     = (const float*)d_in[21];
    const float* Wa_out   = (const float*)d_in[22];
    const float* ba_out   = (const float*)d_in[23];

    void* p;
    cudaGetSymbolAddress(&p, g_x);      float* px    = (float*)p;
    cudaGetSymbolAddress(&p, g_h);      float* ph    = (float*)p;
    cudaGetSymbolAddress(&p, g_temb);   float* ptemb = (float*)p;
    cudaGetSymbolAddress(&p, g_t1);     float* pt1   = (float*)p;
    cudaGetSymbolAddress(&p, g_tv);     float* ptv   = (float*)p;
    cudaGetSymbolAddress(&p, g_adaAll); float* padaA = (float*)p;
    cudaGetSymbolAddress(&p, g_q);      float* pq    = (float*)p;
    cudaGetSymbolAddress(&p, g_k);      float* pk    = (float*)p;
    cudaGetSymbolAddress(&p, g_v);      float* pv    = (float*)p;
    cudaGetSymbolAddress(&p, g_vt);     float* pvt   = (float*)p;
    cudaGetSymbolAddress(&p, g_ao);     float* pao   = (float*)p;
    cudaGetSymbolAddress(&p, g_gg);     float* pg    = (float*)p;
    cudaGetSymbolAddress(&p, g_uu);     float* pu    = (float*)p;

    prep_kernel<<<16, 512>>>(mask, timestep);

    gemv8_kernel<<<16, 256>>>(ptemb, Wt_in, bt_in, pt1, HDIM, HDIM, 1);
    gemv8_kernel<<<16, 256>>>(pt1, Wt_out, bt_out, ptv, HDIM, HDIM, 1);
    adaall_kernel<<<dim3(16, 2 * NLAYER), 256>>>(ptv, Wada1, Wada2, padaA);

    sgemm_kernel<<<gemm_grid(MTOK, HDIM), 256>>>(x_t, Wa_in, px, ba_in,
                                                 MTOK, HDIM, ADIM, ADIM, 0);

    for (int l = 0; l < NLAYER; l++) {
        const float* wq = Wq + (size_t)l * HDIM * (NHEAD * HEADD);
        const float* wk = Wk + (size_t)l * HDIM * HEADD;
        const float* wv = Wv + (size_t)l * HDIM * HEADD;
        const float* wo = Wo + (size_t)l * (NHEAD * HEADD) * HDIM;
        const float* wg = Wg + (size_t)l * HDIM * MLPD;
        const float* wu = Wu + (size_t)l * HDIM * MLPD;
        const float* wd = Wd + (size_t)l * MLPD * HDIM;
        const float* w1 = n1_w + (size_t)l * HDIM;
        const float* w2 = n2_w + (size_t)l * HDIM;
        const float* ada1 = padaA + (size_t)l * BATCH * HDIM;
        const float* ada2 = padaA + (size_t)(NLAYER + l) * BATCH * HDIM;

        rmsnorm_kernel<<<MTOK, 256>>>(px, w1, ada1, ph);

        // zero q/k/v, then split-K QKV with atomicAdd epilogue
        cudaMemsetAsync(pq, 0, (size_t)MTOK * NHEAD * HEADD * sizeof(float));
        cudaMemsetAsync(pk, 0, (size_t)MTOK * HEADD * sizeof(float));
        cudaMemsetAsync(pv, 0, (size_t)MTOK * HEADD * sizeof(float));
        qkv_kernel<<<dim3(20, 7, 2), 256>>>(ph, wq, wk, wv, pq, pk, pv);
        vtrans_kernel<<<dim3(27, 8, 8), dim3(32, 8)>>>(pv, kvc, l, pvt);
        rope_kernel<<<(MTOK * 9 * 128 + 255) / 256, 256>>>(pq, pk);

        attn_scores_kernel<<<dim3(7, 7, 8), 256>>>(pq, pk, kvc, l);
        softmax_kernel<<<BATCH * NHEAD * SEQ, 256>>>();
        cudaMemsetAsync(pao, 0, (size_t)MTOK * NHEAD * HEADD * sizeof(float));
        attn_pv_kernel<<<dim3(2, 7, 16), 256>>>(pvt, pao);

        // x += o @ Wo  (split-K 4, atomic onto residual)
        mma_gemm_kernel<<<dim3(8, 7, 4), 256>>>(
            pao, wo, px, nullptr, MTOK, HDIM, NHEAD * HEADD, 1);

        rmsnorm_kernel<<<MTOK, 256>>>(px, w2, ada2, ph);

        mma_gemm_kernel<<<dim3(32, 7, 1), 256>>>(
            ph, wg, pg, nullptr, MTOK, MLPD, HDIM, 0);
        mma_gemm_kernel<<<dim3(32, 7, 1), 256>>>(
            ph, wu, pu, pg, MTOK, MLPD, HDIM, 2);
        // x += act @ Wd  (split-K 4, atomic onto residual)
        mma_gemm_kernel<<<dim3(8, 7, 4), 256>>>(
            pu, wd, px, nullptr, MTOK, HDIM, MLPD, 1);
    }

    rmsnorm_kernel<<<MTOK, 256>>>(px, nf_w, nullptr, ph);
    sgemm_kernel<<<gemm_grid(MTOK, ADIM), 256>>>(ph, Wa_out, (float*)d_out, ba_out,
                                                 MTOK, ADIM, HDIM, HDIM, 0);
}

// round 9
// speedup vs baseline: 4.5102x; 1.0634x over previous
#include <cuda_runtime.h>
#include <math.h>
#include <stdint.h>

// ---------------- problem dims ----------------
#define NLAYER 18
#define HDIM   1024
#define NHEAD  8
#define HEADD  256
#define MLPD   4096
#define BATCH  8
#define SEQ    50
#define PREF   800
#define ADIM   32
#define TTOT   850
#define TPAD   864
#define MTOK   400
#define QKVW   2560    // combined qkv row width: q[0,2048) k[2048,2304) v[2304,2560)

// ---------------- device scratch ----------------
__device__ float g_x[MTOK * HDIM];
__device__ float g_h[MTOK * HDIM];
__device__ float g_temb[BATCH * HDIM];
__device__ float g_t1[BATCH * HDIM];
__device__ float g_tv[BATCH * HDIM];
__device__ float g_adaAll[2 * NLAYER * BATCH * HDIM];
__device__ float g_qkv[MTOK * QKVW];
__device__ float g_sc[BATCH * NHEAD * SEQ * TPAD];
__device__ float g_vt[BATCH * HEADD * TPAD];
__device__ float g_ao[MTOK * NHEAD * HEADD];
__device__ float g_gg[MTOK * MLPD];
__device__ float g_uu[MTOK * MLPD];
__device__ int   g_plen[BATCH];
__device__ float g_biasPref[BATCH * PREF];

// ---------------- bf16 split helpers ----------------
__device__ __forceinline__ void split2(float lo, float hi, uint32_t& hw, uint32_t& lw) {
    asm("cvt.rn.bf16x2.f32 %0, %1, %2;" : "=r"(hw) : "f"(hi), "f"(lo));
    float hlo = __uint_as_float(hw << 16);
    float hhi = __uint_as_float(hw & 0xffff0000u);
    asm("cvt.rn.bf16x2.f32 %0, %1, %2;" : "=r"(lw) : "f"(hi - hhi), "f"(lo - hlo));
}
__device__ __forceinline__ void mma_bf16(
    float c[4], const uint32_t a[4], uint32_t b0, uint32_t b1)
{
    asm volatile(
        "mma.sync.aligned.m16n8k16.row.col.f32.bf16.bf16.f32 "
        "{%0,%1,%2,%3}, {%4,%5,%6,%7}, {%8,%9}, {%0,%1,%2,%3};"
        : "+f"(c[0]), "+f"(c[1]), "+f"(c[2]), "+f"(c[3])
        : "r"(a[0]), "r"(a[1]), "r"(a[2]), "r"(a[3]), "r"(b0), "r"(b1));
}
__device__ __forceinline__ float gelu_f(float x) {
    float t = tanhf(0.7978845608028654f * (x + 0.044715f * x * x * x));
    return 0.5f * x * (1.f + t);
}

#define PADA 20
#define PADB 136
#define ABUF (64 * PADA)       // 1280 words
#define BBUF (16 * PADB)       // 2176 words
#define BBUF2 (128 * PADA)     // 2560 words
#define SMEM_GEMM_BYTES ((4 * ABUF + 4 * BBUF) * 4)    // 55296
#define SMEM_ATTN_BYTES ((4 * ABUF + 4 * BBUF2) * 4)   // 61440

// ============ split-bf16 (3-term) GEMM core, M64, split-K, double-buffered ============
// epiMode: 0 store, 1 accumulate, 2 gated gelu, 3 atomicAdd.
__device__ __forceinline__ void gemm_core(
    const float* __restrict__ A, const float* __restrict__ W,
    float* __restrict__ C, const float* __restrict__ Cg,
    int M, int NwW, int colBaseW, int Nout, int colBaseC,
    int Kstride, int kBase, int nChunks, int rowBase, int epiMode,
    uint32_t* dyn)
{
    uint32_t* AsH = dyn;
    uint32_t* AsL = dyn + 2 * ABUF;
    uint32_t* BsH = dyn + 4 * ABUF;
    uint32_t* BsL = dyn + 4 * ABUF + 2 * BBUF;

    const int tid  = threadIdx.x;
    const int lane = tid & 31;
    const int warp = tid >> 5;
    const int wm = (warp & 1) << 5;
    const int wn = (warp >> 1) << 5;

    const int aRow = tid >> 3;
    const int aK4  = (tid & 7) << 2;
    const int aKw  = (tid & 7) << 1;
    const int bKw  = tid >> 4;
    const int bN   = (tid & 15) << 3;

    float c[2][4][4];
#pragma unroll
    for (int i = 0; i < 2; i++)
#pragma unroll
        for (int j = 0; j < 4; j++)
#pragma unroll
            for (int r = 0; r < 4; r++) c[i][j][r] = 0.f;

    float4 pa[2], pb[4];
    auto loadg = [&](int k0) {
#pragma unroll
        for (int p = 0; p < 2; p++) {
            int gr = rowBase + aRow + (p << 5);
            pa[p] = make_float4(0.f, 0.f, 0.f, 0.f);
            if (gr < M) pa[p] = *(const float4*)(A + (size_t)gr * Kstride + k0 + aK4);
        }
        const float* br0 = W + (size_t)(k0 + 2 * bKw) * NwW + colBaseW + bN;
        pb[0] = *(const float4*)(br0);
        pb[1] = *(const float4*)(br0 + 4);
        pb[2] = *(const float4*)(br0 + NwW);
        pb[3] = *(const float4*)(br0 + NwW + 4);
    };
    auto storeb = [&](int buf) {
        uint32_t* aH = AsH + buf * ABUF;
        uint32_t* aL = AsL + buf * ABUF;
        uint32_t* bH = BsH + buf * BBUF;
        uint32_t* bL = BsL + buf * BBUF;
#pragma unroll
        for (int p = 0; p < 2; p++) {
            int r = aRow + (p << 5);
            uint32_t h0, l0, h1, l1;
            split2(pa[p].x, pa[p].y, h0, l0);
            split2(pa[p].z, pa[p].w, h1, l1);
            *(uint2*)(&aH[r * PADA + aKw]) = make_uint2(h0, h1);
            *(uint2*)(&aL[r * PADA + aKw]) = make_uint2(l0, l1);
        }
        uint32_t hw[8], lw[8];
        const float* p0 = (const float*)&pb[0];
        const float* p1 = (const float*)&pb[2];
#pragma unroll
        for (int j = 0; j < 8; j++) split2(p0[j], p1[j], hw[j], lw[j]);
        *(uint4*)(&bH[bKw * PADB + bN])     = make_uint4(hw[0], hw[1], hw[2], hw[3]);
        *(uint4*)(&bH[bKw * PADB + bN + 4]) = make_uint4(hw[4], hw[5], hw[6], hw[7]);
        *(uint4*)(&bL[bKw * PADB + bN])     = make_uint4(lw[0], lw[1], lw[2], lw[3]);
        *(uint4*)(&bL[bKw * PADB + bN + 4]) = make_uint4(lw[4], lw[5], lw[6], lw[7]);
    };

    loadg(kBase);
    storeb(0);
    __syncthreads();

    for (int i = 0; i < nChunks; i++) {
        const int cur = i & 1;
        const bool more = (i + 1 < nChunks);
        if (more) loadg(kBase + ((i + 1) << 5));

        uint32_t* aH = AsH + cur * ABUF;
        uint32_t* aL = AsL + cur * ABUF;
        uint32_t* bH = BsH + cur * BBUF;
        uint32_t* bL = BsL + cur * BBUF;
#pragma unroll
        for (int ks = 0; ks < 2; ks++) {
            const int kf = (ks << 3) + (lane & 3);
            uint32_t bh[4][2], bl[4][2];
#pragma unroll
            for (int nf = 0; nf < 4; nf++) {
                int n0 = wn + (nf << 3) + (lane >> 2);
                bh[nf][0] = bH[kf * PADB + n0];
                bh[nf][1] = bH[(kf + 4) * PADB + n0];
                bl[nf][0] = bL[kf * PADB + n0];
                bl[nf][1] = bL[(kf + 4) * PADB + n0];
            }
#pragma unroll
            for (int mf = 0; mf < 2; mf++) {
                int m0 = wm + (mf << 4) + (lane >> 2);
                uint32_t ah[4], al[4];
                ah[0] = aH[m0 * PADA + kf];
                ah[1] = aH[(m0 + 8) * PADA + kf];
                ah[2] = aH[m0 * PADA + kf + 4];
                ah[3] = aH[(m0 + 8) * PADA + kf + 4];
                al[0] = aL[m0 * PADA + kf];
                al[1] = aL[(m0 + 8) * PADA + kf];
                al[2] = aL[m0 * PADA + kf + 4];
                al[3] = aL[(m0 + 8) * PADA + kf + 4];
#pragma unroll
                for (int nf = 0; nf < 4; nf++) {
                    mma_bf16(c[mf][nf], al, bh[nf][0], bh[nf][1]);
                    mma_bf16(c[mf][nf], ah, bl[nf][0], bl[nf][1]);
                    mma_bf16(c[mf][nf], ah, bh[nf][0], bh[nf][1]);
                }
            }
        }
        if (more) storeb(cur ^ 1);
        __syncthreads();
    }

#pragma unroll
    for (int mf = 0; mf < 2; mf++) {
        int r0 = rowBase + wm + (mf << 4) + (lane >> 2);
#pragma unroll
        for (int nf = 0; nf < 4; nf++) {
            int cc = colBaseC + wn + (nf << 3) + ((lane & 3) << 1);
#pragma unroll
            for (int half = 0; half < 2; half++) {
                int rr = r0 + half * 8;
                if (rr >= M) continue;
                size_t off = (size_t)rr * Nout + cc;
                float2 v = make_float2(c[mf][nf][half * 2], c[mf][nf][half * 2 + 1]);
                if (epiMode == 3) {
                    atomicAdd(C + off, v.x);
                    atomicAdd(C + off + 1, v.y);
                    continue;
                }
                if (epiMode == 1) {
                    float2 old = *(float2*)(C + off);
                    v.x += old.x; v.y += old.y;
                } else if (epiMode == 2) {
                    float2 gg = *(const float2*)(Cg + off);
                    v.x *= gelu_f(gg.x); v.y *= gelu_f(gg.y);
                }
                *(float2*)(C + off) = v;
            }
        }
    }
}

__global__ void __launch_bounds__(256, 2) mma_gemm_kernel(
    const float* __restrict__ A, const float* __restrict__ W,
    float* __restrict__ C, const float* __restrict__ Cg,
    int M, int N, int K, int epiMode)
{
    extern __shared__ uint32_t dyn[];
    int splits = gridDim.z;
    int kLen = K / splits;
    int kBase = blockIdx.z * kLen;
    int em = (splits > 1) ? 3 : epiMode;
    gemm_core(A, W, C, Cg, M, N, blockIdx.x * 128, N, blockIdx.x * 128,
              K, kBase, kLen >> 5, blockIdx.y * 64, em, dyn);
}

// fused QKV into combined buffer: grid (20, 7, 2) split-K, atomicAdd into zeroed output
__global__ void __launch_bounds__(256, 2) qkv_kernel(
    const float* __restrict__ A,
    const float* __restrict__ Wq, const float* __restrict__ Wk, const float* __restrict__ Wv,
    float* __restrict__ qkv)
{
    extern __shared__ uint32_t dyn[];
    int bx = blockIdx.x;
    const float* W; int NwW, colBaseW, colBaseC;
    if (bx < 16)      { W = Wq; NwW = 2048; colBaseW = bx * 128;        colBaseC = bx * 128; }
    else if (bx < 18) { W = Wk; NwW = 256;  colBaseW = (bx - 16) * 128; colBaseC = 2048 + (bx - 16) * 128; }
    else              { W = Wv; NwW = 256;  colBaseW = (bx - 18) * 128; colBaseC = 2304 + (bx - 18) * 128; }
    int kBase = blockIdx.z << 9;
    gemm_core(A, W, qkv, nullptr, MTOK, NwW, colBaseW, QKVW, colBaseC,
              HDIM, kBase, 16, blockIdx.y * 64, 3, dyn);
}

// ============ attention scores, double-buffered ============
// grid (7, 7, 8). S = Q @ K^T / 16 + bias.
__global__ void __launch_bounds__(256, 2) attn_scores_kernel(
    const float* __restrict__ qkv, const float* __restrict__ kvc, int layer)
{
    extern __shared__ uint32_t dyn[];
    uint32_t* AsH = dyn;
    uint32_t* AsL = dyn + 2 * ABUF;
    uint32_t* BsH = dyn + 4 * ABUF;
    uint32_t* BsL = dyn + 4 * ABUF + 2 * BBUF2;

    const int tid  = threadIdx.x;
    const int lane = tid & 31;
    const int warp = tid >> 5;
    const int wm = (warp & 1) << 5;
    const int wn = (warp >> 1) << 5;
    const int b = blockIdx.z;
    const int rowBase = blockIdx.y * 64;
    const int colBase = blockIdx.x * 128;

    const float* Kc = kvc + ((size_t)(layer * 2) * BATCH + b) * (size_t)(PREF * HEADD);
    const float* Qb = qkv + (size_t)b * SEQ * QKVW;

    const int aRow = tid >> 3;
    const int aK4  = (tid & 7) << 2;
    const int aKw  = (tid & 7) << 1;

    float c[2][4][4];
#pragma unroll
    for (int i = 0; i < 2; i++)
#pragma unroll
        for (int j = 0; j < 4; j++)
#pragma unroll
            for (int r = 0; r < 4; r++) c[i][j][r] = 0.f;

    float4 pa[2], pb[4];
    auto loadg = [&](int k0) {
#pragma unroll
        for (int p = 0; p < 2; p++) {
            int gr = rowBase + aRow + (p << 5);
            pa[p] = make_float4(0.f, 0.f, 0.f, 0.f);
            if (gr < 400) {
                int s = gr >> 3, h = gr & 7;
                pa[p] = *(const float4*)(Qb + (size_t)s * QKVW + h * 256 + k0 + aK4);
            }
        }
#pragma unroll
        for (int p = 0; p < 4; p++) {
            int t = colBase + aRow + (p << 5);
            pb[p] = make_float4(0.f, 0.f, 0.f, 0.f);
            if (t < PREF)      pb[p] = *(const float4*)(Kc + (size_t)t * 256 + k0 + aK4);
            else if (t < TTOT) pb[p] = *(const float4*)(qkv + (size_t)(b * SEQ + t - PREF) * QKVW + 2048 + k0 + aK4);
        }
    };
    auto storeb = [&](int buf) {
        uint32_t* aH = AsH + buf * ABUF;
        uint32_t* aL = AsL + buf * ABUF;
        uint32_t* bH = BsH + buf * BBUF2;
        uint32_t* bL = BsL + buf * BBUF2;
#pragma unroll
        for (int p = 0; p < 2; p++) {
            int r = aRow + (p << 5);
            uint32_t h0, l0, h1, l1;
            split2(pa[p].x, pa[p].y, h0, l0);
            split2(pa[p].z, pa[p].w, h1, l1);
            *(uint2*)(&aH[r * PADA + aKw]) = make_uint2(h0, h1);
            *(uint2*)(&aL[r * PADA + aKw]) = make_uint2(l0, l1);
        }
#pragma unroll
        for (int p = 0; p < 4; p++) {
            int r = aRow + (p << 5);
            uint32_t h0, l0, h1, l1;
            split2(pb[p].x, pb[p].y, h0, l0);
            split2(pb[p].z, pb[p].w, h1, l1);
            *(uint2*)(&bH[r * PADA + aKw]) = make_uint2(h0, h1);
            *(uint2*)(&bL[r * PADA + aKw]) = make_uint2(l0, l1);
        }
    };

    loadg(0);
    storeb(0);
    __syncthreads();

    for (int i = 0; i < 8; i++) {
        const int cur = i & 1;
        const bool more = (i + 1 < 8);
        if (more) loadg((i + 1) << 5);

        uint32_t* aH = AsH + cur * ABUF;
        uint32_t* aL = AsL + cur * ABUF;
        uint32_t* bH = BsH + cur * BBUF2;
        uint32_t* bL = BsL + cur * BBUF2;
#pragma unroll
        for (int ks = 0; ks < 2; ks++) {
            const int kf = (ks << 3) + (lane & 3);
            uint32_t bh[4][2], bl[4][2];
#pragma unroll
            for (int nf = 0; nf < 4; nf++) {
                int n0 = wn + (nf << 3) + (lane >> 2);
                bh[nf][0] = bH[n0 * PADA + kf];
                bh[nf][1] = bH[n0 * PADA + kf + 4];
                bl[nf][0] = bL[n0 * PADA + kf];
                bl[nf][1] = bL[n0 * PADA + kf + 4];
            }
#pragma unroll
            for (int mf = 0; mf < 2; mf++) {
                int m0 = wm + (mf << 4) + (lane >> 2);
                uint32_t ah[4], al[4];
                ah[0] = aH[m0 * PADA + kf];
                ah[1] = aH[(m0 + 8) * PADA + kf];
                ah[2] = aH[m0 * PADA + kf + 4];
                ah[3] = aH[(m0 + 8) * PADA + kf + 4];
                al[0] = aL[m0 * PADA + kf];
                al[1] = aL[(m0 + 8) * PADA + kf];
                al[2] = aL[m0 * PADA + kf + 4];
                al[3] = aL[(m0 + 8) * PADA + kf + 4];
#pragma unroll
                for (int nf = 0; nf < 4; nf++) {
                    mma_bf16(c[mf][nf], al, bh[nf][0], bh[nf][1]);
                    mma_bf16(c[mf][nf], ah, bl[nf][0], bl[nf][1]);
                    mma_bf16(c[mf][nf], ah, bh[nf][0], bh[nf][1]);
                }
            }
        }
        if (more) storeb(cur ^ 1);
        __syncthreads();
    }

    const float scale = 0.0625f;
#pragma unroll
    for (int mf = 0; mf < 2; mf++) {
        int r0 = rowBase + wm + (mf << 4) + (lane >> 2);
#pragma unroll
        for (int nf = 0; nf < 4; nf++) {
            int t = colBase + wn + (nf << 3) + ((lane & 3) << 1);
            if (t >= TTOT) continue;
            float2 bias;
            bias.x = (t < PREF) ? g_biasPref[b * PREF + t] : 0.f;
            bias.y = (t + 1 < PREF) ? g_biasPref[b * PREF + t + 1] : 0.f;
#pragma unroll
            for (int half = 0; half < 2; half++) {
                int rr = r0 + half * 8;
                if (rr >= 400) continue;
                int h = rr & 7, s = rr >> 3;
                size_t off = ((size_t)(b * 8 + h) * SEQ + s) * TPAD + t;
                float2 v = make_float2(c[mf][nf][half * 2] * scale + bias.x,
                                       c[mf][nf][half * 2 + 1] * scale + bias.y);
                *(float2*)(g_sc + off) = v;
            }
        }
    }
}

// ============ attention PV, double-buffered, split-T ============
// grid (2, 7, 16): z = b*2 + half. atomicAdd into zeroed out.
__global__ void __launch_bounds__(256, 2) attn_pv_kernel(
    const float* __restrict__ vt, float* __restrict__ out)
{
    extern __shared__ uint32_t dyn[];
    uint32_t* AsH = dyn;
    uint32_t* AsL = dyn + 2 * ABUF;
    uint32_t* BsH = dyn + 4 * ABUF;
    uint32_t* BsL = dyn + 4 * ABUF + 2 * BBUF2;

    const int tid  = threadIdx.x;
    const int lane = tid & 31;
    const int warp = tid >> 5;
    const int wm = (warp & 1) << 5;
    const int wn = (warp >> 1) << 5;
    const int bz = blockIdx.z;
    const int b = bz >> 1;
    const int zs = bz & 1;
    const int kBase = zs ? 448 : 0;
    const int nChunks = zs ? 13 : 14;
    const int rowBase = blockIdx.y * 64;
    const int colBase = blockIdx.x * 128;

    const float* Ab = g_sc + (size_t)b * 400 * TPAD;
    const float* Bb = vt + (size_t)b * HEADD * TPAD;

    const int aRow = tid >> 3;
    const int aK4  = (tid & 7) << 2;
    const int aKw  = (tid & 7) << 1;

    float c[2][4][4];
#pragma unroll
    for (int i = 0; i < 2; i++)
#pragma unroll
        for (int j = 0; j < 4; j++)
#pragma unroll
            for (int r = 0; r < 4; r++) c[i][j][r] = 0.f;

    float4 pa[2], pb[4];
    auto loadg = [&](int k0) {
#pragma unroll
        for (int p = 0; p < 2; p++) {
            int gr = rowBase + aRow + (p << 5);
            pa[p] = make_float4(0.f, 0.f, 0.f, 0.f);
            if (gr < 400) pa[p] = *(const float4*)(Ab + (size_t)gr * TPAD + k0 + aK4);
        }
#pragma unroll
        for (int p = 0; p < 4; p++) {
            int d = colBase + aRow + (p << 5);
            pb[p] = *(const float4*)(Bb + (size_t)d * TPAD + k0 + aK4);
        }
    };
    auto storeb = [&](int buf) {
        uint32_t* aH = AsH + buf * ABUF;
        uint32_t* aL = AsL + buf * ABUF;
        uint32_t* bH = BsH + buf * BBUF2;
        uint32_t* bL = BsL + buf * BBUF2;
#pragma unroll
        for (int p = 0; p < 2; p++) {
            int r = aRow + (p << 5);
            uint32_t h0, l0, h1, l1;
            split2(pa[p].x, pa[p].y, h0, l0);
            split2(pa[p].z, pa[p].w, h1, l1);
            *(uint2*)(&aH[r * PADA + aKw]) = make_uint2(h0, h1);
            *(uint2*)(&aL[r * PADA + aKw]) = make_uint2(l0, l1);
        }
#pragma unroll
        for (int p = 0; p < 4; p++) {
            int r = aRow + (p << 5);
            uint32_t h0, l0, h1, l1;
            split2(pb[p].x, pb[p].y, h0, l0);
            split2(pb[p].z, pb[p].w, h1, l1);
            *(uint2*)(&bH[r * PADA + aKw]) = make_uint2(h0, h1);
            *(uint2*)(&bL[r * PADA + aKw]) = make_uint2(l0, l1);
        }
    };

    loadg(kBase);
    storeb(0);
    __syncthreads();

    for (int i = 0; i < nChunks; i++) {
        const int cur = i & 1;
        const bool more = (i + 1 < nChunks);
        if (more) loadg(kBase + ((i + 1) << 5));

        uint32_t* aH = AsH + cur * ABUF;
        uint32_t* aL = AsL + cur * ABUF;
        uint32_t* bH = BsH + cur * BBUF2;
        uint32_t* bL = BsL + cur * BBUF2;
#pragma unroll
        for (int ks = 0; ks < 2; ks++) {
            const int kf = (ks << 3) + (lane & 3);
            uint32_t bh[4][2], bl[4][2];
#pragma unroll
            for (int nf = 0; nf < 4; nf++) {
                int n0 = wn + (nf << 3) + (lane >> 2);
                bh[nf][0] = bH[n0 * PADA + kf];
                bh[nf][1] = bH[n0 * PADA + kf + 4];
                bl[nf][0] = bL[n0 * PADA + kf];
                bl[nf][1] = bL[n0 * PADA + kf + 4];
            }
#pragma unroll
            for (int mf = 0; mf < 2; mf++) {
                int m0 = wm + (mf << 4) + (lane >> 2);
                uint32_t ah[4], al[4];
                ah[0] = aH[m0 * PADA + kf];
                ah[1] = aH[(m0 + 8) * PADA + kf];
                ah[2] = aH[m0 * PADA + kf + 4];
                ah[3] = aH[(m0 + 8) * PADA + kf + 4];
                al[0] = aL[m0 * PADA + kf];
                al[1] = aL[(m0 + 8) * PADA + kf];
                al[2] = aL[m0 * PADA + kf + 4];
                al[3] = aL[(m0 + 8) * PADA + kf + 4];
#pragma unroll
                for (int nf = 0; nf < 4; nf++) {
                    mma_bf16(c[mf][nf], al, bh[nf][0], bh[nf][1]);
                    mma_bf16(c[mf][nf], ah, bl[nf][0], bl[nf][1]);
                    mma_bf16(c[mf][nf], ah, bh[nf][0], bh[nf][1]);
                }
            }
        }
        if (more) storeb(cur ^ 1);
        __syncthreads();
    }

#pragma unroll
    for (int mf = 0; mf < 2; mf++) {
        int r0 = rowBase + wm + (mf << 4) + (lane >> 2);
#pragma unroll
        for (int nf = 0; nf < 4; nf++) {
            int d = colBase + wn + (nf << 3) + ((lane & 3) << 1);
#pragma unroll
            for (int half = 0; half < 2; half++) {
                int rr = r0 + half * 8;
                if (rr >= 400) continue;
                int h = rr / SEQ, s = rr % SEQ;
                size_t off = (((size_t)(b * SEQ + s)) * 8 + h) * 256 + d;
                atomicAdd(out + off,     c[mf][nf][half * 2]);
                atomicAdd(out + off + 1, c[mf][nf][half * 2 + 1]);
            }
        }
    }
}

// ---------------- fused rope (q,k) + V transpose ----------------
// grid: [0,1728) vtrans blocks, [1728, 1728+1800) rope blocks. 256 threads.
__global__ void ropevtrans_kernel(float* __restrict__ qkv,
                                  const float* __restrict__ kvc, int layer,
                                  float* __restrict__ vt)
{
    int bid = blockIdx.x;
    int tid = threadIdx.x;
    if (bid < 1728) {
        __shared__ float tile[32][33];
        int t0 = (bid % 27) * 32;
        int rest = bid / 27;
        int d0 = (rest & 7) * 32;
        int b = rest >> 3;
        int tx = tid & 31, ty = tid >> 5;
        const float* Vc = kvc + ((size_t)(layer * 2 + 1) * BATCH + b) * (size_t)(PREF * HEADD);
#pragma unroll
        for (int j = 0; j < 4; j++) {
            int t = t0 + ty + j * 8;
            float v = 0.f;
            if (t < PREF)      v = Vc[(size_t)t * 256 + d0 + tx];
            else if (t < TTOT) v = qkv[(size_t)(b * SEQ + t - PREF) * QKVW + 2304 + d0 + tx];
            tile[ty + j * 8][tx] = v;
        }
        __syncthreads();
#pragma unroll
        for (int j = 0; j < 4; j++) {
            int d = d0 + ty + j * 8;
            vt[((size_t)b * HEADD + d) * TPAD + t0 + tx] = tile[tx][ty + j * 8];
        }
    } else {
        int idx = (bid - 1728) * 256 + tid;
        if (idx >= MTOK * 9 * 128) return;
        int j = idx & 127;
        int rest = idx >> 7;
        int hh = rest % 9;
        int row = rest / 9;
        int b = row / SEQ, s = row % SEQ;
        float pos = (float)(g_plen[b] + s);
        float inv = powf(10000.f, -(float)j / 128.f);
        float fr = pos * inv;
        float sn, cs;
        sincosf(fr, &sn, &cs);
        float* p = qkv + (size_t)row * QKVW + ((hh < 8) ? hh * 256 : 2048);
        float x1 = p[j], x2 = p[j + 128];
        p[j]       = x1 * cs - x2 * sn;
        p[j + 128] = x2 * cs + x1 * sn;
    }
}

// ---------------- prep ----------------
__global__ void prep_kernel(const void* __restrict__ maskp,
                            const float* __restrict__ ts)
{
    int bb = blockIdx.x;
    if (bb < BATCH) {
        int b = bb;
        const int* mi = (const int*)maskp;
        const unsigned char* mu = (const unsigned char*)maskp;
        int w0 = mi[0];
        bool is_i32 = (w0 == 0 || w0 == 1);
        __shared__ int cnt;
        if (threadIdx.x == 0) cnt = 0;
        __syncthreads();
        int local = 0;
        for (int t = threadIdx.x; t < PREF; t += blockDim.x) {
            int m = is_i32 ? mi[b * PREF + t] : (int)mu[b * PREF + t];
            bool on = (m != 0);
            g_biasPref[b * PREF + t] = on ? 0.f : -1e9f;
            if (on) local++;
        }
        atomicAdd(&cnt, local);
        __syncthreads();
        if (threadIdx.x == 0) g_plen[b] = cnt;
    } else {
        int b = bb - BATCH;
        float tsb = ts[b];
        for (int i = threadIdx.x; i < 512; i += blockDim.x) {
            float frac = (float)i / 511.f;
            float period = 4e-3f * powf(1000.f, frac);
            float arg = (6.283185307179586f / period) * tsb;
            float sv, cv;
            sincosf(arg, &sv, &cv);
            g_temb[b * HDIM + i]       = sv;
            g_temb[b * HDIM + 512 + i] = cv;
        }
    }
}

// ---------------- SIMT SGEMM (small GEMMs only) ----------------
__global__ void __launch_bounds__(256) sgemm_kernel(
    const float* __restrict__ A, const float* __restrict__ W,
    float* __restrict__ C, const float* __restrict__ bias,
    int M, int N, int K, int lda, int accumulate)
{
    __shared__ float As[16][64];
    __shared__ float Bs[16][64];
    const int tid = threadIdx.x;
    const int tx = tid & 15;
    const int ty = tid >> 4;
    const int rowBase = blockIdx.y * 64;
    const int colBase = blockIdx.x * 64;

    const int lm  = tid >> 2;
    const int lk  = (tid & 3) << 2;
    const int lkr = tid >> 4;
    const int ln  = (tid & 15) << 2;

    float acc[4][4];
#pragma unroll
    for (int i = 0; i < 4; i++)
#pragma unroll
        for (int j = 0; j < 4; j++) acc[i][j] = 0.f;

    for (int k0 = 0; k0 < K; k0 += 16) {
        float4 av = make_float4(0.f, 0.f, 0.f, 0.f);
        int ar = rowBase + lm;
        if (ar < M) av = *(const float4*)(A + (size_t)ar * lda + (k0 + lk));
        As[lk + 0][lm] = av.x;
        As[lk + 1][lm] = av.y;
        As[lk + 2][lm] = av.z;
        As[lk + 3][lm] = av.w;

        float4 bv;
        int bn = colBase + ln;
        const float* wrow = W + (size_t)(k0 + lkr) * N;
        if (bn + 3 < N) {
            bv = *(const float4*)(wrow + bn);
        } else {
            bv.x = (bn + 0 < N) ? wrow[bn + 0] : 0.f;
            bv.y = (bn + 1 < N) ? wrow[bn + 1] : 0.f;
            bv.z = (bn + 2 < N) ? wrow[bn + 2] : 0.f;
            bv.w = (bn + 3 < N) ? wrow[bn + 3] : 0.f;
        }
        *(float4*)(&Bs[lkr][ln]) = bv;
        __syncthreads();

#pragma unroll
        for (int kk = 0; kk < 16; kk++) {
            float4 a = *(const float4*)(&As[kk][ty << 2]);
            float4 b = *(const float4*)(&Bs[kk][tx << 2]);
            acc[0][0] += a.x * b.x; acc[0][1] += a.x * b.y; acc[0][2] += a.x * b.z; acc[0][3] += a.x * b.w;
            acc[1][0] += a.y * b.x; acc[1][1] += a.y * b.y; acc[1][2] += a.y * b.z; acc[1][3] += a.y * b.w;
            acc[2][0] += a.z * b.x; acc[2][1] += a.z * b.y; acc[2][2] += a.z * b.z; acc[2][3] += a.z * b.w;
            acc[3][0] += a.w * b.x; acc[3][1] += a.w * b.y; acc[3][2] += a.w * b.z; acc[3][3] += a.w * b.w;
        }
        __syncthreads();
    }

#pragma unroll
    for (int i = 0; i < 4; i++) {
        int r = rowBase + (ty << 2) + i;
        if (r >= M) continue;
#pragma unroll
        for (int j = 0; j < 4; j++) {
            int cx = colBase + (tx << 2) + j;
            if (cx >= N) continue;
            float v = acc[i][j];
            if (bias) v += bias[cx];
            size_t off = (size_t)r * N + cx;
            if (accumulate) v += C[off];
            C[off] = v;
        }
    }
}

// ---------------- small-M (M<=8) GEMM core ----------------
__device__ __forceinline__ void gemv8_core(
    const float* __restrict__ A, const float* __restrict__ W,
    const float* __restrict__ bias, float* __restrict__ C,
    int N, int K, int act, int bx)
{
    __shared__ float a_s[8 * 1024];
    __shared__ float red[4 * 64 * 8];
    int tid = threadIdx.x;
    for (int e = tid; e < 8 * K; e += 256) a_s[e] = A[e];
    __syncthreads();

    int nl = tid & 63;
    int n  = bx * 64 + nl;
    int ks = tid >> 6;
    float acc[8];
#pragma unroll
    for (int m = 0; m < 8; m++) acc[m] = 0.f;

    int kc = K >> 2;
    if (n < N) {
        int kbeg = ks * kc;
#pragma unroll 4
        for (int k = 0; k < kc; k++) {
            float w = W[(size_t)(kbeg + k) * N + n];
#pragma unroll
            for (int m = 0; m < 8; m++) acc[m] += a_s[m * K + kbeg + k] * w;
        }
    }
#pragma unroll
    for (int m = 0; m < 8; m++) red[tid * 8 + m] = acc[m];
    __syncthreads();
    if (ks == 0 && n < N) {
#pragma unroll
        for (int m = 0; m < 8; m++) {
            float v = red[(0 * 64 + nl) * 8 + m] + red[(1 * 64 + nl) * 8 + m] +
                      red[(2 * 64 + nl) * 8 + m] + red[(3 * 64 + nl) * 8 + m];
            if (bias) v += bias[n];
            if (act == 1) v = v / (1.f + expf(-v));
            C[(size_t)m * N + n] = v;
        }
    }
}

__global__ void __launch_bounds__(256) gemv8_kernel(
    const float* __restrict__ A, const float* __restrict__ W,
    const float* __restrict__ bias, float* __restrict__ C,
    int N, int K, int act)
{
    gemv8_core(A, W, bias, C, N, K, act, blockIdx.x);
}

__global__ void __launch_bounds__(256) adaall_kernel(
    const float* __restrict__ tvec,
    const float* __restrict__ Wada1, const float* __restrict__ Wada2,
    float* __restrict__ out)
{
    int li = blockIdx.y;
    const float* W = (li < NLAYER) ? (Wada1 + (size_t)li * HDIM * HDIM)
                                   : (Wada2 + (size_t)(li - NLAYER) * HDIM * HDIM);
    gemv8_core(tvec, W, nullptr, out + (size_t)li * BATCH * HDIM,
               HDIM, HDIM, 0, blockIdx.x);
}

// ---------------- rmsnorm ----------------
__global__ void __launch_bounds__(256) rmsnorm_kernel(
    const float* __restrict__ x, const float* __restrict__ w,
    const float* __restrict__ ada, float* __restrict__ out)
{
    int row = blockIdx.x;
    int b = row / SEQ;
    const float* xr = x + (size_t)row * HDIM;
    __shared__ float red[256];
    float s = 0.f;
    for (int i = threadIdx.x; i < HDIM; i += 256) {
        float v = xr[i];
        s += v * v;
    }
    red[threadIdx.x] = s;
    __syncthreads();
    for (int st = 128; st > 0; st >>= 1) {
        if (threadIdx.x < st) red[threadIdx.x] += red[threadIdx.x + st];
        __syncthreads();
    }
    float r = rsqrtf(red[0] * (1.f / HDIM) + 1e-6f);
    for (int i = threadIdx.x; i < HDIM; i += 256) {
        float gmul = w[i];
        if (ada) gmul *= (1.f + ada[b * HDIM + i]);
        out[(size_t)row * HDIM + i] = xr[i] * r * gmul;
    }
}

// ---------------- softmax (zero-pads [TTOT, TPAD)) ----------------
__global__ void __launch_bounds__(256) softmax_kernel()
{
    int row = blockIdx.x;
    float* p = g_sc + (size_t)row * TPAD;
    __shared__ float red[256];
    float mx = -1e30f;
    for (int i = threadIdx.x; i < TTOT; i += 256) mx = fmaxf(mx, p[i]);
    red[threadIdx.x] = mx;
    __syncthreads();
    for (int st = 128; st > 0; st >>= 1) {
        if (threadIdx.x < st) red[threadIdx.x] = fmaxf(red[threadIdx.x], red[threadIdx.x + st]);
        __syncthreads();
    }
    float m = red[0];
    __syncthreads();
    float s = 0.f;
    for (int i = threadIdx.x; i < TTOT; i += 256) {
        float e = expf(p[i] - m);
        p[i] = e;
        s += e;
    }
    red[threadIdx.x] = s;
    __syncthreads();
    for (int st = 128; st > 0; st >>= 1) {
        if (threadIdx.x < st) red[threadIdx.x] += red[threadIdx.x + st];
        __syncthreads();
    }
    float inv = 1.f / red[0];
    for (int i = threadIdx.x; i < TTOT; i += 256) p[i] *= inv;
    if (threadIdx.x < TPAD - TTOT) p[TTOT + threadIdx.x] = 0.f;
}

// ---------------- host ----------------
static inline dim3 gemm_grid(int M, int N) { return dim3((N + 63) / 64, (M + 63) / 64); }

extern "C" void kernel_launch(void* const* d_in, const int* in_sizes, int n_in,
                              void* d_out, int out_size)
{
    const float* x_t      = (const float*)d_in[0];
    const float* timestep = (const float*)d_in[1];
    const void*  mask     = d_in[2];
    const float* kvc      = (const float*)d_in[3];
    const float* Wa_in    = (const float*)d_in[4];
    const float* ba_in    = (const float*)d_in[5];
    const float* Wt_in    = (const float*)d_in[6];
    const float* bt_in    = (const float*)d_in[7];
    const float* Wt_out   = (const float*)d_in[8];
    const float* bt_out   = (const float*)d_in[9];
    const float* Wq       = (const float*)d_in[10];
    const float* Wk       = (const float*)d_in[11];
    const float* Wv       = (const float*)d_in[12];
    const float* Wo       = (const float*)d_in[13];
    const float* Wg       = (const float*)d_in[14];
    const float* Wu       = (const float*)d_in[15];
    const float* Wd       = (const float*)d_in[16];
    const float* n1_w     = (const float*)d_in[17];
    const float* n2_w     = (const float*)d_in[18];
    const float* Wada1    = (const float*)d_in[19];
    const float* Wada2    = (const float*)d_in[20];
    const float* nf_w     = (const float*)d_in[21];
    const float* Wa_out   = (const float*)d_in[22];
    const float* ba_out   = (const float*)d_in[23];

    cudaFuncSetAttribute(mma_gemm_kernel,
                         cudaFuncAttributeMaxDynamicSharedMemorySize, SMEM_GEMM_BYTES);
    cudaFuncSetAttribute(qkv_kernel,
                         cudaFuncAttributeMaxDynamicSharedMemorySize, SMEM_GEMM_BYTES);
    cudaFuncSetAttribute(attn_scores_kernel,
                         cudaFuncAttributeMaxDynamicSharedMemorySize, SMEM_ATTN_BYTES);
    cudaFuncSetAttribute(attn_pv_kernel,
                         cudaFuncAttributeMaxDynamicSharedMemorySize, SMEM_ATTN_BYTES);

    void* p;
    cudaGetSymbolAddress(&p, g_x);      float* px    = (float*)p;
    cudaGetSymbolAddress(&p, g_h);      float* ph    = (float*)p;
    cudaGetSymbolAddress(&p, g_temb);   float* ptemb = (float*)p;
    cudaGetSymbolAddress(&p, g_t1);     float* pt1   = (float*)p;
    cudaGetSymbolAddress(&p, g_tv);     float* ptv   = (float*)p;
    cudaGetSymbolAddress(&p, g_adaAll); float* padaA = (float*)p;
    cudaGetSymbolAddress(&p, g_qkv);    float* pqkv  = (float*)p;
    cudaGetSymbolAddress(&p, g_vt);     float* pvt   = (float*)p;
    cudaGetSymbolAddress(&p, g_ao);     float* pao   = (float*)p;
    cudaGetSymbolAddress(&p, g_gg);     float* pg    = (float*)p;
    cudaGetSymbolAddress(&p, g_uu);     float* pu    = (float*)p;

    prep_kernel<<<16, 512>>>(mask, timestep);

    gemv8_kernel<<<16, 256>>>(ptemb, Wt_in, bt_in, pt1, HDIM, HDIM, 1);
    gemv8_kernel<<<16, 256>>>(pt1, Wt_out, bt_out, ptv, HDIM, HDIM, 1);
    adaall_kernel<<<dim3(16, 2 * NLAYER), 256>>>(ptv, Wada1, Wada2, padaA);

    sgemm_kernel<<<gemm_grid(MTOK, HDIM), 256>>>(x_t, Wa_in, px, ba_in,
                                                 MTOK, HDIM, ADIM, ADIM, 0);

    for (int l = 0; l < NLAYER; l++) {
        const float* wq = Wq + (size_t)l * HDIM * (NHEAD * HEADD);
        const float* wk = Wk + (size_t)l * HDIM * HEADD;
        const float* wv = Wv + (size_t)l * HDIM * HEADD;
        const float* wo = Wo + (size_t)l * (NHEAD * HEADD) * HDIM;
        const float* wg = Wg + (size_t)l * HDIM * MLPD;
        const float* wu = Wu + (size_t)l * HDIM * MLPD;
        const float* wd = Wd + (size_t)l * MLPD * HDIM;
        const float* w1 = n1_w + (size_t)l * HDIM;
        const float* w2 = n2_w + (size_t)l * HDIM;
        const float* ada1 = padaA + (size_t)l * BATCH * HDIM;
        const float* ada2 = padaA + (size_t)(NLAYER + l) * BATCH * HDIM;

        rmsnorm_kernel<<<MTOK, 256>>>(px, w1, ada1, ph);

        cudaMemsetAsync(pqkv, 0, (size_t)MTOK * QKVW * sizeof(float));
        qkv_kernel<<<dim3(20, 7, 2), 256, SMEM_GEMM_BYTES>>>(ph, wq, wk, wv, pqkv);
        ropevtrans_kernel<<<1728 + 1800, 256>>>(pqkv, kvc, l, pvt);

        attn_scores_kernel<<<dim3(7, 7, 8), 256, SMEM_ATTN_BYTES>>>(pqkv, kvc, l);
        softmax_kernel<<<BATCH * NHEAD * SEQ, 256>>>();
        cudaMemsetAsync(pao, 0, (size_t)MTOK * NHEAD * HEADD * sizeof(float));
        attn_pv_kernel<<<dim3(2, 7, 16), 256, SMEM_ATTN_BYTES>>>(pvt, pao);

        mma_gemm_kernel<<<dim3(8, 7, 4), 256, SMEM_GEMM_BYTES>>>(
            pao, wo, px, nullptr, MTOK, HDIM, NHEAD * HEADD, 1);

        rmsnorm_kernel<<<MTOK, 256>>>(px, w2, ada2, ph);

        mma_gemm_kernel<<<dim3(32, 7, 1), 256, SMEM_GEMM_BYTES>>>(
            ph, wg, pg, nullptr, MTOK, MLPD, HDIM, 0);
        mma_gemm_kernel<<<dim3(32, 7, 1), 256, SMEM_GEMM_BYTES>>>(
            ph, wu, pu, pg, MTOK, MLPD, HDIM, 2);
        mma_gemm_kernel<<<dim3(8, 7, 4), 256, SMEM_GEMM_BYTES>>>(
            pu, wd, px, nullptr, MTOK, HDIM, MLPD, 1);
    }

    rmsnorm_kernel<<<MTOK, 256>>>(px, nf_w, nullptr, ph);
    sgemm_kernel<<<gemm_grid(MTOK, ADIM), 256>>>(ph, Wa_out, (float*)d_out, ba_out,
                                                 MTOK, ADIM, HDIM, HDIM, 0);
}